// round 1
// baseline (speedup 1.0000x reference)
#include <cuda_runtime.h>
#include <math.h>

// ---------------- problem constants ----------------
#define T_DIM   64
#define HW_DIM  729
#define M_TRK   512
#define DM      1152
#define NH      8
#define DH      144      // head dim (and value head dim)
#define MQ      (T_DIM * M_TRK)    // 32768 query rows
#define MK      (T_DIM * HW_DIM)   // 46656 key rows

// ---------------- device scratch (no allocs allowed) ----------------
__device__ float g_Q[(size_t)MQ * DM];   // Q after GEMM (+LN in place)
__device__ float g_K[(size_t)MK * DM];   // K after GEMM (+RoPE+LN in place)
__device__ float g_S[(size_t)MQ * DM];   // attention output (sampled)

// ---------------- SGEMM: C[M,N] = A[M,K] @ B[K,N], row-major ----------------
// BM=128, BN=128, BK=16, TM=TN=8, 256 threads.
__global__ __launch_bounds__(256)
void sgemm_kernel(const float* __restrict__ A, const float* __restrict__ B,
                  float* __restrict__ C, int M, int N, int K)
{
    const int BM = 128, BN = 128, BK = 16, TM = 8, TN = 8;
    __shared__ float As[BK][BM];
    __shared__ float Bs[BK][BN];

    const int tid = threadIdx.x;
    const int bx = blockIdx.x;          // N tile
    const int by = blockIdx.y;          // M tile
    const int tx = tid % (BN / TN);     // 0..15
    const int ty = tid / (BN / TN);     // 0..15

    const long rowBase = (long)by * BM;
    const long aBase   = rowBase * K;

    // A loader: 128x16 floats = 512 float4 -> 2 per thread
    const int aRow = tid / 4;           // 0..63
    const int aCol = (tid % 4) * 4;     // 0,4,8,12
    // B loader: 16x128 floats = 512 float4 -> 2 per thread
    const int bRow = tid / 32;          // 0..7
    const int bCol = (tid % 32) * 4;

    float acc[TM][TN];
    #pragma unroll
    for (int i = 0; i < TM; i++)
        #pragma unroll
        for (int j = 0; j < TN; j++) acc[i][j] = 0.f;

    float ar[TM], br[TN];

    for (int k0 = 0; k0 < K; k0 += BK) {
        // load A tile (transposed into As[k][m]); guard M boundary
        #pragma unroll
        for (int r = 0; r < 2; r++) {
            int row = aRow + r * 64;
            float4 v;
            if (rowBase + row < M)
                v = *(const float4*)(A + aBase + (long)row * K + k0 + aCol);
            else
                v = make_float4(0.f, 0.f, 0.f, 0.f);
            As[aCol + 0][row] = v.x;
            As[aCol + 1][row] = v.y;
            As[aCol + 2][row] = v.z;
            As[aCol + 3][row] = v.w;
        }
        // load B tile
        #pragma unroll
        for (int r = 0; r < 2; r++) {
            int row = bRow + r * 8;
            float4 v = *(const float4*)(B + (long)(k0 + row) * N + (long)bx * BN + bCol);
            *(float4*)&Bs[row][bCol] = v;
        }
        __syncthreads();

        #pragma unroll
        for (int k = 0; k < BK; k++) {
            #pragma unroll
            for (int i = 0; i < TM; i++) ar[i] = As[k][ty * TM + i];
            #pragma unroll
            for (int j = 0; j < TN; j++) br[j] = Bs[k][tx * TN + j];
            #pragma unroll
            for (int i = 0; i < TM; i++)
                #pragma unroll
                for (int j = 0; j < TN; j++)
                    acc[i][j] += ar[i] * br[j];
        }
        __syncthreads();
    }

    // store
    #pragma unroll
    for (int i = 0; i < TM; i++) {
        long gRow = rowBase + ty * TM + i;
        if (gRow < M) {
            #pragma unroll
            for (int j = 0; j < TN; j += 4) {
                float4 v = make_float4(acc[i][j], acc[i][j+1], acc[i][j+2], acc[i][j+3]);
                *(float4*)(C + gRow * N + (long)bx * BN + tx * TN + j) = v;
            }
        }
    }
}

// ---------------- LayerNorm (no bias), in place, one block per row ----------------
__device__ __forceinline__ void block_ln_inplace(float* x, const float* __restrict__ w)
{
    __shared__ float red[18];
    float s = 0.f, ss = 0.f;
    for (int i = threadIdx.x; i < DM; i += 256) {
        float v = x[i];
        s += v; ss += v * v;
    }
    #pragma unroll
    for (int o = 16; o; o >>= 1) {
        s  += __shfl_down_sync(0xffffffffu, s, o);
        ss += __shfl_down_sync(0xffffffffu, ss, o);
    }
    int wid = threadIdx.x >> 5, lane = threadIdx.x & 31;
    if (lane == 0) { red[wid] = s; red[8 + wid] = ss; }
    __syncthreads();
    if (threadIdx.x == 0) {
        float S = 0.f, SS = 0.f;
        #pragma unroll
        for (int i = 0; i < 8; i++) { S += red[i]; SS += red[8 + i]; }
        red[16] = S; red[17] = SS;
    }
    __syncthreads();
    float mu  = red[16] * (1.f / DM);
    float var = red[17] * (1.f / DM) - mu * mu;
    float inv = rsqrtf(var + 1e-6f);
    for (int i = threadIdx.x; i < DM; i += 256)
        x[i] = (x[i] - mu) * inv * w[i];
}

__global__ __launch_bounds__(256)
void ln_kernel(float* __restrict__ X, const float* __restrict__ w)
{
    block_ln_inplace(X + (size_t)blockIdx.x * DM, w);
}

// RoPE-2D then LayerNorm, in place, one block per K row.
__global__ __launch_bounds__(256)
void rope_ln_kernel(float* __restrict__ X, const float* __restrict__ fpos,
                    const float* __restrict__ w)
{
    const int row = blockIdx.x;            // t*HW + n
    const int n = row % HW_DIM;
    float* x = X + (size_t)row * DM;
    const float px = fpos[2 * n];
    const float py = fpos[2 * n + 1];
    // theta_q = 10000^(-q/288),  q in [0,288)
    const float TS = -9.210340371976184f / 288.0f;   // -ln(10000)/288
    for (int p = threadIdx.x; p < 576; p += 256) {
        int q = (p < 288) ? p : (p - 288);
        float theta = expf((float)q * TS);
        float ang = ((p < 288) ? px : py) * theta;
        float c, s;
        sincosf(ang, &s, &c);   // s = sin, c = cos
        int base = (p < 288) ? (2 * q) : (576 + 2 * q);
        float a = x[base], b = x[base + 1];
        x[base]     = a * c - b * s;
        x[base + 1] = a * s + b * c;
    }
    __syncthreads();
    block_ln_inplace(x, w);
}

// ---------------- fused attention (flash-style, fp32) ----------------
#define MT 64    // queries per block
#define KT 32    // keys per tile
#define KP 148   // smem row pitch (floats): 148 % 4 == 0, conflict-free patterns

struct AttnSmem {
    float Qs[MT][KP];
    float Ks[KT][KP];
    float Vs[KT][KP];
    float Ss[MT][KT + 1];
    float2 qpos[MT];
    float2 kpos[KT];
};

__global__ __launch_bounds__(256)
void attn_kernel(const float* __restrict__ Qln, const float* __restrict__ Kln,
                 const float* __restrict__ features, const float* __restrict__ tracks,
                 const float* __restrict__ fpos, float* __restrict__ sampled)
{
    extern __shared__ char smem_raw[];
    AttnSmem& sm = *reinterpret_cast<AttnSmem*>(smem_raw);

    const int tid = threadIdx.x;
    const int mt = blockIdx.x;   // 0..7
    const int h  = blockIdx.y;   // 0..7
    const int t  = blockIdx.z;   // 0..63
    const int m0 = mt * MT;

    const float* qbase = Qln      + ((size_t)t * M_TRK + m0) * DM + h * DH;
    const float* kbase = Kln      + (size_t)t * HW_DIM * DM + h * DH;
    const float* vbase = features + (size_t)t * HW_DIM * DM + h * DH;

    // load Q tile (64 x 144)
    for (int f = tid; f < MT * (DH / 4); f += 256) {
        int r = f / 36, c = (f % 36) * 4;
        *(float4*)&sm.Qs[r][c] = *(const float4*)(qbase + (size_t)r * DM + c);
    }
    if (tid < MT)
        sm.qpos[tid] = *(const float2*)(tracks + ((size_t)t * M_TRK + m0 + tid) * 2);

    const int m = tid / 4;       // query row this thread owns (4 threads/row)
    const int g = tid % 4;       // group: j-lane interleave / d-range owner

    float mi = -1e30f, li = 0.f;
    float4 acc[9];
    #pragma unroll
    for (int i = 0; i < 9; i++) acc[i] = make_float4(0.f, 0.f, 0.f, 0.f);

    const int ntiles = (HW_DIM + KT - 1) / KT;   // 23
    for (int kt = 0; kt < ntiles; kt++) {
        const int k0 = kt * KT;
        const int cnt = min(KT, HW_DIM - k0);
        __syncthreads();   // prev AV readers done before overwriting K/V

        for (int f = tid; f < KT * 36; f += 256) {
            int r = f / 36, c = (f % 36) * 4;
            if (r < cnt) {
                *(float4*)&sm.Ks[r][c] = *(const float4*)(kbase + (size_t)(k0 + r) * DM + c);
                *(float4*)&sm.Vs[r][c] = *(const float4*)(vbase + (size_t)(k0 + r) * DM + c);
            } else {
                *(float4*)&sm.Ks[r][c] = make_float4(0.f, 0.f, 0.f, 0.f);
                *(float4*)&sm.Vs[r][c] = make_float4(0.f, 0.f, 0.f, 0.f);
            }
        }
        if (tid < KT) {
            int j = k0 + tid;
            sm.kpos[tid] = (j < HW_DIM) ? *(const float2*)(fpos + (size_t)j * 2)
                                        : make_float2(0.f, 0.f);
        }
        __syncthreads();

        // ---- scores: thread computes s[m][g + 4*jj], jj = 0..7 ----
        float sc[8];
        #pragma unroll
        for (int jj = 0; jj < 8; jj++) sc[jj] = 0.f;
        #pragma unroll 9
        for (int d4 = 0; d4 < 36; d4++) {
            float4 q = *(const float4*)&sm.Qs[m][d4 * 4];
            #pragma unroll
            for (int jj = 0; jj < 8; jj++) {
                float4 k = *(const float4*)&sm.Ks[g + 4 * jj][d4 * 4];
                sc[jj] += q.x * k.x + q.y * k.y + q.z * k.z + q.w * k.w;
            }
        }
        float2 qp = sm.qpos[m];
        #pragma unroll
        for (int jj = 0; jj < 8; jj++) {
            int j = g + 4 * jj;
            float s;
            if (j < cnt) {
                float2 kp = sm.kpos[j];
                float dx = qp.x - kp.x, dy = qp.y - kp.y;
                s = sc[jj] * (1.f / 12.f) - (dx * dx + dy * dy) * 0.125f;
            } else {
                s = -1e30f;
            }
            sm.Ss[m][j] = s;
        }
        __syncthreads();

        // ---- online softmax + AV for this thread's 36-dim slice ----
        float tmax = mi;
        #pragma unroll
        for (int j = 0; j < KT; j++) tmax = fmaxf(tmax, sm.Ss[m][j]);
        float corr = expf(mi - tmax);
        mi = tmax;
        li *= corr;
        #pragma unroll
        for (int i = 0; i < 9; i++) {
            acc[i].x *= corr; acc[i].y *= corr; acc[i].z *= corr; acc[i].w *= corr;
        }
        #pragma unroll 4
        for (int j = 0; j < KT; j++) {
            float p = expf(sm.Ss[m][j] - mi);
            li += p;
            #pragma unroll
            for (int i = 0; i < 9; i++) {
                float4 v = *(const float4*)&sm.Vs[j][g * 36 + i * 4];
                acc[i].x += p * v.x; acc[i].y += p * v.y;
                acc[i].z += p * v.z; acc[i].w += p * v.w;
            }
        }
    }

    float inv = 1.f / li;
    float* obase = sampled + ((size_t)t * M_TRK + m0 + m) * DM + h * DH + g * 36;
    #pragma unroll
    for (int i = 0; i < 9; i++) {
        float4 v = make_float4(acc[i].x * inv, acc[i].y * inv, acc[i].z * inv, acc[i].w * inv);
        *(float4*)(obase + i * 4) = v;
    }
}

// ---------------- launch ----------------
extern "C" void kernel_launch(void* const* d_in, const int* in_sizes, int n_in,
                              void* d_out, int out_size)
{
    const float* features    = (const float*)d_in[0];
    const float* tracks      = (const float*)d_in[1];
    const float* track_toks  = (const float*)d_in[2];
    const float* fpos        = (const float*)d_in[3];
    const float* W_q         = (const float*)d_in[4];
    const float* W_k         = (const float*)d_in[5];
    const float* q_norm_w    = (const float*)d_in[6];
    const float* k_norm_w    = (const float*)d_in[7];
    const float* out_proj_w  = (const float*)d_in[8];
    float* out = (float*)d_out;

    float *gQ, *gK, *gS;
    cudaGetSymbolAddress((void**)&gQ, g_Q);
    cudaGetSymbolAddress((void**)&gK, g_K);
    cudaGetSymbolAddress((void**)&gS, g_S);

    cudaFuncSetAttribute(attn_kernel, cudaFuncAttributeMaxDynamicSharedMemorySize,
                         (int)sizeof(AttnSmem));

    // Q = track_tokens @ W_q
    {
        dim3 grid(DM / 128, (MQ + 127) / 128);
        sgemm_kernel<<<grid, 256>>>(track_toks, W_q, gQ, MQ, DM, DM);
    }
    // K = features @ W_k
    {
        dim3 grid(DM / 128, (MK + 127) / 128);
        sgemm_kernel<<<grid, 256>>>(features, W_k, gK, MK, DM, DM);
    }
    // LN(Q), RoPE+LN(K)
    ln_kernel<<<MQ, 256>>>(gQ, q_norm_w);
    rope_ln_kernel<<<MK, 256>>>(gK, fpos, k_norm_w);

    // fused attention -> sampled
    {
        dim3 grid(M_TRK / MT, NH, T_DIM);
        attn_kernel<<<grid, 256, sizeof(AttnSmem)>>>(gQ, gK, features, tracks, fpos, gS);
    }
    // out = sampled @ out_proj_w
    {
        dim3 grid(DM / 128, (MQ + 127) / 128);
        sgemm_kernel<<<grid, 256>>>(gS, out_proj_w, out, MQ, DM, DM);
    }
}

// round 4
// speedup vs baseline: 1.3277x; 1.3277x over previous
#include <cuda_runtime.h>
#include <cuda_bf16.h>
#include <math.h>
#include <stdint.h>

// ---------------- problem constants ----------------
#define T_DIM   64
#define HW_DIM  729
#define M_TRK   512
#define DM      1152
#define NH      8
#define DH      144
#define MQ      (T_DIM * M_TRK)    // 32768
#define MK      (T_DIM * HW_DIM)   // 46656

// ---------------- device scratch ----------------
__device__ float g_Q[(size_t)MQ * DM];
__device__ float g_K[(size_t)MK * DM];
__device__ float g_S[(size_t)MQ * DM];
__device__ __nv_bfloat16 g_Ah[(size_t)MK * DM];   // activation hi (max rows = MK)
__device__ __nv_bfloat16 g_Al[(size_t)MK * DM];   // activation lo
__device__ __nv_bfloat16 g_WhT[(size_t)DM * DM];  // weight hi, transposed [N,K]
__device__ __nv_bfloat16 g_WlT[(size_t)DM * DM];  // weight lo, transposed [N,K]

__device__ __forceinline__ uint32_t smem_u32(const void* p) {
    uint32_t a;
    asm("{ .reg .u64 t; cvta.to.shared.u64 t, %1; cvt.u32.u64 %0, t; }" : "=r"(a) : "l"(p));
    return a;
}
__device__ __forceinline__ void cp16(uint32_t dst, const void* src) {
    asm volatile("cp.async.cg.shared.global [%0], [%1], 16;" :: "r"(dst), "l"(src));
}
__device__ __forceinline__ void ldm4(uint32_t addr, uint32_t* r) {
    asm volatile("ldmatrix.sync.aligned.m8n8.x4.shared.b16 {%0,%1,%2,%3}, [%4];"
                 : "=r"(r[0]), "=r"(r[1]), "=r"(r[2]), "=r"(r[3])
                 : "r"(addr) : "memory");
}
__device__ __forceinline__ void mma16816(float* d, const uint32_t* a,
                                         uint32_t b0, uint32_t b1) {
    asm volatile(
        "mma.sync.aligned.m16n8k16.row.col.f32.bf16.bf16.f32 "
        "{%0,%1,%2,%3}, {%4,%5,%6,%7}, {%8,%9}, {%0,%1,%2,%3};"
        : "+f"(d[0]), "+f"(d[1]), "+f"(d[2]), "+f"(d[3])
        : "r"(a[0]), "r"(a[1]), "r"(a[2]), "r"(a[3]), "r"(b0), "r"(b1));
}

// ================= fp32 -> bf16 hi/lo split (activations, row-major) =========
__global__ __launch_bounds__(256)
void split_act_kernel(const float* __restrict__ X, __nv_bfloat16* __restrict__ H,
                      __nv_bfloat16* __restrict__ L, long n4)
{
    long i = (long)blockIdx.x * blockDim.x + threadIdx.x;
    long stride = (long)gridDim.x * blockDim.x;
    for (; i < n4; i += stride) {
        float4 v = ((const float4*)X)[i];
        __nv_bfloat16 h0 = __float2bfloat16_rn(v.x);
        __nv_bfloat16 h1 = __float2bfloat16_rn(v.y);
        __nv_bfloat16 h2 = __float2bfloat16_rn(v.z);
        __nv_bfloat16 h3 = __float2bfloat16_rn(v.w);
        __nv_bfloat16 l0 = __float2bfloat16_rn(v.x - __bfloat162float(h0));
        __nv_bfloat16 l1 = __float2bfloat16_rn(v.y - __bfloat162float(h1));
        __nv_bfloat16 l2 = __float2bfloat16_rn(v.z - __bfloat162float(h2));
        __nv_bfloat16 l3 = __float2bfloat16_rn(v.w - __bfloat162float(h3));
        __nv_bfloat162 hp0; hp0.x = h0; hp0.y = h1;
        __nv_bfloat162 hp1; hp1.x = h2; hp1.y = h3;
        __nv_bfloat162 lp0; lp0.x = l0; lp0.y = l1;
        __nv_bfloat162 lp1; lp1.x = l2; lp1.y = l3;
        ((__nv_bfloat162*)H)[2*i]     = hp0;
        ((__nv_bfloat162*)H)[2*i + 1] = hp1;
        ((__nv_bfloat162*)L)[2*i]     = lp0;
        ((__nv_bfloat162*)L)[2*i + 1] = lp1;
    }
}

// ============ weight split + transpose: W[K,N] fp32 -> Ht,Lt [N,K] bf16 ======
__global__ __launch_bounds__(256)
void split_wt_kernel(const float* __restrict__ W, __nv_bfloat16* __restrict__ Ht,
                     __nv_bfloat16* __restrict__ Lt)
{
    __shared__ float tile[32][33];
    int tx = threadIdx.x & 31, ty = threadIdx.x >> 5;   // 32 x 8
    int nb = blockIdx.x * 32, kb = blockIdx.y * 32;
    #pragma unroll
    for (int r = ty; r < 32; r += 8)
        tile[r][tx] = W[(size_t)(kb + r) * DM + nb + tx];
    __syncthreads();
    #pragma unroll
    for (int r = ty; r < 32; r += 8) {
        float v = tile[tx][r];                 // = W[kb+tx][nb+r]
        __nv_bfloat16 h = __float2bfloat16_rn(v);
        size_t o = (size_t)(nb + r) * DM + kb + tx;
        Ht[o] = h;
        Lt[o] = __float2bfloat16_rn(v - __bfloat162float(h));
    }
}

// =================== mma.sync bf16x3 GEMM ====================================
// C[M, 1152] = A[M,1152] @ B, with Ah/Al row-major [M,K] and BhT/BlT [N,K].
// BM=128, BN=128, BK=32; 8 warps (2M x 4N), warp tile 64x32 of m16n8k16 atoms.
// smem: per stage 4 tiles (Ah, Al, Bh, Bl), each 128 rows x 64B padded to 80B.
#define TPITCH 80
#define TBYTES (128 * TPITCH)          // 10240
#define STAGEB (4 * TBYTES)            // 40960
#define GEMM_SMEM (2 * STAGEB)         // 81920
#define KC 36                          // 1152 / 32

__global__ __launch_bounds__(256, 1)
void gemm_mma_bf16x3(const __nv_bfloat16* __restrict__ Ah, const __nv_bfloat16* __restrict__ Al,
                     const __nv_bfloat16* __restrict__ BhT, const __nv_bfloat16* __restrict__ BlT,
                     float* __restrict__ C, int M)
{
    extern __shared__ char dsm[];
    const int tid  = threadIdx.x;
    const int lane = tid & 31;
    const int wid  = tid >> 5;
    const int wm   = wid & 1;          // 0..1  -> M offset 64*wm
    const int wn   = wid >> 1;         // 0..3  -> N offset 32*wn
    const int n0   = blockIdx.x * 128;
    const int m0   = blockIdx.y * 128;

    uint32_t sb = smem_u32(dsm);

    const char* srcbase[4] = { (const char*)Ah, (const char*)Al,
                               (const char*)BhT, (const char*)BlT };

    float acc[4][4][4];
    #pragma unroll
    for (int i = 0; i < 4; i++)
        #pragma unroll
        for (int j = 0; j < 4; j++)
            #pragma unroll
            for (int q = 0; q < 4; q++) acc[i][j][q] = 0.f;

    // properly-scoped stage loader (no macro shadowing!)
    auto load_stage = [&](int stage, int chunk) {
        uint32_t stb = sb + (uint32_t)stage * (uint32_t)STAGEB;
        #pragma unroll
        for (int it = 0; it < 8; it++) {
            int flat = tid + it * 256;          // 0..2047
            int t4 = flat >> 9;                 // which of 4 tiles
            int r  = (flat >> 2) & 127;         // row in tile
            int c4 = flat & 3;                  // 16B chunk in row
            int grow;
            if (t4 < 2) { grow = m0 + r; if (grow > M - 1) grow = M - 1; }
            else        { grow = n0 + r; }
            const char* src = srcbase[t4] + (size_t)grow * (DM * 2)
                              + (size_t)chunk * 64 + c4 * 16;
            uint32_t dst = stb + (uint32_t)t4 * (uint32_t)TBYTES
                           + (uint32_t)r * TPITCH + (uint32_t)c4 * 16u;
            cp16(dst, src);
        }
        asm volatile("cp.async.commit_group;" ::: "memory");
    };

    load_stage(0, 0);
    load_stage(1, 1);

    const uint32_t aoffH = (uint32_t)(wm * 64 + (lane & 15)) * TPITCH + (uint32_t)(lane >> 4) * 16u;
    const uint32_t boffH = (uint32_t)(wn * 32 + (lane & 15)) * TPITCH + (uint32_t)(lane >> 4) * 16u;

    for (int c = 0; c < KC; c++) {
        const int s = c & 1;
        if (c < KC - 2) asm volatile("cp.async.wait_group 1;" ::: "memory");
        else            asm volatile("cp.async.wait_group 0;" ::: "memory");
        __syncthreads();

        uint32_t stb = sb + (uint32_t)s * (uint32_t)STAGEB;
        uint32_t aH = stb + aoffH;
        uint32_t aL = aH + TBYTES;
        uint32_t bH = stb + 2u * TBYTES + boffH;
        uint32_t bL = bH + TBYTES;

        #pragma unroll
        for (int s16 = 0; s16 < 2; s16++) {
            uint32_t ah[4][4], al[4][4], bh[2][4], bl[2][4];
            #pragma unroll
            for (int a = 0; a < 4; a++) {
                ldm4(aH + a * (16 * TPITCH) + s16 * 32, ah[a]);
                ldm4(aL + a * (16 * TPITCH) + s16 * 32, al[a]);
            }
            #pragma unroll
            for (int b = 0; b < 2; b++) {
                ldm4(bH + b * (16 * TPITCH) + s16 * 32, bh[b]);
                ldm4(bL + b * (16 * TPITCH) + s16 * 32, bl[b]);
            }
            #pragma unroll
            for (int am = 0; am < 4; am++) {
                #pragma unroll
                for (int bt = 0; bt < 2; bt++) {
                    // n-atom lo (n = bt*16 + 0..7):  b-frag {r0, r2}
                    mma16816(acc[am][2*bt],   ah[am], bh[bt][0], bh[bt][2]);
                    mma16816(acc[am][2*bt],   al[am], bh[bt][0], bh[bt][2]);
                    mma16816(acc[am][2*bt],   ah[am], bl[bt][0], bl[bt][2]);
                    // n-atom hi (n = bt*16 + 8..15): b-frag {r1, r3}
                    mma16816(acc[am][2*bt+1], ah[am], bh[bt][1], bh[bt][3]);
                    mma16816(acc[am][2*bt+1], al[am], bh[bt][1], bh[bt][3]);
                    mma16816(acc[am][2*bt+1], ah[am], bl[bt][1], bl[bt][3]);
                }
            }
        }
        __syncthreads();
        if (c + 2 < KC) load_stage(s, c + 2);
    }

    // epilogue: direct fp32 stores
    #pragma unroll
    for (int am = 0; am < 4; am++) {
        int m = m0 + wm * 64 + am * 16 + (lane >> 2);
        #pragma unroll
        for (int bt = 0; bt < 4; bt++) {
            int n = n0 + wn * 32 + bt * 8 + (lane & 3) * 2;
            if (m < M) {
                float2 v = make_float2(acc[am][bt][0], acc[am][bt][1]);
                *(float2*)(C + (size_t)m * DM + n) = v;
            }
            if (m + 8 < M) {
                float2 v = make_float2(acc[am][bt][2], acc[am][bt][3]);
                *(float2*)(C + (size_t)(m + 8) * DM + n) = v;
            }
        }
    }
}

// ---------------- LayerNorm (no bias), in place, one block per row ----------
__device__ __forceinline__ void block_ln_inplace(float* x, const float* __restrict__ w)
{
    __shared__ float red[18];
    float s = 0.f, ss = 0.f;
    for (int i = threadIdx.x; i < DM; i += 256) {
        float v = x[i];
        s += v; ss += v * v;
    }
    #pragma unroll
    for (int o = 16; o; o >>= 1) {
        s  += __shfl_down_sync(0xffffffffu, s, o);
        ss += __shfl_down_sync(0xffffffffu, ss, o);
    }
    int wid = threadIdx.x >> 5, lane = threadIdx.x & 31;
    if (lane == 0) { red[wid] = s; red[8 + wid] = ss; }
    __syncthreads();
    if (threadIdx.x == 0) {
        float S = 0.f, SS = 0.f;
        #pragma unroll
        for (int i = 0; i < 8; i++) { S += red[i]; SS += red[8 + i]; }
        red[16] = S; red[17] = SS;
    }
    __syncthreads();
    float mu  = red[16] * (1.f / DM);
    float var = red[17] * (1.f / DM) - mu * mu;
    float inv = rsqrtf(var + 1e-6f);
    for (int i = threadIdx.x; i < DM; i += 256)
        x[i] = (x[i] - mu) * inv * w[i];
}

__global__ __launch_bounds__(256)
void ln_kernel(float* __restrict__ X, const float* __restrict__ w)
{
    block_ln_inplace(X + (size_t)blockIdx.x * DM, w);
}

__global__ __launch_bounds__(256)
void rope_ln_kernel(float* __restrict__ X, const float* __restrict__ fpos,
                    const float* __restrict__ w)
{
    const int row = blockIdx.x;
    const int n = row % HW_DIM;
    float* x = X + (size_t)row * DM;
    const float px = fpos[2 * n];
    const float py = fpos[2 * n + 1];
    const float TS = -9.210340371976184f / 288.0f;
    for (int p = threadIdx.x; p < 576; p += 256) {
        int q = (p < 288) ? p : (p - 288);
        float theta = expf((float)q * TS);
        float ang = ((p < 288) ? px : py) * theta;
        float c, s;
        sincosf(ang, &s, &c);
        int base = (p < 288) ? (2 * q) : (576 + 2 * q);
        float a = x[base], b = x[base + 1];
        x[base]     = a * c - b * s;
        x[base + 1] = a * s + b * c;
    }
    __syncthreads();
    block_ln_inplace(x, w);
}

// ---------------- fused attention (flash-style, fp32) -----------------------
#define MT 64
#define KT 32
#define KP 148

struct AttnSmem {
    float Qs[MT][KP];
    float Ks[KT][KP];
    float Vs[KT][KP];
    float Ss[MT][KT + 1];
    float2 qpos[MT];
    float2 kpos[KT];
};

__global__ __launch_bounds__(256)
void attn_kernel(const float* __restrict__ Qln, const float* __restrict__ Kln,
                 const float* __restrict__ features, const float* __restrict__ tracks,
                 const float* __restrict__ fpos, float* __restrict__ sampled)
{
    extern __shared__ char smem_raw[];
    AttnSmem& sm = *reinterpret_cast<AttnSmem*>(smem_raw);

    const int tid = threadIdx.x;
    const int mt = blockIdx.x;
    const int h  = blockIdx.y;
    const int t  = blockIdx.z;
    const int m0 = mt * MT;

    const float* qbase = Qln      + ((size_t)t * M_TRK + m0) * DM + h * DH;
    const float* kbase = Kln      + (size_t)t * HW_DIM * DM + h * DH;
    const float* vbase = features + (size_t)t * HW_DIM * DM + h * DH;

    for (int f = tid; f < MT * (DH / 4); f += 256) {
        int r = f / 36, c = (f % 36) * 4;
        *(float4*)&sm.Qs[r][c] = *(const float4*)(qbase + (size_t)r * DM + c);
    }
    if (tid < MT)
        sm.qpos[tid] = *(const float2*)(tracks + ((size_t)t * M_TRK + m0 + tid) * 2);

    const int m = tid / 4;
    const int g = tid % 4;

    float mi = -1e30f, li = 0.f;
    float4 acc[9];
    #pragma unroll
    for (int i = 0; i < 9; i++) acc[i] = make_float4(0.f, 0.f, 0.f, 0.f);

    const int ntiles = (HW_DIM + KT - 1) / KT;
    for (int kt = 0; kt < ntiles; kt++) {
        const int k0 = kt * KT;
        const int cnt = min(KT, HW_DIM - k0);
        __syncthreads();

        for (int f = tid; f < KT * 36; f += 256) {
            int r = f / 36, c = (f % 36) * 4;
            if (r < cnt) {
                *(float4*)&sm.Ks[r][c] = *(const float4*)(kbase + (size_t)(k0 + r) * DM + c);
                *(float4*)&sm.Vs[r][c] = *(const float4*)(vbase + (size_t)(k0 + r) * DM + c);
            } else {
                *(float4*)&sm.Ks[r][c] = make_float4(0.f, 0.f, 0.f, 0.f);
                *(float4*)&sm.Vs[r][c] = make_float4(0.f, 0.f, 0.f, 0.f);
            }
        }
        if (tid < KT) {
            int j = k0 + tid;
            sm.kpos[tid] = (j < HW_DIM) ? *(const float2*)(fpos + (size_t)j * 2)
                                        : make_float2(0.f, 0.f);
        }
        __syncthreads();

        float sc[8];
        #pragma unroll
        for (int jj = 0; jj < 8; jj++) sc[jj] = 0.f;
        #pragma unroll 9
        for (int d4 = 0; d4 < 36; d4++) {
            float4 q = *(const float4*)&sm.Qs[m][d4 * 4];
            #pragma unroll
            for (int jj = 0; jj < 8; jj++) {
                float4 k = *(const float4*)&sm.Ks[g + 4 * jj][d4 * 4];
                sc[jj] += q.x * k.x + q.y * k.y + q.z * k.z + q.w * k.w;
            }
        }
        float2 qp = sm.qpos[m];
        #pragma unroll
        for (int jj = 0; jj < 8; jj++) {
            int j = g + 4 * jj;
            float s;
            if (j < cnt) {
                float2 kp = sm.kpos[j];
                float dx = qp.x - kp.x, dy = qp.y - kp.y;
                s = sc[jj] * (1.f / 12.f) - (dx * dx + dy * dy) * 0.125f;
            } else {
                s = -1e30f;
            }
            sm.Ss[m][j] = s;
        }
        __syncthreads();

        float tmax = mi;
        #pragma unroll
        for (int j = 0; j < KT; j++) tmax = fmaxf(tmax, sm.Ss[m][j]);
        float corr = expf(mi - tmax);
        mi = tmax;
        li *= corr;
        #pragma unroll
        for (int i = 0; i < 9; i++) {
            acc[i].x *= corr; acc[i].y *= corr; acc[i].z *= corr; acc[i].w *= corr;
        }
        #pragma unroll 4
        for (int j = 0; j < KT; j++) {
            float p = expf(sm.Ss[m][j] - mi);
            li += p;
            #pragma unroll
            for (int i = 0; i < 9; i++) {
                float4 v = *(const float4*)&sm.Vs[j][g * 36 + i * 4];
                acc[i].x += p * v.x; acc[i].y += p * v.y;
                acc[i].z += p * v.z; acc[i].w += p * v.w;
            }
        }
    }

    float inv = 1.f / li;
    float* obase = sampled + ((size_t)t * M_TRK + m0 + m) * DM + h * DH + g * 36;
    #pragma unroll
    for (int i = 0; i < 9; i++) {
        float4 v = make_float4(acc[i].x * inv, acc[i].y * inv, acc[i].z * inv, acc[i].w * inv);
        *(float4*)(obase + i * 4) = v;
    }
}

// ---------------- launch ----------------
extern "C" void kernel_launch(void* const* d_in, const int* in_sizes, int n_in,
                              void* d_out, int out_size)
{
    const float* features    = (const float*)d_in[0];
    const float* tracks      = (const float*)d_in[1];
    const float* track_toks  = (const float*)d_in[2];
    const float* fpos        = (const float*)d_in[3];
    const float* W_q         = (const float*)d_in[4];
    const float* W_k         = (const float*)d_in[5];
    const float* q_norm_w    = (const float*)d_in[6];
    const float* k_norm_w    = (const float*)d_in[7];
    const float* out_proj_w  = (const float*)d_in[8];
    float* out = (float*)d_out;

    float *gQ, *gK, *gS;
    __nv_bfloat16 *gAh, *gAl, *gWh, *gWl;
    cudaGetSymbolAddress((void**)&gQ, g_Q);
    cudaGetSymbolAddress((void**)&gK, g_K);
    cudaGetSymbolAddress((void**)&gS, g_S);
    cudaGetSymbolAddress((void**)&gAh, g_Ah);
    cudaGetSymbolAddress((void**)&gAl, g_Al);
    cudaGetSymbolAddress((void**)&gWh, g_WhT);
    cudaGetSymbolAddress((void**)&gWl, g_WlT);

    cudaFuncSetAttribute(attn_kernel, cudaFuncAttributeMaxDynamicSharedMemorySize,
                         (int)sizeof(AttnSmem));
    cudaFuncSetAttribute(gemm_mma_bf16x3, cudaFuncAttributeMaxDynamicSharedMemorySize,
                         GEMM_SMEM);

    dim3 wtg(DM / 32, DM / 32);

    // ---- Q = track_tokens @ W_q ----
    split_wt_kernel<<<wtg, 256>>>(W_q, gWh, gWl);
    split_act_kernel<<<4096, 256>>>(track_toks, gAh, gAl, (long)MQ * DM / 4);
    {
        dim3 g(DM / 128, (MQ + 127) / 128);
        gemm_mma_bf16x3<<<g, 256, GEMM_SMEM>>>(gAh, gAl, gWh, gWl, gQ, MQ);
    }

    // ---- K = features @ W_k ----
    split_wt_kernel<<<wtg, 256>>>(W_k, gWh, gWl);
    split_act_kernel<<<4096, 256>>>(features, gAh, gAl, (long)MK * DM / 4);
    {
        dim3 g(DM / 128, (MK + 127) / 128);
        gemm_mma_bf16x3<<<g, 256, GEMM_SMEM>>>(gAh, gAl, gWh, gWl, gK, MK);
    }

    // ---- LN(Q), RoPE+LN(K) ----
    ln_kernel<<<MQ, 256>>>(gQ, q_norm_w);
    rope_ln_kernel<<<MK, 256>>>(gK, fpos, k_norm_w);

    // ---- fused attention ----
    {
        dim3 g(M_TRK / MT, NH, T_DIM);
        attn_kernel<<<g, 256, sizeof(AttnSmem)>>>(gQ, gK, features, tracks, fpos, gS);
    }

    // ---- out = sampled @ out_proj_w ----
    split_wt_kernel<<<wtg, 256>>>(out_proj_w, gWh, gWl);
    split_act_kernel<<<4096, 256>>>(gS, gAh, gAl, (long)MQ * DM / 4);
    {
        dim3 g(DM / 128, (MQ + 127) / 128);
        gemm_mma_bf16x3<<<g, 256, GEMM_SMEM>>>(gAh, gAl, gWh, gWl, out, MQ);
    }
}

// round 5
// speedup vs baseline: 3.1129x; 2.3446x over previous
#include <cuda_runtime.h>
#include <cuda_bf16.h>
#include <cuda_fp16.h>
#include <math.h>
#include <stdint.h>

// ---------------- problem constants ----------------
#define T_DIM   64
#define HW_DIM  729
#define M_TRK   512
#define DM      1152
#define NH      8
#define DH      144
#define MQ      (T_DIM * M_TRK)    // 32768
#define MK      (T_DIM * HW_DIM)   // 46656

// ---------------- device scratch ----------------
__device__ float g_Q[(size_t)MQ * DM];
__device__ float g_K[(size_t)MK * DM];
__device__ float g_S[(size_t)MQ * DM];
__device__ __nv_bfloat16 g_Ah[(size_t)MK * DM];
__device__ __nv_bfloat16 g_Al[(size_t)MK * DM];
__device__ __nv_bfloat16 g_WhT[(size_t)DM * DM];
__device__ __nv_bfloat16 g_WlT[(size_t)DM * DM];
__device__ __half g_Qh[(size_t)MQ * DM];   // LN'd Q fp16
__device__ __half g_Kh[(size_t)MK * DM];   // LN'd+RoPE'd K fp16 hi
__device__ __half g_Kl[(size_t)MK * DM];   // residual lo
__device__ __half g_Vh[(size_t)MK * DM];   // features fp16

__device__ __forceinline__ uint32_t smem_u32(const void* p) {
    uint32_t a;
    asm("{ .reg .u64 t; cvta.to.shared.u64 t, %1; cvt.u32.u64 %0, t; }" : "=r"(a) : "l"(p));
    return a;
}
__device__ __forceinline__ void cp16(uint32_t dst, const void* src) {
    asm volatile("cp.async.cg.shared.global [%0], [%1], 16;" :: "r"(dst), "l"(src));
}
__device__ __forceinline__ void ldm4(uint32_t addr, uint32_t* r) {
    asm volatile("ldmatrix.sync.aligned.m8n8.x4.shared.b16 {%0,%1,%2,%3}, [%4];"
                 : "=r"(r[0]), "=r"(r[1]), "=r"(r[2]), "=r"(r[3])
                 : "r"(addr) : "memory");
}
__device__ __forceinline__ void ldm4t(uint32_t addr, uint32_t* r) {
    asm volatile("ldmatrix.sync.aligned.m8n8.x4.trans.shared.b16 {%0,%1,%2,%3}, [%4];"
                 : "=r"(r[0]), "=r"(r[1]), "=r"(r[2]), "=r"(r[3])
                 : "r"(addr) : "memory");
}
__device__ __forceinline__ void mma_bf16(float* d, const uint32_t* a,
                                         uint32_t b0, uint32_t b1) {
    asm volatile(
        "mma.sync.aligned.m16n8k16.row.col.f32.bf16.bf16.f32 "
        "{%0,%1,%2,%3}, {%4,%5,%6,%7}, {%8,%9}, {%0,%1,%2,%3};"
        : "+f"(d[0]), "+f"(d[1]), "+f"(d[2]), "+f"(d[3])
        : "r"(a[0]), "r"(a[1]), "r"(a[2]), "r"(a[3]), "r"(b0), "r"(b1));
}
__device__ __forceinline__ void mma_f16(float* d, const uint32_t* a,
                                        uint32_t b0, uint32_t b1) {
    asm volatile(
        "mma.sync.aligned.m16n8k16.row.col.f32.f16.f16.f32 "
        "{%0,%1,%2,%3}, {%4,%5,%6,%7}, {%8,%9}, {%0,%1,%2,%3};"
        : "+f"(d[0]), "+f"(d[1]), "+f"(d[2]), "+f"(d[3])
        : "r"(a[0]), "r"(a[1]), "r"(a[2]), "r"(a[3]), "r"(b0), "r"(b1));
}
__device__ __forceinline__ uint32_t pack_h2(float a, float b) {
    __half2 h = __floats2half2_rn(a, b);
    return *(uint32_t*)&h;
}

// ================= fp32 -> bf16 hi/lo split (activations) ====================
__global__ __launch_bounds__(256)
void split_act_kernel(const float* __restrict__ X, __nv_bfloat16* __restrict__ H,
                      __nv_bfloat16* __restrict__ L, long n4)
{
    long i = (long)blockIdx.x * blockDim.x + threadIdx.x;
    long stride = (long)gridDim.x * blockDim.x;
    for (; i < n4; i += stride) {
        float4 v = ((const float4*)X)[i];
        __nv_bfloat16 h0 = __float2bfloat16_rn(v.x);
        __nv_bfloat16 h1 = __float2bfloat16_rn(v.y);
        __nv_bfloat16 h2 = __float2bfloat16_rn(v.z);
        __nv_bfloat16 h3 = __float2bfloat16_rn(v.w);
        __nv_bfloat16 l0 = __float2bfloat16_rn(v.x - __bfloat162float(h0));
        __nv_bfloat16 l1 = __float2bfloat16_rn(v.y - __bfloat162float(h1));
        __nv_bfloat16 l2 = __float2bfloat16_rn(v.z - __bfloat162float(h2));
        __nv_bfloat16 l3 = __float2bfloat16_rn(v.w - __bfloat162float(h3));
        __nv_bfloat162 hp0; hp0.x = h0; hp0.y = h1;
        __nv_bfloat162 hp1; hp1.x = h2; hp1.y = h3;
        __nv_bfloat162 lp0; lp0.x = l0; lp0.y = l1;
        __nv_bfloat162 lp1; lp1.x = l2; lp1.y = l3;
        ((__nv_bfloat162*)H)[2*i]     = hp0;
        ((__nv_bfloat162*)H)[2*i + 1] = hp1;
        ((__nv_bfloat162*)L)[2*i]     = lp0;
        ((__nv_bfloat162*)L)[2*i + 1] = lp1;
    }
}

// ============ weight split + transpose: W[K,N] fp32 -> Ht,Lt [N,K] bf16 ======
__global__ __launch_bounds__(256)
void split_wt_kernel(const float* __restrict__ W, __nv_bfloat16* __restrict__ Ht,
                     __nv_bfloat16* __restrict__ Lt)
{
    __shared__ float tile[32][33];
    int tx = threadIdx.x & 31, ty = threadIdx.x >> 5;
    int nb = blockIdx.x * 32, kb = blockIdx.y * 32;
    #pragma unroll
    for (int r = ty; r < 32; r += 8)
        tile[r][tx] = W[(size_t)(kb + r) * DM + nb + tx];
    __syncthreads();
    #pragma unroll
    for (int r = ty; r < 32; r += 8) {
        float v = tile[tx][r];
        __nv_bfloat16 h = __float2bfloat16_rn(v);
        size_t o = (size_t)(nb + r) * DM + kb + tx;
        Ht[o] = h;
        Lt[o] = __float2bfloat16_rn(v - __bfloat162float(h));
    }
}

// ================= fp32 -> fp16 convert (V) ==================================
__global__ __launch_bounds__(256)
void f32_to_f16_kernel(const float* __restrict__ X, __half* __restrict__ O, long n4)
{
    long i = (long)blockIdx.x * blockDim.x + threadIdx.x;
    long stride = (long)gridDim.x * blockDim.x;
    for (; i < n4; i += stride) {
        float4 v = ((const float4*)X)[i];
        __half2 a = __floats2half2_rn(v.x, v.y);
        __half2 b = __floats2half2_rn(v.z, v.w);
        ((__half2*)O)[2*i]   = a;
        ((__half2*)O)[2*i+1] = b;
    }
}

// =================== mma.sync bf16x3 GEMM (round-4, unchanged) ===============
#define TPITCH 80
#define TBYTES (128 * TPITCH)
#define STAGEB (4 * TBYTES)
#define GEMM_SMEM (2 * STAGEB)
#define KC 36

__global__ __launch_bounds__(256, 1)
void gemm_mma_bf16x3(const __nv_bfloat16* __restrict__ Ah, const __nv_bfloat16* __restrict__ Al,
                     const __nv_bfloat16* __restrict__ BhT, const __nv_bfloat16* __restrict__ BlT,
                     float* __restrict__ C, int M)
{
    extern __shared__ char dsm[];
    const int tid  = threadIdx.x;
    const int lane = tid & 31;
    const int wid  = tid >> 5;
    const int wm   = wid & 1;
    const int wn   = wid >> 1;
    const int n0   = blockIdx.x * 128;
    const int m0   = blockIdx.y * 128;

    uint32_t sb = smem_u32(dsm);
    const char* srcbase[4] = { (const char*)Ah, (const char*)Al,
                               (const char*)BhT, (const char*)BlT };

    float acc[4][4][4];
    #pragma unroll
    for (int i = 0; i < 4; i++)
        #pragma unroll
        for (int j = 0; j < 4; j++)
            #pragma unroll
            for (int q = 0; q < 4; q++) acc[i][j][q] = 0.f;

    auto load_stage = [&](int stage, int chunk) {
        uint32_t stb = sb + (uint32_t)stage * (uint32_t)STAGEB;
        #pragma unroll
        for (int it = 0; it < 8; it++) {
            int flat = tid + it * 256;
            int t4 = flat >> 9;
            int r  = (flat >> 2) & 127;
            int c4 = flat & 3;
            int grow;
            if (t4 < 2) { grow = m0 + r; if (grow > M - 1) grow = M - 1; }
            else        { grow = n0 + r; }
            const char* src = srcbase[t4] + (size_t)grow * (DM * 2)
                              + (size_t)chunk * 64 + c4 * 16;
            uint32_t dst = stb + (uint32_t)t4 * (uint32_t)TBYTES
                           + (uint32_t)r * TPITCH + (uint32_t)c4 * 16u;
            cp16(dst, src);
        }
        asm volatile("cp.async.commit_group;" ::: "memory");
    };

    load_stage(0, 0);
    load_stage(1, 1);

    const uint32_t aoffH = (uint32_t)(wm * 64 + (lane & 15)) * TPITCH + (uint32_t)(lane >> 4) * 16u;
    const uint32_t boffH = (uint32_t)(wn * 32 + (lane & 15)) * TPITCH + (uint32_t)(lane >> 4) * 16u;

    for (int c = 0; c < KC; c++) {
        const int s = c & 1;
        if (c < KC - 2) asm volatile("cp.async.wait_group 1;" ::: "memory");
        else            asm volatile("cp.async.wait_group 0;" ::: "memory");
        __syncthreads();

        uint32_t stb = sb + (uint32_t)s * (uint32_t)STAGEB;
        uint32_t aH = stb + aoffH;
        uint32_t aL = aH + TBYTES;
        uint32_t bH = stb + 2u * TBYTES + boffH;
        uint32_t bL = bH + TBYTES;

        #pragma unroll
        for (int s16 = 0; s16 < 2; s16++) {
            uint32_t ah[4][4], al[4][4], bh[2][4], bl[2][4];
            #pragma unroll
            for (int a = 0; a < 4; a++) {
                ldm4(aH + a * (16 * TPITCH) + s16 * 32, ah[a]);
                ldm4(aL + a * (16 * TPITCH) + s16 * 32, al[a]);
            }
            #pragma unroll
            for (int b = 0; b < 2; b++) {
                ldm4(bH + b * (16 * TPITCH) + s16 * 32, bh[b]);
                ldm4(bL + b * (16 * TPITCH) + s16 * 32, bl[b]);
            }
            #pragma unroll
            for (int am = 0; am < 4; am++) {
                #pragma unroll
                for (int bt = 0; bt < 2; bt++) {
                    mma_bf16(acc[am][2*bt],   ah[am], bh[bt][0], bh[bt][2]);
                    mma_bf16(acc[am][2*bt],   al[am], bh[bt][0], bh[bt][2]);
                    mma_bf16(acc[am][2*bt],   ah[am], bl[bt][0], bl[bt][2]);
                    mma_bf16(acc[am][2*bt+1], ah[am], bh[bt][1], bh[bt][3]);
                    mma_bf16(acc[am][2*bt+1], al[am], bh[bt][1], bh[bt][3]);
                    mma_bf16(acc[am][2*bt+1], ah[am], bl[bt][1], bl[bt][3]);
                }
            }
        }
        __syncthreads();
        if (c + 2 < KC) load_stage(s, c + 2);
    }

    #pragma unroll
    for (int am = 0; am < 4; am++) {
        int m = m0 + wm * 64 + am * 16 + (lane >> 2);
        #pragma unroll
        for (int bt = 0; bt < 4; bt++) {
            int n = n0 + wn * 32 + bt * 8 + (lane & 3) * 2;
            if (m < M)
                *(float2*)(C + (size_t)m * DM + n) = make_float2(acc[am][bt][0], acc[am][bt][1]);
            if (m + 8 < M)
                *(float2*)(C + (size_t)(m + 8) * DM + n) = make_float2(acc[am][bt][2], acc[am][bt][3]);
        }
    }
}

// ---------------- LayerNorm helpers ------------------------------------------
__device__ __forceinline__ void block_ln_stats(const float* x, float& mu, float& inv)
{
    __shared__ float red[18];
    float s = 0.f, ss = 0.f;
    for (int i = threadIdx.x; i < DM; i += 256) {
        float v = x[i];
        s += v; ss += v * v;
    }
    #pragma unroll
    for (int o = 16; o; o >>= 1) {
        s  += __shfl_down_sync(0xffffffffu, s, o);
        ss += __shfl_down_sync(0xffffffffu, ss, o);
    }
    int wid = threadIdx.x >> 5, lane = threadIdx.x & 31;
    if (lane == 0) { red[wid] = s; red[8 + wid] = ss; }
    __syncthreads();
    if (threadIdx.x == 0) {
        float S = 0.f, SS = 0.f;
        #pragma unroll
        for (int i = 0; i < 8; i++) { S += red[i]; SS += red[8 + i]; }
        red[16] = S; red[17] = SS;
    }
    __syncthreads();
    mu  = red[16] * (1.f / DM);
    float var = red[17] * (1.f / DM) - mu * mu;
    inv = rsqrtf(var + 1e-6f);
}

// LN(Q) -> fp16
__global__ __launch_bounds__(256)
void ln_f16_kernel(const float* __restrict__ X, const float* __restrict__ w,
                   __half* __restrict__ O)
{
    const float* x = X + (size_t)blockIdx.x * DM;
    __half* o = O + (size_t)blockIdx.x * DM;
    float mu, inv;
    block_ln_stats(x, mu, inv);
    for (int i = threadIdx.x; i < DM; i += 256)
        o[i] = __float2half_rn((x[i] - mu) * inv * w[i]);
}

// RoPE + LN(K) -> fp16 hi/lo
__global__ __launch_bounds__(256)
void rope_ln_f16_kernel(float* __restrict__ X, const float* __restrict__ fpos,
                        const float* __restrict__ w,
                        __half* __restrict__ Oh, __half* __restrict__ Ol)
{
    const int row = blockIdx.x;
    const int n = row % HW_DIM;
    float* x = X + (size_t)row * DM;
    const float px = fpos[2 * n];
    const float py = fpos[2 * n + 1];
    const float TS = -9.210340371976184f / 288.0f;
    for (int p = threadIdx.x; p < 576; p += 256) {
        int q = (p < 288) ? p : (p - 288);
        float theta = expf((float)q * TS);
        float ang = ((p < 288) ? px : py) * theta;
        float c, s;
        sincosf(ang, &s, &c);
        int base = (p < 288) ? (2 * q) : (576 + 2 * q);
        float a = x[base], b = x[base + 1];
        x[base]     = a * c - b * s;
        x[base + 1] = a * s + b * c;
    }
    __syncthreads();
    float mu, inv;
    block_ln_stats(x, mu, inv);
    __half* oh = Oh + (size_t)row * DM;
    __half* ol = Ol + (size_t)row * DM;
    for (int i = threadIdx.x; i < DM; i += 256) {
        float y = (x[i] - mu) * inv * w[i];
        __half h = __float2half_rn(y);
        oh[i] = h;
        ol[i] = __float2half_rn(y - __half2float(h));
    }
}

// ---------------- tensor-core fused attention --------------------------------
// block: 128 queries x one (t, h); 8 warps x 16 rows. keys tiled by 64.
// smem: double-buffered Kh/Kl/Vh tiles (64 x 144 fp16, pitch 152 halfs) + kpos.
#define APITCH 304                  // bytes per row (152 halfs)
#define ATSZ   (64 * APITCH)        // 19456 one tile
#define ASTG   (3 * ATSZ)           // 58368 per stage (Kh, Kl, Vh)
#define AKPOS  (2 * ASTG)           // 116736
#define ATTN_SMEM (AKPOS + 2 * 512) // 117760

__global__ __launch_bounds__(256, 1)
void attn_mma_kernel(const __half* __restrict__ Qh, const __half* __restrict__ Kh,
                     const __half* __restrict__ Kl, const __half* __restrict__ Vh,
                     const float* __restrict__ tracks, const float* __restrict__ fpos,
                     float* __restrict__ sampled)
{
    extern __shared__ char sm[];
    uint32_t sb = smem_u32(sm);
    const int tid  = threadIdx.x;
    const int lane = tid & 31;
    const int w    = tid >> 5;
    const int gid  = lane >> 2;
    const int tig  = lane & 3;
    const int m0   = blockIdx.x * 128;
    const int h    = blockIdx.y;
    const int t    = blockIdx.z;

    const char* qbase  = (const char*)(Qh + ((size_t)t * M_TRK + m0) * DM + h * DH);
    const char* khbase = (const char*)(Kh + (size_t)t * HW_DIM * DM + h * DH);
    const char* klbase = (const char*)(Kl + (size_t)t * HW_DIM * DM + h * DH);
    const char* vbase  = (const char*)(Vh + (size_t)t * HW_DIM * DM + h * DH);

    // query positions for this thread's two rows
    float2 qp0 = *(const float2*)(tracks + ((size_t)t * M_TRK + m0 + w * 16 + gid) * 2);
    float2 qp1 = *(const float2*)(tracks + ((size_t)t * M_TRK + m0 + w * 16 + gid + 8) * 2);

    // ---- stage Q (128 rows x 18 16B-chunks) into stage-0 buffer, frag to regs
    #pragma unroll
    for (int i = 0; i < 9; i++) {
        int c = tid + i * 256;              // 0..2303
        int row = c / 18, ch = c % 18;
        cp16(sb + row * APITCH + ch * 16, qbase + (size_t)row * (DM * 2) + ch * 16);
    }
    asm volatile("cp.async.commit_group;" ::: "memory");
    asm volatile("cp.async.wait_group 0;" ::: "memory");
    __syncthreads();

    uint32_t qf[9][4];
    {
        uint32_t qa = sb + (uint32_t)(w * 16 + (lane & 15)) * APITCH + (uint32_t)(lane >> 4) * 16u;
        #pragma unroll
        for (int kc = 0; kc < 9; kc++) ldm4(qa + kc * 32, qf[kc]);
    }
    __syncthreads();

    auto load_tile = [&](int st, int kt) {
        int k0 = kt * 64;
        uint32_t stb = sb + (uint32_t)st * (uint32_t)ASTG;
        #pragma unroll
        for (int i = 0; i < 14; i++) {
            int c = tid + i * 256;
            if (c < 3456) {
                int buf = c / 1152, rem = c % 1152;
                int row = rem / 18, ch = rem % 18;
                int krow = k0 + row; if (krow > HW_DIM - 1) krow = HW_DIM - 1;
                const char* src = (buf == 0) ? khbase : (buf == 1) ? klbase : vbase;
                cp16(stb + (uint32_t)buf * (uint32_t)ATSZ + (uint32_t)row * APITCH + (uint32_t)ch * 16u,
                     src + (size_t)krow * (DM * 2) + ch * 16);
            }
        }
        asm volatile("cp.async.commit_group;" ::: "memory");
        if (tid < 64) {
            int kr = k0 + tid; if (kr > HW_DIM - 1) kr = HW_DIM - 1;
            float2 v = *(const float2*)(fpos + (size_t)kr * 2);
            *(float2*)(sm + AKPOS + st * 512 + tid * 8) = v;
        }
    };

    load_tile(0, 0);
    load_tile(1, 1);

    float m_0 = -1e30f, m_1 = -1e30f, l_0 = 0.f, l_1 = 0.f;
    float oacc[18][4];
    #pragma unroll
    for (int a = 0; a < 18; a++)
        #pragma unroll
        for (int q = 0; q < 4; q++) oacc[a][q] = 0.f;

    const int NT = (HW_DIM + 63) / 64;   // 12
    for (int kt = 0; kt < NT; kt++) {
        const int st = kt & 1;
        const int k0 = kt * 64;
        const int cnt = min(64, HW_DIM - k0);
        if (kt < NT - 1) asm volatile("cp.async.wait_group 1;" ::: "memory");
        else             asm volatile("cp.async.wait_group 0;" ::: "memory");
        __syncthreads();

        uint32_t stb = sb + (uint32_t)st * (uint32_t)ASTG;
        uint32_t lrow = (uint32_t)(lane & 15) * APITCH + (uint32_t)(lane >> 4) * 16u;
        uint32_t khb = stb + lrow;
        uint32_t klb = khb + ATSZ;
        uint32_t vhb = stb + 2u * ATSZ + lrow;

        // ---- scores S (16 x 64), 2-pass fp16 compensated
        float sacc[8][4];
        #pragma unroll
        for (int a = 0; a < 8; a++)
            #pragma unroll
            for (int q = 0; q < 4; q++) sacc[a][q] = 0.f;

        #pragma unroll
        for (int kc = 0; kc < 9; kc++) {
            uint32_t bh[4][4], bl[4][4];
            #pragma unroll
            for (int g = 0; g < 4; g++) {
                ldm4(khb + g * (16 * APITCH) + kc * 32, bh[g]);
                ldm4(klb + g * (16 * APITCH) + kc * 32, bl[g]);
            }
            #pragma unroll
            for (int g = 0; g < 4; g++) {
                mma_f16(sacc[2*g],   qf[kc], bh[g][0], bh[g][2]);
                mma_f16(sacc[2*g],   qf[kc], bl[g][0], bl[g][2]);
                mma_f16(sacc[2*g+1], qf[kc], bh[g][1], bh[g][3]);
                mma_f16(sacc[2*g+1], qf[kc], bl[g][1], bl[g][3]);
            }
        }

        // ---- bias + mask + online softmax
        const float2* kp = (const float2*)(sm + AKPOS + st * 512);
        float mn0 = m_0, mn1 = m_1;
        #pragma unroll
        for (int a = 0; a < 8; a++) {
            int c0 = a * 8 + tig * 2;
            float2 ka = kp[c0];
            float2 kb = kp[c0 + 1];
            float dxa0 = qp0.x - ka.x, dya0 = qp0.y - ka.y;
            float dxb0 = qp0.x - kb.x, dyb0 = qp0.y - kb.y;
            float dxa1 = qp1.x - ka.x, dya1 = qp1.y - ka.y;
            float dxb1 = qp1.x - kb.x, dyb1 = qp1.y - kb.y;
            bool va = (c0 < cnt), vb = (c0 + 1 < cnt);
            sacc[a][0] = va ? sacc[a][0] * (1.f/12.f) - (dxa0*dxa0 + dya0*dya0) * 0.125f : -1e30f;
            sacc[a][1] = vb ? sacc[a][1] * (1.f/12.f) - (dxb0*dxb0 + dyb0*dyb0) * 0.125f : -1e30f;
            sacc[a][2] = va ? sacc[a][2] * (1.f/12.f) - (dxa1*dxa1 + dya1*dya1) * 0.125f : -1e30f;
            sacc[a][3] = vb ? sacc[a][3] * (1.f/12.f) - (dxb1*dxb1 + dyb1*dyb1) * 0.125f : -1e30f;
            mn0 = fmaxf(mn0, fmaxf(sacc[a][0], sacc[a][1]));
            mn1 = fmaxf(mn1, fmaxf(sacc[a][2], sacc[a][3]));
        }
        mn0 = fmaxf(mn0, __shfl_xor_sync(0xffffffffu, mn0, 1));
        mn0 = fmaxf(mn0, __shfl_xor_sync(0xffffffffu, mn0, 2));
        mn1 = fmaxf(mn1, __shfl_xor_sync(0xffffffffu, mn1, 1));
        mn1 = fmaxf(mn1, __shfl_xor_sync(0xffffffffu, mn1, 2));
        float corr0 = __expf(m_0 - mn0);
        float corr1 = __expf(m_1 - mn1);
        m_0 = mn0; m_1 = mn1;
        l_0 *= corr0; l_1 *= corr1;
        #pragma unroll
        for (int a = 0; a < 18; a++) {
            oacc[a][0] *= corr0; oacc[a][1] *= corr0;
            oacc[a][2] *= corr1; oacc[a][3] *= corr1;
        }
        #pragma unroll
        for (int a = 0; a < 8; a++) {
            float p0 = __expf(sacc[a][0] - m_0);
            float p1 = __expf(sacc[a][1] - m_0);
            float p2 = __expf(sacc[a][2] - m_1);
            float p3 = __expf(sacc[a][3] - m_1);
            l_0 += p0 + p1; l_1 += p2 + p3;
            sacc[a][0] = p0; sacc[a][1] = p1; sacc[a][2] = p2; sacc[a][3] = p3;
        }

        // ---- AV: O += P (16x64) @ V (64x144)
        #pragma unroll
        for (int kc4 = 0; kc4 < 4; kc4++) {
            uint32_t pa[4];
            pa[0] = pack_h2(sacc[2*kc4][0],   sacc[2*kc4][1]);
            pa[1] = pack_h2(sacc[2*kc4][2],   sacc[2*kc4][3]);
            pa[2] = pack_h2(sacc[2*kc4+1][0], sacc[2*kc4+1][1]);
            pa[3] = pack_h2(sacc[2*kc4+1][2], sacc[2*kc4+1][3]);
            #pragma unroll
            for (int dp = 0; dp < 9; dp++) {
                uint32_t vf[4];
                ldm4t(vhb + kc4 * (16 * APITCH) + dp * 32, vf);
                mma_f16(oacc[2*dp],   pa, vf[0], vf[1]);
                mma_f16(oacc[2*dp+1], pa, vf[2], vf[3]);
            }
        }

        __syncthreads();
        if (kt + 2 < NT) load_tile(st, kt + 2);
    }

    // ---- epilogue
    l_0 += __shfl_xor_sync(0xffffffffu, l_0, 1);
    l_0 += __shfl_xor_sync(0xffffffffu, l_0, 2);
    l_1 += __shfl_xor_sync(0xffffffffu, l_1, 1);
    l_1 += __shfl_xor_sync(0xffffffffu, l_1, 2);
    float inv0 = 1.f / l_0, inv1 = 1.f / l_1;

    size_t row0 = (size_t)t * M_TRK + m0 + w * 16 + gid;
    #pragma unroll
    for (int a = 0; a < 18; a++) {
        int col = h * DH + a * 8 + tig * 2;
        *(float2*)(sampled + row0 * DM + col) =
            make_float2(oacc[a][0] * inv0, oacc[a][1] * inv0);
        *(float2*)(sampled + (row0 + 8) * DM + col) =
            make_float2(oacc[a][2] * inv1, oacc[a][3] * inv1);
    }
}

// ---------------- launch ----------------
extern "C" void kernel_launch(void* const* d_in, const int* in_sizes, int n_in,
                              void* d_out, int out_size)
{
    const float* features    = (const float*)d_in[0];
    const float* tracks      = (const float*)d_in[1];
    const float* track_toks  = (const float*)d_in[2];
    const float* fpos        = (const float*)d_in[3];
    const float* W_q         = (const float*)d_in[4];
    const float* W_k         = (const float*)d_in[5];
    const float* q_norm_w    = (const float*)d_in[6];
    const float* k_norm_w    = (const float*)d_in[7];
    const float* out_proj_w  = (const float*)d_in[8];
    float* out = (float*)d_out;

    float *gQ, *gK, *gS;
    __nv_bfloat16 *gAh, *gAl, *gWh, *gWl;
    __half *gQh, *gKh, *gKl, *gVh;
    cudaGetSymbolAddress((void**)&gQ, g_Q);
    cudaGetSymbolAddress((void**)&gK, g_K);
    cudaGetSymbolAddress((void**)&gS, g_S);
    cudaGetSymbolAddress((void**)&gAh, g_Ah);
    cudaGetSymbolAddress((void**)&gAl, g_Al);
    cudaGetSymbolAddress((void**)&gWh, g_WhT);
    cudaGetSymbolAddress((void**)&gWl, g_WlT);
    cudaGetSymbolAddress((void**)&gQh, g_Qh);
    cudaGetSymbolAddress((void**)&gKh, g_Kh);
    cudaGetSymbolAddress((void**)&gKl, g_Kl);
    cudaGetSymbolAddress((void**)&gVh, g_Vh);

    cudaFuncSetAttribute(gemm_mma_bf16x3, cudaFuncAttributeMaxDynamicSharedMemorySize,
                         GEMM_SMEM);
    cudaFuncSetAttribute(attn_mma_kernel, cudaFuncAttributeMaxDynamicSharedMemorySize,
                         ATTN_SMEM);

    dim3 wtg(DM / 32, DM / 32);

    // ---- Q = track_tokens @ W_q ----
    split_wt_kernel<<<wtg, 256>>>(W_q, gWh, gWl);
    split_act_kernel<<<4096, 256>>>(track_toks, gAh, gAl, (long)MQ * DM / 4);
    {
        dim3 g(DM / 128, (MQ + 127) / 128);
        gemm_mma_bf16x3<<<g, 256, GEMM_SMEM>>>(gAh, gAl, gWh, gWl, gQ, MQ);
    }

    // ---- K = features @ W_k ----
    split_wt_kernel<<<wtg, 256>>>(W_k, gWh, gWl);
    split_act_kernel<<<4096, 256>>>(features, gAh, gAl, (long)MK * DM / 4);
    {
        dim3 g(DM / 128, (MK + 127) / 128);
        gemm_mma_bf16x3<<<g, 256, GEMM_SMEM>>>(gAh, gAl, gWh, gWl, gK, MK);
    }

    // ---- LN(Q)->fp16, RoPE+LN(K)->fp16 hi/lo, V->fp16 ----
    ln_f16_kernel<<<MQ, 256>>>(gQ, q_norm_w, gQh);
    rope_ln_f16_kernel<<<MK, 256>>>(gK, fpos, k_norm_w, gKh, gKl);
    f32_to_f16_kernel<<<4096, 256>>>(features, gVh, (long)MK * DM / 4);

    // ---- fused tensor-core attention ----
    {
        dim3 g(M_TRK / 128, NH, T_DIM);
        attn_mma_kernel<<<g, 256, ATTN_SMEM>>>(gQh, gKh, gKl, gVh, tracks, fpos, gS);
    }

    // ---- out = sampled @ out_proj_w ----
    split_wt_kernel<<<wtg, 256>>>(out_proj_w, gWh, gWl);
    split_act_kernel<<<4096, 256>>>(gS, gAh, gAl, (long)MQ * DM / 4);
    {
        dim3 g(DM / 128, (MQ + 127) / 128);
        gemm_mma_bf16x3<<<g, 256, GEMM_SMEM>>>(gAh, gAl, gWh, gWl, out, MQ);
    }
}

// round 6
// speedup vs baseline: 4.3932x; 1.4113x over previous
#include <cuda_runtime.h>
#include <cuda_fp16.h>
#include <math.h>
#include <stdint.h>

// ---------------- problem constants ----------------
#define T_DIM   64
#define HW_DIM  729
#define M_TRK   512
#define DM      1152
#define NH      8
#define DH      144
#define MQ      (T_DIM * M_TRK)    // 32768
#define MK      (T_DIM * HW_DIM)   // 46656

// ---------------- device scratch ----------------
__device__ float g_Q[(size_t)MQ * DM];     // Q gemm out (fp32)
__device__ float g_K[(size_t)MK * DM];     // K gemm out (fp32)
__device__ __half g_TTh[(size_t)MQ * DM];  // track_tokens hi
__device__ __half g_TTl[(size_t)MQ * DM];  // track_tokens lo
__device__ __half g_Fh[(size_t)MK * DM];   // features hi (also V for attention)
__device__ __half g_Fl[(size_t)MK * DM];   // features lo
__device__ __half g_Wh[(size_t)DM * DM];   // weight fp16, transposed [N,K]
__device__ __half g_Qh[(size_t)MQ * DM];   // LN'd Q fp16
__device__ __half g_Kh[(size_t)MK * DM];   // LN'd+RoPE'd K hi
__device__ __half g_Kl[(size_t)MK * DM];   // K lo
__device__ __half g_Sh[(size_t)MQ * DM];   // attention out hi
__device__ __half g_Sl[(size_t)MQ * DM];   // attention out lo

__device__ __forceinline__ uint32_t smem_u32(const void* p) {
    uint32_t a;
    asm("{ .reg .u64 t; cvta.to.shared.u64 t, %1; cvt.u32.u64 %0, t; }" : "=r"(a) : "l"(p));
    return a;
}
__device__ __forceinline__ void cp16(uint32_t dst, const void* src) {
    asm volatile("cp.async.cg.shared.global [%0], [%1], 16;" :: "r"(dst), "l"(src));
}
__device__ __forceinline__ void ldm4(uint32_t addr, uint32_t* r) {
    asm volatile("ldmatrix.sync.aligned.m8n8.x4.shared.b16 {%0,%1,%2,%3}, [%4];"
                 : "=r"(r[0]), "=r"(r[1]), "=r"(r[2]), "=r"(r[3])
                 : "r"(addr) : "memory");
}
__device__ __forceinline__ void ldm4t(uint32_t addr, uint32_t* r) {
    asm volatile("ldmatrix.sync.aligned.m8n8.x4.trans.shared.b16 {%0,%1,%2,%3}, [%4];"
                 : "=r"(r[0]), "=r"(r[1]), "=r"(r[2]), "=r"(r[3])
                 : "r"(addr) : "memory");
}
__device__ __forceinline__ void mma_f16(float* d, const uint32_t* a,
                                        uint32_t b0, uint32_t b1) {
    asm volatile(
        "mma.sync.aligned.m16n8k16.row.col.f32.f16.f16.f32 "
        "{%0,%1,%2,%3}, {%4,%5,%6,%7}, {%8,%9}, {%0,%1,%2,%3};"
        : "+f"(d[0]), "+f"(d[1]), "+f"(d[2]), "+f"(d[3])
        : "r"(a[0]), "r"(a[1]), "r"(a[2]), "r"(a[3]), "r"(b0), "r"(b1));
}
__device__ __forceinline__ uint32_t pack_h2(float a, float b) {
    __half2 h = __floats2half2_rn(a, b);
    return *(uint32_t*)&h;
}

// ================= fp32 -> fp16 hi/lo split (activations) ====================
__global__ __launch_bounds__(256)
void split_act_f16(const float* __restrict__ X, __half* __restrict__ H,
                   __half* __restrict__ L, long n4)
{
    long i = (long)blockIdx.x * blockDim.x + threadIdx.x;
    long stride = (long)gridDim.x * blockDim.x;
    for (; i < n4; i += stride) {
        float4 v = ((const float4*)X)[i];
        __half h0 = __float2half_rn(v.x);
        __half h1 = __float2half_rn(v.y);
        __half h2 = __float2half_rn(v.z);
        __half h3 = __float2half_rn(v.w);
        __half2 hp0; hp0.x = h0; hp0.y = h1;
        __half2 hp1; hp1.x = h2; hp1.y = h3;
        __half2 lp0 = __floats2half2_rn(v.x - __half2float(h0), v.y - __half2float(h1));
        __half2 lp1 = __floats2half2_rn(v.z - __half2float(h2), v.w - __half2float(h3));
        ((__half2*)H)[2*i]     = hp0;
        ((__half2*)H)[2*i + 1] = hp1;
        ((__half2*)L)[2*i]     = lp0;
        ((__half2*)L)[2*i + 1] = lp1;
    }
}

// ============ weight fp16 + transpose: W[K,N] fp32 -> Ht [N,K] fp16 ==========
__global__ __launch_bounds__(256)
void wt_f16_kernel(const float* __restrict__ W, __half* __restrict__ Ht)
{
    __shared__ float tile[32][33];
    int tx = threadIdx.x & 31, ty = threadIdx.x >> 5;
    int nb = blockIdx.x * 32, kb = blockIdx.y * 32;
    #pragma unroll
    for (int r = ty; r < 32; r += 8)
        tile[r][tx] = W[(size_t)(kb + r) * DM + nb + tx];
    __syncthreads();
    #pragma unroll
    for (int r = ty; r < 32; r += 8)
        Ht[(size_t)(nb + r) * DM + kb + tx] = __float2half_rn(tile[tx][r]);
}

// =================== mma.sync fp16x2 GEMM ====================================
// C[M,1152] = A @ B; Ah/Al fp16 row-major [M,K], BhT fp16 [N,K].
// BM=128, BN=128, BK=32; 8 warps (2M x 4N); 3-stage cp.async pipeline.
#define TPITCH 80
#define TBYTES (128 * TPITCH)          // 10240
#define STAGEB (3 * TBYTES)            // 30720 (Ah, Al, Bh)
#define NSTG   3
#define GEMM_SMEM (NSTG * STAGEB)      // 92160
#define KC 36

__global__ __launch_bounds__(256, 1)
void gemm_mma_f16x2(const __half* __restrict__ Ah, const __half* __restrict__ Al,
                    const __half* __restrict__ BhT, float* __restrict__ C, int M)
{
    extern __shared__ char dsm[];
    const int tid  = threadIdx.x;
    const int lane = tid & 31;
    const int wid  = tid >> 5;
    const int wm   = wid & 1;
    const int wn   = wid >> 1;
    const int n0   = blockIdx.x * 128;
    const int m0   = blockIdx.y * 128;

    uint32_t sb = smem_u32(dsm);
    const char* srcbase[3] = { (const char*)Ah, (const char*)Al, (const char*)BhT };

    float acc[4][4][4];
    #pragma unroll
    for (int i = 0; i < 4; i++)
        #pragma unroll
        for (int j = 0; j < 4; j++)
            #pragma unroll
            for (int q = 0; q < 4; q++) acc[i][j][q] = 0.f;

    auto load_stage = [&](int stage, int chunk) {
        uint32_t stb = sb + (uint32_t)stage * (uint32_t)STAGEB;
        #pragma unroll
        for (int it = 0; it < 6; it++) {
            int flat = tid + it * 256;          // 0..1535
            int t3 = flat >> 9;                 // 0..2
            int r  = (flat >> 2) & 127;
            int c4 = flat & 3;
            int grow;
            if (t3 < 2) { grow = m0 + r; if (grow > M - 1) grow = M - 1; }
            else        { grow = n0 + r; }
            const char* src = srcbase[t3] + (size_t)grow * (DM * 2)
                              + (size_t)chunk * 64 + c4 * 16;
            uint32_t dst = stb + (uint32_t)t3 * (uint32_t)TBYTES
                           + (uint32_t)r * TPITCH + (uint32_t)c4 * 16u;
            cp16(dst, src);
        }
        asm volatile("cp.async.commit_group;" ::: "memory");
    };

    load_stage(0, 0);
    load_stage(1, 1);
    load_stage(2, 2);

    const uint32_t aoffH = (uint32_t)(wm * 64 + (lane & 15)) * TPITCH + (uint32_t)(lane >> 4) * 16u;
    const uint32_t boffH = (uint32_t)(wn * 32 + (lane & 15)) * TPITCH + (uint32_t)(lane >> 4) * 16u;

    for (int c = 0; c < KC; c++) {
        const int s = c % NSTG;
        if (c < KC - NSTG) asm volatile("cp.async.wait_group 2;" ::: "memory");
        else               asm volatile("cp.async.wait_group 0;" ::: "memory");
        __syncthreads();

        uint32_t stb = sb + (uint32_t)s * (uint32_t)STAGEB;
        uint32_t aH = stb + aoffH;
        uint32_t aL = aH + TBYTES;
        uint32_t bH = stb + 2u * TBYTES + boffH;

        #pragma unroll
        for (int s16 = 0; s16 < 2; s16++) {
            uint32_t ah[4][4], al[4][4], bh[2][4];
            #pragma unroll
            for (int a = 0; a < 4; a++) {
                ldm4(aH + a * (16 * TPITCH) + s16 * 32, ah[a]);
                ldm4(aL + a * (16 * TPITCH) + s16 * 32, al[a]);
            }
            #pragma unroll
            for (int b = 0; b < 2; b++)
                ldm4(bH + b * (16 * TPITCH) + s16 * 32, bh[b]);
            #pragma unroll
            for (int am = 0; am < 4; am++) {
                #pragma unroll
                for (int bt = 0; bt < 2; bt++) {
                    mma_f16(acc[am][2*bt],   ah[am], bh[bt][0], bh[bt][2]);
                    mma_f16(acc[am][2*bt],   al[am], bh[bt][0], bh[bt][2]);
                    mma_f16(acc[am][2*bt+1], ah[am], bh[bt][1], bh[bt][3]);
                    mma_f16(acc[am][2*bt+1], al[am], bh[bt][1], bh[bt][3]);
                }
            }
        }
        __syncthreads();
        if (c + NSTG < KC) load_stage(s, c + NSTG);
    }

    #pragma unroll
    for (int am = 0; am < 4; am++) {
        int m = m0 + wm * 64 + am * 16 + (lane >> 2);
        #pragma unroll
        for (int bt = 0; bt < 4; bt++) {
            int n = n0 + wn * 32 + bt * 8 + (lane & 3) * 2;
            if (m < M)
                *(float2*)(C + (size_t)m * DM + n) = make_float2(acc[am][bt][0], acc[am][bt][1]);
            if (m + 8 < M)
                *(float2*)(C + (size_t)(m + 8) * DM + n) = make_float2(acc[am][bt][2], acc[am][bt][3]);
        }
    }
}

// ---------------- LayerNorm helpers ------------------------------------------
__device__ __forceinline__ void block_ln_stats(const float* x, float& mu, float& inv)
{
    __shared__ float red[18];
    float s = 0.f, ss = 0.f;
    for (int i = threadIdx.x; i < DM; i += 256) {
        float v = x[i];
        s += v; ss += v * v;
    }
    #pragma unroll
    for (int o = 16; o; o >>= 1) {
        s  += __shfl_down_sync(0xffffffffu, s, o);
        ss += __shfl_down_sync(0xffffffffu, ss, o);
    }
    int wid = threadIdx.x >> 5, lane = threadIdx.x & 31;
    if (lane == 0) { red[wid] = s; red[8 + wid] = ss; }
    __syncthreads();
    if (threadIdx.x == 0) {
        float S = 0.f, SS = 0.f;
        #pragma unroll
        for (int i = 0; i < 8; i++) { S += red[i]; SS += red[8 + i]; }
        red[16] = S; red[17] = SS;
    }
    __syncthreads();
    mu  = red[16] * (1.f / DM);
    float var = red[17] * (1.f / DM) - mu * mu;
    inv = rsqrtf(var + 1e-6f);
}

// LN(Q) -> fp16
__global__ __launch_bounds__(256)
void ln_f16_kernel(const float* __restrict__ X, const float* __restrict__ w,
                   __half* __restrict__ O)
{
    const float* x = X + (size_t)blockIdx.x * DM;
    __half* o = O + (size_t)blockIdx.x * DM;
    float mu, inv;
    block_ln_stats(x, mu, inv);
    for (int i = threadIdx.x; i < DM; i += 256)
        o[i] = __float2half_rn((x[i] - mu) * inv * w[i]);
}

// RoPE + LN(K) -> fp16 hi/lo
__global__ __launch_bounds__(256)
void rope_ln_f16_kernel(float* __restrict__ X, const float* __restrict__ fpos,
                        const float* __restrict__ w,
                        __half* __restrict__ Oh, __half* __restrict__ Ol)
{
    const int row = blockIdx.x;
    const int n = row % HW_DIM;
    float* x = X + (size_t)row * DM;
    const float px = fpos[2 * n];
    const float py = fpos[2 * n + 1];
    const float TS = -9.210340371976184f / 288.0f;
    for (int p = threadIdx.x; p < 576; p += 256) {
        int q = (p < 288) ? p : (p - 288);
        float theta = expf((float)q * TS);
        float ang = ((p < 288) ? px : py) * theta;
        float c, s;
        sincosf(ang, &s, &c);
        int base = (p < 288) ? (2 * q) : (576 + 2 * q);
        float a = x[base], b = x[base + 1];
        x[base]     = a * c - b * s;
        x[base + 1] = a * s + b * c;
    }
    __syncthreads();
    float mu, inv;
    block_ln_stats(x, mu, inv);
    __half* oh = Oh + (size_t)row * DM;
    __half* ol = Ol + (size_t)row * DM;
    for (int i = threadIdx.x; i < DM; i += 256) {
        float y = (x[i] - mu) * inv * w[i];
        __half h = __float2half_rn(y);
        oh[i] = h;
        ol[i] = __float2half_rn(y - __half2float(h));
    }
}

// ---------------- tensor-core fused attention --------------------------------
#define APITCH 304
#define ATSZ   (64 * APITCH)
#define ASTG   (3 * ATSZ)
#define AKPOS  (2 * ASTG)
#define ATTN_SMEM (AKPOS + 2 * 512)

__global__ __launch_bounds__(256, 1)
void attn_mma_kernel(const __half* __restrict__ Qh, const __half* __restrict__ Kh,
                     const __half* __restrict__ Kl, const __half* __restrict__ Vh,
                     const float* __restrict__ tracks, const float* __restrict__ fpos,
                     __half* __restrict__ Sh, __half* __restrict__ Sl)
{
    extern __shared__ char sm[];
    uint32_t sb = smem_u32(sm);
    const int tid  = threadIdx.x;
    const int lane = tid & 31;
    const int w    = tid >> 5;
    const int gid  = lane >> 2;
    const int tig  = lane & 3;
    const int m0   = blockIdx.x * 128;
    const int h    = blockIdx.y;
    const int t    = blockIdx.z;

    const char* qbase  = (const char*)(Qh + ((size_t)t * M_TRK + m0) * DM + h * DH);
    const char* khbase = (const char*)(Kh + (size_t)t * HW_DIM * DM + h * DH);
    const char* klbase = (const char*)(Kl + (size_t)t * HW_DIM * DM + h * DH);
    const char* vbase  = (const char*)(Vh + (size_t)t * HW_DIM * DM + h * DH);

    float2 qp0 = *(const float2*)(tracks + ((size_t)t * M_TRK + m0 + w * 16 + gid) * 2);
    float2 qp1 = *(const float2*)(tracks + ((size_t)t * M_TRK + m0 + w * 16 + gid + 8) * 2);

    #pragma unroll
    for (int i = 0; i < 9; i++) {
        int c = tid + i * 256;
        int row = c / 18, ch = c % 18;
        cp16(sb + row * APITCH + ch * 16, qbase + (size_t)row * (DM * 2) + ch * 16);
    }
    asm volatile("cp.async.commit_group;" ::: "memory");
    asm volatile("cp.async.wait_group 0;" ::: "memory");
    __syncthreads();

    uint32_t qf[9][4];
    {
        uint32_t qa = sb + (uint32_t)(w * 16 + (lane & 15)) * APITCH + (uint32_t)(lane >> 4) * 16u;
        #pragma unroll
        for (int kc = 0; kc < 9; kc++) ldm4(qa + kc * 32, qf[kc]);
    }
    __syncthreads();

    auto load_tile = [&](int st, int kt) {
        int k0 = kt * 64;
        uint32_t stb = sb + (uint32_t)st * (uint32_t)ASTG;
        #pragma unroll
        for (int i = 0; i < 14; i++) {
            int c = tid + i * 256;
            if (c < 3456) {
                int buf = c / 1152, rem = c % 1152;
                int row = rem / 18, ch = rem % 18;
                int krow = k0 + row; if (krow > HW_DIM - 1) krow = HW_DIM - 1;
                const char* src = (buf == 0) ? khbase : (buf == 1) ? klbase : vbase;
                cp16(stb + (uint32_t)buf * (uint32_t)ATSZ + (uint32_t)row * APITCH + (uint32_t)ch * 16u,
                     src + (size_t)krow * (DM * 2) + ch * 16);
            }
        }
        asm volatile("cp.async.commit_group;" ::: "memory");
        if (tid < 64) {
            int kr = k0 + tid; if (kr > HW_DIM - 1) kr = HW_DIM - 1;
            float2 v = *(const float2*)(fpos + (size_t)kr * 2);
            *(float2*)(sm + AKPOS + st * 512 + tid * 8) = v;
        }
    };

    load_tile(0, 0);
    load_tile(1, 1);

    float m_0 = -1e30f, m_1 = -1e30f, l_0 = 0.f, l_1 = 0.f;
    float oacc[18][4];
    #pragma unroll
    for (int a = 0; a < 18; a++)
        #pragma unroll
        for (int q = 0; q < 4; q++) oacc[a][q] = 0.f;

    const int NT = (HW_DIM + 63) / 64;   // 12
    for (int kt = 0; kt < NT; kt++) {
        const int st = kt & 1;
        const int k0 = kt * 64;
        const int cnt = min(64, HW_DIM - k0);
        if (kt < NT - 1) asm volatile("cp.async.wait_group 1;" ::: "memory");
        else             asm volatile("cp.async.wait_group 0;" ::: "memory");
        __syncthreads();

        uint32_t stb = sb + (uint32_t)st * (uint32_t)ASTG;
        uint32_t lrow = (uint32_t)(lane & 15) * APITCH + (uint32_t)(lane >> 4) * 16u;
        uint32_t khb = stb + lrow;
        uint32_t klb = khb + ATSZ;
        uint32_t vhb = stb + 2u * ATSZ + lrow;

        float sacc[8][4];
        #pragma unroll
        for (int a = 0; a < 8; a++)
            #pragma unroll
            for (int q = 0; q < 4; q++) sacc[a][q] = 0.f;

        #pragma unroll
        for (int kc = 0; kc < 9; kc++) {
            uint32_t bh[4][4], bl[4][4];
            #pragma unroll
            for (int g = 0; g < 4; g++) {
                ldm4(khb + g * (16 * APITCH) + kc * 32, bh[g]);
                ldm4(klb + g * (16 * APITCH) + kc * 32, bl[g]);
            }
            #pragma unroll
            for (int g = 0; g < 4; g++) {
                mma_f16(sacc[2*g],   qf[kc], bh[g][0], bh[g][2]);
                mma_f16(sacc[2*g],   qf[kc], bl[g][0], bl[g][2]);
                mma_f16(sacc[2*g+1], qf[kc], bh[g][1], bh[g][3]);
                mma_f16(sacc[2*g+1], qf[kc], bl[g][1], bl[g][3]);
            }
        }

        const float2* kp = (const float2*)(sm + AKPOS + st * 512);
        float mn0 = m_0, mn1 = m_1;
        #pragma unroll
        for (int a = 0; a < 8; a++) {
            int c0 = a * 8 + tig * 2;
            float2 ka = kp[c0];
            float2 kb = kp[c0 + 1];
            float dxa0 = qp0.x - ka.x, dya0 = qp0.y - ka.y;
            float dxb0 = qp0.x - kb.x, dyb0 = qp0.y - kb.y;
            float dxa1 = qp1.x - ka.x, dya1 = qp1.y - ka.y;
            float dxb1 = qp1.x - kb.x, dyb1 = qp1.y - kb.y;
            bool va = (c0 < cnt), vb = (c0 + 1 < cnt);
            sacc[a][0] = va ? sacc[a][0] * (1.f/12.f) - (dxa0*dxa0 + dya0*dya0) * 0.125f : -1e30f;
            sacc[a][1] = vb ? sacc[a][1] * (1.f/12.f) - (dxb0*dxb0 + dyb0*dyb0) * 0.125f : -1e30f;
            sacc[a][2] = va ? sacc[a][2] * (1.f/12.f) - (dxa1*dxa1 + dya1*dya1) * 0.125f : -1e30f;
            sacc[a][3] = vb ? sacc[a][3] * (1.f/12.f) - (dxb1*dxb1 + dyb1*dyb1) * 0.125f : -1e30f;
            mn0 = fmaxf(mn0, fmaxf(sacc[a][0], sacc[a][1]));
            mn1 = fmaxf(mn1, fmaxf(sacc[a][2], sacc[a][3]));
        }
        mn0 = fmaxf(mn0, __shfl_xor_sync(0xffffffffu, mn0, 1));
        mn0 = fmaxf(mn0, __shfl_xor_sync(0xffffffffu, mn0, 2));
        mn1 = fmaxf(mn1, __shfl_xor_sync(0xffffffffu, mn1, 1));
        mn1 = fmaxf(mn1, __shfl_xor_sync(0xffffffffu, mn1, 2));
        float corr0 = __expf(m_0 - mn0);
        float corr1 = __expf(m_1 - mn1);
        m_0 = mn0; m_1 = mn1;
        l_0 *= corr0; l_1 *= corr1;
        #pragma unroll
        for (int a = 0; a < 18; a++) {
            oacc[a][0] *= corr0; oacc[a][1] *= corr0;
            oacc[a][2] *= corr1; oacc[a][3] *= corr1;
        }
        #pragma unroll
        for (int a = 0; a < 8; a++) {
            float p0 = __expf(sacc[a][0] - m_0);
            float p1 = __expf(sacc[a][1] - m_0);
            float p2 = __expf(sacc[a][2] - m_1);
            float p3 = __expf(sacc[a][3] - m_1);
            l_0 += p0 + p1; l_1 += p2 + p3;
            sacc[a][0] = p0; sacc[a][1] = p1; sacc[a][2] = p2; sacc[a][3] = p3;
        }

        #pragma unroll
        for (int kc4 = 0; kc4 < 4; kc4++) {
            uint32_t pa[4];
            pa[0] = pack_h2(sacc[2*kc4][0],   sacc[2*kc4][1]);
            pa[1] = pack_h2(sacc[2*kc4][2],   sacc[2*kc4][3]);
            pa[2] = pack_h2(sacc[2*kc4+1][0], sacc[2*kc4+1][1]);
            pa[3] = pack_h2(sacc[2*kc4+1][2], sacc[2*kc4+1][3]);
            #pragma unroll
            for (int dp = 0; dp < 9; dp++) {
                uint32_t vf[4];
                ldm4t(vhb + kc4 * (16 * APITCH) + dp * 32, vf);
                mma_f16(oacc[2*dp],   pa, vf[0], vf[1]);
                mma_f16(oacc[2*dp+1], pa, vf[2], vf[3]);
            }
        }

        __syncthreads();
        if (kt + 2 < NT) load_tile(st, kt + 2);
    }

    // ---- epilogue: write fp16 hi/lo directly (feeds the out-proj GEMM)
    l_0 += __shfl_xor_sync(0xffffffffu, l_0, 1);
    l_0 += __shfl_xor_sync(0xffffffffu, l_0, 2);
    l_1 += __shfl_xor_sync(0xffffffffu, l_1, 1);
    l_1 += __shfl_xor_sync(0xffffffffu, l_1, 2);
    float inv0 = 1.f / l_0, inv1 = 1.f / l_1;

    size_t row0 = (size_t)t * M_TRK + m0 + w * 16 + gid;
    #pragma unroll
    for (int a = 0; a < 18; a++) {
        int col = h * DH + a * 8 + tig * 2;
        {
            float v0 = oacc[a][0] * inv0, v1 = oacc[a][1] * inv0;
            __half h0 = __float2half_rn(v0), h1 = __float2half_rn(v1);
            __half2 hp; hp.x = h0; hp.y = h1;
            *(__half2*)(Sh + row0 * DM + col) = hp;
            *(__half2*)(Sl + row0 * DM + col) =
                __floats2half2_rn(v0 - __half2float(h0), v1 - __half2float(h1));
        }
        {
            float v0 = oacc[a][2] * inv1, v1 = oacc[a][3] * inv1;
            __half h0 = __float2half_rn(v0), h1 = __float2half_rn(v1);
            __half2 hp; hp.x = h0; hp.y = h1;
            *(__half2*)(Sh + (row0 + 8) * DM + col) = hp;
            *(__half2*)(Sl + (row0 + 8) * DM + col) =
                __floats2half2_rn(v0 - __half2float(h0), v1 - __half2float(h1));
        }
    }
}

// ---------------- launch ----------------
extern "C" void kernel_launch(void* const* d_in, const int* in_sizes, int n_in,
                              void* d_out, int out_size)
{
    const float* features    = (const float*)d_in[0];
    const float* tracks      = (const float*)d_in[1];
    const float* track_toks  = (const float*)d_in[2];
    const float* fpos        = (const float*)d_in[3];
    const float* W_q         = (const float*)d_in[4];
    const float* W_k         = (const float*)d_in[5];
    const float* q_norm_w    = (const float*)d_in[6];
    const float* k_norm_w    = (const float*)d_in[7];
    const float* out_proj_w  = (const float*)d_in[8];
    float* out = (float*)d_out;

    float *gQ, *gK;
    __half *gTTh, *gTTl, *gFh, *gFl, *gWh, *gQh, *gKh, *gKl, *gSh, *gSl;
    cudaGetSymbolAddress((void**)&gQ, g_Q);
    cudaGetSymbolAddress((void**)&gK, g_K);
    cudaGetSymbolAddress((void**)&gTTh, g_TTh);
    cudaGetSymbolAddress((void**)&gTTl, g_TTl);
    cudaGetSymbolAddress((void**)&gFh, g_Fh);
    cudaGetSymbolAddress((void**)&gFl, g_Fl);
    cudaGetSymbolAddress((void**)&gWh, g_Wh);
    cudaGetSymbolAddress((void**)&gQh, g_Qh);
    cudaGetSymbolAddress((void**)&gKh, g_Kh);
    cudaGetSymbolAddress((void**)&gKl, g_Kl);
    cudaGetSymbolAddress((void**)&gSh, g_Sh);
    cudaGetSymbolAddress((void**)&gSl, g_Sl);

    cudaFuncSetAttribute(gemm_mma_f16x2, cudaFuncAttributeMaxDynamicSharedMemorySize,
                         GEMM_SMEM);
    cudaFuncSetAttribute(attn_mma_kernel, cudaFuncAttributeMaxDynamicSharedMemorySize,
                         ATTN_SMEM);

    dim3 wtg(DM / 32, DM / 32);

    // ---- splits for Q and K GEMMs ----
    split_act_f16<<<4096, 256>>>(track_toks, gTTh, gTTl, (long)MQ * DM / 4);
    split_act_f16<<<4096, 256>>>(features, gFh, gFl, (long)MK * DM / 4);

    // ---- Q = track_tokens @ W_q ----
    wt_f16_kernel<<<wtg, 256>>>(W_q, gWh);
    {
        dim3 g(DM / 128, (MQ + 127) / 128);
        gemm_mma_f16x2<<<g, 256, GEMM_SMEM>>>(gTTh, gTTl, gWh, gQ, MQ);
    }

    // ---- K = features @ W_k ----
    wt_f16_kernel<<<wtg, 256>>>(W_k, gWh);
    {
        dim3 g(DM / 128, (MK + 127) / 128);
        gemm_mma_f16x2<<<g, 256, GEMM_SMEM>>>(gFh, gFl, gWh, gK, MK);
    }

    // ---- LN(Q)->fp16, RoPE+LN(K)->fp16 hi/lo ----
    ln_f16_kernel<<<MQ, 256>>>(gQ, q_norm_w, gQh);
    rope_ln_f16_kernel<<<MK, 256>>>(gK, fpos, k_norm_w, gKh, gKl);

    // ---- fused tensor-core attention (V = features hi fp16) ----
    {
        dim3 g(M_TRK / 128, NH, T_DIM);
        attn_mma_kernel<<<g, 256, ATTN_SMEM>>>(gQh, gKh, gKl, gFh, tracks, fpos, gSh, gSl);
    }

    // ---- out = sampled @ out_proj_w ----
    wt_f16_kernel<<<wtg, 256>>>(out_proj_w, gWh);
    {
        dim3 g(DM / 128, (MQ + 127) / 128);
        gemm_mma_f16x2<<<g, 256, GEMM_SMEM>>>(gSh, gSl, gWh, out, MQ);
    }
}

// round 7
// speedup vs baseline: 6.1068x; 1.3901x over previous
#include <cuda_runtime.h>
#include <cuda_fp16.h>
#include <math.h>
#include <stdint.h>

// ---------------- problem constants ----------------
#define T_DIM   64
#define HW_DIM  729
#define M_TRK   512
#define DM      1152
#define NH      8
#define DH      144
#define MQ      (T_DIM * M_TRK)    // 32768
#define MK      (T_DIM * HW_DIM)   // 46656

// ---------------- device scratch ----------------
__device__ float g_Q[(size_t)MQ * DM];     // Q gemm out (fp32)
__device__ float g_K[(size_t)MK * DM];     // K gemm out (fp32)
__device__ __half g_TTh[(size_t)MQ * DM];  // track_tokens fp16
__device__ __half g_Fh[(size_t)MK * DM];   // features fp16 (GEMM A and attention V)
__device__ __half g_Wh[(size_t)DM * DM];   // weight fp16, transposed [N,K]
__device__ __half g_Qh[(size_t)MQ * DM];   // LN'd Q fp16
__device__ __half g_Kh[(size_t)MK * DM];   // LN'd+RoPE'd K hi
__device__ __half g_Kl[(size_t)MK * DM];   // K lo
__device__ __half g_Sh[(size_t)MQ * DM];   // attention out fp16

__device__ __forceinline__ uint32_t smem_u32(const void* p) {
    uint32_t a;
    asm("{ .reg .u64 t; cvta.to.shared.u64 t, %1; cvt.u32.u64 %0, t; }" : "=r"(a) : "l"(p));
    return a;
}
__device__ __forceinline__ void cp16(uint32_t dst, const void* src) {
    asm volatile("cp.async.cg.shared.global [%0], [%1], 16;" :: "r"(dst), "l"(src));
}
__device__ __forceinline__ void ldm4(uint32_t addr, uint32_t* r) {
    asm volatile("ldmatrix.sync.aligned.m8n8.x4.shared.b16 {%0,%1,%2,%3}, [%4];"
                 : "=r"(r[0]), "=r"(r[1]), "=r"(r[2]), "=r"(r[3])
                 : "r"(addr) : "memory");
}
__device__ __forceinline__ void ldm4t(uint32_t addr, uint32_t* r) {
    asm volatile("ldmatrix.sync.aligned.m8n8.x4.trans.shared.b16 {%0,%1,%2,%3}, [%4];"
                 : "=r"(r[0]), "=r"(r[1]), "=r"(r[2]), "=r"(r[3])
                 : "r"(addr) : "memory");
}
__device__ __forceinline__ void mma_f16(float* d, const uint32_t* a,
                                        uint32_t b0, uint32_t b1) {
    asm volatile(
        "mma.sync.aligned.m16n8k16.row.col.f32.f16.f16.f32 "
        "{%0,%1,%2,%3}, {%4,%5,%6,%7}, {%8,%9}, {%0,%1,%2,%3};"
        : "+f"(d[0]), "+f"(d[1]), "+f"(d[2]), "+f"(d[3])
        : "r"(a[0]), "r"(a[1]), "r"(a[2]), "r"(a[3]), "r"(b0), "r"(b1));
}
__device__ __forceinline__ uint32_t pack_h2(float a, float b) {
    __half2 h = __floats2half2_rn(a, b);
    return *(uint32_t*)&h;
}

// ================= fp32 -> fp16 convert ======================================
__global__ __launch_bounds__(256)
void f32_to_f16_kernel(const float* __restrict__ X, __half* __restrict__ O, long n4)
{
    long i = (long)blockIdx.x * blockDim.x + threadIdx.x;
    long stride = (long)gridDim.x * blockDim.x;
    for (; i < n4; i += stride) {
        float4 v = ((const float4*)X)[i];
        ((__half2*)O)[2*i]   = __floats2half2_rn(v.x, v.y);
        ((__half2*)O)[2*i+1] = __floats2half2_rn(v.z, v.w);
    }
}

// ============ weight fp16 + transpose: W[K,N] fp32 -> Ht [N,K] fp16 ==========
__global__ __launch_bounds__(256)
void wt_f16_kernel(const float* __restrict__ W, __half* __restrict__ Ht)
{
    __shared__ float tile[32][33];
    int tx = threadIdx.x & 31, ty = threadIdx.x >> 5;
    int nb = blockIdx.x * 32, kb = blockIdx.y * 32;
    #pragma unroll
    for (int r = ty; r < 32; r += 8)
        tile[r][tx] = W[(size_t)(kb + r) * DM + nb + tx];
    __syncthreads();
    #pragma unroll
    for (int r = ty; r < 32; r += 8)
        Ht[(size_t)(nb + r) * DM + kb + tx] = __float2half_rn(tile[tx][r]);
}

// =================== mma.sync fp16 single-pass GEMM ==========================
// C[M,1152] = A @ B; A fp16 row-major [M,K], BhT fp16 [N,K].
// BM=128, BN=128, BK=32; 8 warps (2M x 4N); 4-stage cp.async pipeline.
#define TPITCH 80
#define TBYTES (128 * TPITCH)          // 10240
#define STAGEB (2 * TBYTES)            // 20480 (A, B)
#define NSTG   4
#define GEMM_SMEM (NSTG * STAGEB)      // 81920
#define KC 36

__global__ __launch_bounds__(256)
void gemm_mma_f16(const __half* __restrict__ A, const __half* __restrict__ BhT,
                  float* __restrict__ C, int M)
{
    extern __shared__ char dsm[];
    const int tid  = threadIdx.x;
    const int lane = tid & 31;
    const int wid  = tid >> 5;
    const int wm   = wid & 1;
    const int wn   = wid >> 1;
    const int n0   = blockIdx.x * 128;
    const int m0   = blockIdx.y * 128;

    uint32_t sb = smem_u32(dsm);
    const char* srcbase[2] = { (const char*)A, (const char*)BhT };

    float acc[4][4][4];
    #pragma unroll
    for (int i = 0; i < 4; i++)
        #pragma unroll
        for (int j = 0; j < 4; j++)
            #pragma unroll
            for (int q = 0; q < 4; q++) acc[i][j][q] = 0.f;

    auto load_stage = [&](int stage, int chunk) {
        uint32_t stb = sb + (uint32_t)stage * (uint32_t)STAGEB;
        #pragma unroll
        for (int it = 0; it < 4; it++) {
            int flat = tid + it * 256;          // 0..1023
            int t2 = flat >> 9;                 // 0..1
            int r  = (flat >> 2) & 127;
            int c4 = flat & 3;
            int grow;
            if (t2 == 0) { grow = m0 + r; if (grow > M - 1) grow = M - 1; }
            else         { grow = n0 + r; }
            const char* src = srcbase[t2] + (size_t)grow * (DM * 2)
                              + (size_t)chunk * 64 + c4 * 16;
            uint32_t dst = stb + (uint32_t)t2 * (uint32_t)TBYTES
                           + (uint32_t)r * TPITCH + (uint32_t)c4 * 16u;
            cp16(dst, src);
        }
        asm volatile("cp.async.commit_group;" ::: "memory");
    };

    load_stage(0, 0);
    load_stage(1, 1);
    load_stage(2, 2);
    load_stage(3, 3);

    const uint32_t aoffH = (uint32_t)(wm * 64 + (lane & 15)) * TPITCH + (uint32_t)(lane >> 4) * 16u;
    const uint32_t boffH = (uint32_t)(wn * 32 + (lane & 15)) * TPITCH + (uint32_t)(lane >> 4) * 16u;

    for (int c = 0; c < KC; c++) {
        const int s = c % NSTG;
        if (c < KC - NSTG) asm volatile("cp.async.wait_group 3;" ::: "memory");
        else               asm volatile("cp.async.wait_group 0;" ::: "memory");
        __syncthreads();

        uint32_t stb = sb + (uint32_t)s * (uint32_t)STAGEB;
        uint32_t aH = stb + aoffH;
        uint32_t bH = stb + TBYTES + boffH;

        #pragma unroll
        for (int s16 = 0; s16 < 2; s16++) {
            uint32_t ah[4][4], bh[2][4];
            #pragma unroll
            for (int a = 0; a < 4; a++)
                ldm4(aH + a * (16 * TPITCH) + s16 * 32, ah[a]);
            #pragma unroll
            for (int b = 0; b < 2; b++)
                ldm4(bH + b * (16 * TPITCH) + s16 * 32, bh[b]);
            #pragma unroll
            for (int am = 0; am < 4; am++) {
                #pragma unroll
                for (int bt = 0; bt < 2; bt++) {
                    mma_f16(acc[am][2*bt],   ah[am], bh[bt][0], bh[bt][2]);
                    mma_f16(acc[am][2*bt+1], ah[am], bh[bt][1], bh[bt][3]);
                }
            }
        }
        __syncthreads();
        if (c + NSTG < KC) load_stage(s, c + NSTG);
    }

    #pragma unroll
    for (int am = 0; am < 4; am++) {
        int m = m0 + wm * 64 + am * 16 + (lane >> 2);
        #pragma unroll
        for (int bt = 0; bt < 4; bt++) {
            int n = n0 + wn * 32 + bt * 8 + (lane & 3) * 2;
            if (m < M)
                *(float2*)(C + (size_t)m * DM + n) = make_float2(acc[am][bt][0], acc[am][bt][1]);
            if (m + 8 < M)
                *(float2*)(C + (size_t)(m + 8) * DM + n) = make_float2(acc[am][bt][2], acc[am][bt][3]);
        }
    }
}

// ---------------- LayerNorm helpers ------------------------------------------
__device__ __forceinline__ void block_ln_stats(const float* x, float& mu, float& inv)
{
    __shared__ float red[18];
    float s = 0.f, ss = 0.f;
    for (int i = threadIdx.x; i < DM; i += 256) {
        float v = x[i];
        s += v; ss += v * v;
    }
    #pragma unroll
    for (int o = 16; o; o >>= 1) {
        s  += __shfl_down_sync(0xffffffffu, s, o);
        ss += __shfl_down_sync(0xffffffffu, ss, o);
    }
    int wid = threadIdx.x >> 5, lane = threadIdx.x & 31;
    if (lane == 0) { red[wid] = s; red[8 + wid] = ss; }
    __syncthreads();
    if (threadIdx.x == 0) {
        float S = 0.f, SS = 0.f;
        #pragma unroll
        for (int i = 0; i < 8; i++) { S += red[i]; SS += red[8 + i]; }
        red[16] = S; red[17] = SS;
    }
    __syncthreads();
    mu  = red[16] * (1.f / DM);
    float var = red[17] * (1.f / DM) - mu * mu;
    inv = rsqrtf(var + 1e-6f);
}

// LN(Q) -> fp16
__global__ __launch_bounds__(256)
void ln_f16_kernel(const float* __restrict__ X, const float* __restrict__ w,
                   __half* __restrict__ O)
{
    const float* x = X + (size_t)blockIdx.x * DM;
    __half* o = O + (size_t)blockIdx.x * DM;
    float mu, inv;
    block_ln_stats(x, mu, inv);
    for (int i = threadIdx.x; i < DM; i += 256)
        o[i] = __float2half_rn((x[i] - mu) * inv * w[i]);
}

// RoPE + LN(K) -> fp16 hi/lo
__global__ __launch_bounds__(256)
void rope_ln_f16_kernel(float* __restrict__ X, const float* __restrict__ fpos,
                        const float* __restrict__ w,
                        __half* __restrict__ Oh, __half* __restrict__ Ol)
{
    const int row = blockIdx.x;
    const int n = row % HW_DIM;
    float* x = X + (size_t)row * DM;
    const float px = fpos[2 * n];
    const float py = fpos[2 * n + 1];
    const float TS = -9.210340371976184f / 288.0f;
    for (int p = threadIdx.x; p < 576; p += 256) {
        int q = (p < 288) ? p : (p - 288);
        float theta = expf((float)q * TS);
        float ang = ((p < 288) ? px : py) * theta;
        float c, s;
        sincosf(ang, &s, &c);
        int base = (p < 288) ? (2 * q) : (576 + 2 * q);
        float a = x[base], b = x[base + 1];
        x[base]     = a * c - b * s;
        x[base + 1] = a * s + b * c;
    }
    __syncthreads();
    float mu, inv;
    block_ln_stats(x, mu, inv);
    __half* oh = Oh + (size_t)row * DM;
    __half* ol = Ol + (size_t)row * DM;
    for (int i = threadIdx.x; i < DM; i += 256) {
        float y = (x[i] - mu) * inv * w[i];
        __half h = __float2half_rn(y);
        oh[i] = h;
        ol[i] = __float2half_rn(y - __half2float(h));
    }
}

// ---------------- tensor-core fused attention --------------------------------
#define APITCH 304
#define ATSZ   (64 * APITCH)
#define ASTG   (3 * ATSZ)
#define AKPOS  (2 * ASTG)
#define ATTN_SMEM (AKPOS + 2 * 512)

__global__ __launch_bounds__(256, 1)
void attn_mma_kernel(const __half* __restrict__ Qh, const __half* __restrict__ Kh,
                     const __half* __restrict__ Kl, const __half* __restrict__ Vh,
                     const float* __restrict__ tracks, const float* __restrict__ fpos,
                     __half* __restrict__ Sh)
{
    extern __shared__ char sm[];
    uint32_t sb = smem_u32(sm);
    const int tid  = threadIdx.x;
    const int lane = tid & 31;
    const int w    = tid >> 5;
    const int gid  = lane >> 2;
    const int tig  = lane & 3;
    const int m0   = blockIdx.x * 128;
    const int h    = blockIdx.y;
    const int t    = blockIdx.z;

    const char* qbase  = (const char*)(Qh + ((size_t)t * M_TRK + m0) * DM + h * DH);
    const char* khbase = (const char*)(Kh + (size_t)t * HW_DIM * DM + h * DH);
    const char* klbase = (const char*)(Kl + (size_t)t * HW_DIM * DM + h * DH);
    const char* vbase  = (const char*)(Vh + (size_t)t * HW_DIM * DM + h * DH);

    float2 qp0 = *(const float2*)(tracks + ((size_t)t * M_TRK + m0 + w * 16 + gid) * 2);
    float2 qp1 = *(const float2*)(tracks + ((size_t)t * M_TRK + m0 + w * 16 + gid + 8) * 2);

    #pragma unroll
    for (int i = 0; i < 9; i++) {
        int c = tid + i * 256;
        int row = c / 18, ch = c % 18;
        cp16(sb + row * APITCH + ch * 16, qbase + (size_t)row * (DM * 2) + ch * 16);
    }
    asm volatile("cp.async.commit_group;" ::: "memory");
    asm volatile("cp.async.wait_group 0;" ::: "memory");
    __syncthreads();

    uint32_t qf[9][4];
    {
        uint32_t qa = sb + (uint32_t)(w * 16 + (lane & 15)) * APITCH + (uint32_t)(lane >> 4) * 16u;
        #pragma unroll
        for (int kc = 0; kc < 9; kc++) ldm4(qa + kc * 32, qf[kc]);
    }
    __syncthreads();

    auto load_tile = [&](int st, int kt) {
        int k0 = kt * 64;
        uint32_t stb = sb + (uint32_t)st * (uint32_t)ASTG;
        #pragma unroll
        for (int i = 0; i < 14; i++) {
            int c = tid + i * 256;
            if (c < 3456) {
                int buf = c / 1152, rem = c % 1152;
                int row = rem / 18, ch = rem % 18;
                int krow = k0 + row; if (krow > HW_DIM - 1) krow = HW_DIM - 1;
                const char* src = (buf == 0) ? khbase : (buf == 1) ? klbase : vbase;
                cp16(stb + (uint32_t)buf * (uint32_t)ATSZ + (uint32_t)row * APITCH + (uint32_t)ch * 16u,
                     src + (size_t)krow * (DM * 2) + ch * 16);
            }
        }
        asm volatile("cp.async.commit_group;" ::: "memory");
        if (tid < 64) {
            int kr = k0 + tid; if (kr > HW_DIM - 1) kr = HW_DIM - 1;
            float2 v = *(const float2*)(fpos + (size_t)kr * 2);
            *(float2*)(sm + AKPOS + st * 512 + tid * 8) = v;
        }
    };

    load_tile(0, 0);
    load_tile(1, 1);

    float m_0 = -1e30f, m_1 = -1e30f, l_0 = 0.f, l_1 = 0.f;
    float oacc[18][4];
    #pragma unroll
    for (int a = 0; a < 18; a++)
        #pragma unroll
        for (int q = 0; q < 4; q++) oacc[a][q] = 0.f;

    const int NT = (HW_DIM + 63) / 64;   // 12
    for (int kt = 0; kt < NT; kt++) {
        const int st = kt & 1;
        const int k0 = kt * 64;
        const int cnt = min(64, HW_DIM - k0);
        if (kt < NT - 1) asm volatile("cp.async.wait_group 1;" ::: "memory");
        else             asm volatile("cp.async.wait_group 0;" ::: "memory");
        __syncthreads();

        uint32_t stb = sb + (uint32_t)st * (uint32_t)ASTG;
        uint32_t lrow = (uint32_t)(lane & 15) * APITCH + (uint32_t)(lane >> 4) * 16u;
        uint32_t khb = stb + lrow;
        uint32_t klb = khb + ATSZ;
        uint32_t vhb = stb + 2u * ATSZ + lrow;

        float sacc[8][4];
        #pragma unroll
        for (int a = 0; a < 8; a++)
            #pragma unroll
            for (int q = 0; q < 4; q++) sacc[a][q] = 0.f;

        #pragma unroll
        for (int kc = 0; kc < 9; kc++) {
            uint32_t bh[4][4], bl[4][4];
            #pragma unroll
            for (int g = 0; g < 4; g++) {
                ldm4(khb + g * (16 * APITCH) + kc * 32, bh[g]);
                ldm4(klb + g * (16 * APITCH) + kc * 32, bl[g]);
            }
            #pragma unroll
            for (int g = 0; g < 4; g++) {
                mma_f16(sacc[2*g],   qf[kc], bh[g][0], bh[g][2]);
                mma_f16(sacc[2*g],   qf[kc], bl[g][0], bl[g][2]);
                mma_f16(sacc[2*g+1], qf[kc], bh[g][1], bh[g][3]);
                mma_f16(sacc[2*g+1], qf[kc], bl[g][1], bl[g][3]);
            }
        }

        const float2* kp = (const float2*)(sm + AKPOS + st * 512);
        float mn0 = m_0, mn1 = m_1;
        #pragma unroll
        for (int a = 0; a < 8; a++) {
            int c0 = a * 8 + tig * 2;
            float2 ka = kp[c0];
            float2 kb = kp[c0 + 1];
            float dxa0 = qp0.x - ka.x, dya0 = qp0.y - ka.y;
            float dxb0 = qp0.x - kb.x, dyb0 = qp0.y - kb.y;
            float dxa1 = qp1.x - ka.x, dya1 = qp1.y - ka.y;
            float dxb1 = qp1.x - kb.x, dyb1 = qp1.y - kb.y;
            bool va = (c0 < cnt), vb = (c0 + 1 < cnt);
            sacc[a][0] = va ? sacc[a][0] * (1.f/12.f) - (dxa0*dxa0 + dya0*dya0) * 0.125f : -1e30f;
            sacc[a][1] = vb ? sacc[a][1] * (1.f/12.f) - (dxb0*dxb0 + dyb0*dyb0) * 0.125f : -1e30f;
            sacc[a][2] = va ? sacc[a][2] * (1.f/12.f) - (dxa1*dxa1 + dya1*dya1) * 0.125f : -1e30f;
            sacc[a][3] = vb ? sacc[a][3] * (1.f/12.f) - (dxb1*dxb1 + dyb1*dyb1) * 0.125f : -1e30f;
            mn0 = fmaxf(mn0, fmaxf(sacc[a][0], sacc[a][1]));
            mn1 = fmaxf(mn1, fmaxf(sacc[a][2], sacc[a][3]));
        }
        mn0 = fmaxf(mn0, __shfl_xor_sync(0xffffffffu, mn0, 1));
        mn0 = fmaxf(mn0, __shfl_xor_sync(0xffffffffu, mn0, 2));
        mn1 = fmaxf(mn1, __shfl_xor_sync(0xffffffffu, mn1, 1));
        mn1 = fmaxf(mn1, __shfl_xor_sync(0xffffffffu, mn1, 2));
        float corr0 = __expf(m_0 - mn0);
        float corr1 = __expf(m_1 - mn1);
        m_0 = mn0; m_1 = mn1;
        l_0 *= corr0; l_1 *= corr1;
        #pragma unroll
        for (int a = 0; a < 18; a++) {
            oacc[a][0] *= corr0; oacc[a][1] *= corr0;
            oacc[a][2] *= corr1; oacc[a][3] *= corr1;
        }
        #pragma unroll
        for (int a = 0; a < 8; a++) {
            float p0 = __expf(sacc[a][0] - m_0);
            float p1 = __expf(sacc[a][1] - m_0);
            float p2 = __expf(sacc[a][2] - m_1);
            float p3 = __expf(sacc[a][3] - m_1);
            l_0 += p0 + p1; l_1 += p2 + p3;
            sacc[a][0] = p0; sacc[a][1] = p1; sacc[a][2] = p2; sacc[a][3] = p3;
        }

        #pragma unroll
        for (int kc4 = 0; kc4 < 4; kc4++) {
            uint32_t pa[4];
            pa[0] = pack_h2(sacc[2*kc4][0],   sacc[2*kc4][1]);
            pa[1] = pack_h2(sacc[2*kc4][2],   sacc[2*kc4][3]);
            pa[2] = pack_h2(sacc[2*kc4+1][0], sacc[2*kc4+1][1]);
            pa[3] = pack_h2(sacc[2*kc4+1][2], sacc[2*kc4+1][3]);
            #pragma unroll
            for (int dp = 0; dp < 9; dp++) {
                uint32_t vf[4];
                ldm4t(vhb + kc4 * (16 * APITCH) + dp * 32, vf);
                mma_f16(oacc[2*dp],   pa, vf[0], vf[1]);
                mma_f16(oacc[2*dp+1], pa, vf[2], vf[3]);
            }
        }

        __syncthreads();
        if (kt + 2 < NT) load_tile(st, kt + 2);
    }

    l_0 += __shfl_xor_sync(0xffffffffu, l_0, 1);
    l_0 += __shfl_xor_sync(0xffffffffu, l_0, 2);
    l_1 += __shfl_xor_sync(0xffffffffu, l_1, 1);
    l_1 += __shfl_xor_sync(0xffffffffu, l_1, 2);
    float inv0 = 1.f / l_0, inv1 = 1.f / l_1;

    size_t row0 = (size_t)t * M_TRK + m0 + w * 16 + gid;
    #pragma unroll
    for (int a = 0; a < 18; a++) {
        int col = h * DH + a * 8 + tig * 2;
        *(__half2*)(Sh + row0 * DM + col) =
            __floats2half2_rn(oacc[a][0] * inv0, oacc[a][1] * inv0);
        *(__half2*)(Sh + (row0 + 8) * DM + col) =
            __floats2half2_rn(oacc[a][2] * inv1, oacc[a][3] * inv1);
    }
}

// ---------------- launch ----------------
extern "C" void kernel_launch(void* const* d_in, const int* in_sizes, int n_in,
                              void* d_out, int out_size)
{
    const float* features    = (const float*)d_in[0];
    const float* tracks      = (const float*)d_in[1];
    const float* track_toks  = (const float*)d_in[2];
    const float* fpos        = (const float*)d_in[3];
    const float* W_q         = (const float*)d_in[4];
    const float* W_k         = (const float*)d_in[5];
    const float* q_norm_w    = (const float*)d_in[6];
    const float* k_norm_w    = (const float*)d_in[7];
    const float* out_proj_w  = (const float*)d_in[8];
    float* out = (float*)d_out;

    float *gQ, *gK;
    __half *gTTh, *gFh, *gWh, *gQh, *gKh, *gKl, *gSh;
    cudaGetSymbolAddress((void**)&gQ, g_Q);
    cudaGetSymbolAddress((void**)&gK, g_K);
    cudaGetSymbolAddress((void**)&gTTh, g_TTh);
    cudaGetSymbolAddress((void**)&gFh, g_Fh);
    cudaGetSymbolAddress((void**)&gWh, g_Wh);
    cudaGetSymbolAddress((void**)&gQh, g_Qh);
    cudaGetSymbolAddress((void**)&gKh, g_Kh);
    cudaGetSymbolAddress((void**)&gKl, g_Kl);
    cudaGetSymbolAddress((void**)&gSh, g_Sh);

    cudaFuncSetAttribute(gemm_mma_f16, cudaFuncAttributeMaxDynamicSharedMemorySize,
                         GEMM_SMEM);
    cudaFuncSetAttribute(attn_mma_kernel, cudaFuncAttributeMaxDynamicSharedMemorySize,
                         ATTN_SMEM);

    dim3 wtg(DM / 32, DM / 32);

    // ---- fp16 conversions for GEMM A operands ----
    f32_to_f16_kernel<<<4096, 256>>>(track_toks, gTTh, (long)MQ * DM / 4);
    f32_to_f16_kernel<<<4096, 256>>>(features, gFh, (long)MK * DM / 4);

    // ---- Q = track_tokens @ W_q ----
    wt_f16_kernel<<<wtg, 256>>>(W_q, gWh);
    {
        dim3 g(DM / 128, (MQ + 127) / 128);
        gemm_mma_f16<<<g, 256, GEMM_SMEM>>>(gTTh, gWh, gQ, MQ);
    }

    // ---- K = features @ W_k ----
    wt_f16_kernel<<<wtg, 256>>>(W_k, gWh);
    {
        dim3 g(DM / 128, (MK + 127) / 128);
        gemm_mma_f16<<<g, 256, GEMM_SMEM>>>(gFh, gWh, gK, MK);
    }

    // ---- LN(Q)->fp16, RoPE+LN(K)->fp16 hi/lo ----
    ln_f16_kernel<<<MQ, 256>>>(gQ, q_norm_w, gQh);
    rope_ln_f16_kernel<<<MK, 256>>>(gK, fpos, k_norm_w, gKh, gKl);

    // ---- fused tensor-core attention (V = features fp16) ----
    {
        dim3 g(M_TRK / 128, NH, T_DIM);
        attn_mma_kernel<<<g, 256, ATTN_SMEM>>>(gQh, gKh, gKl, gFh, tracks, fpos, gSh);
    }

    // ---- out = sampled @ out_proj_w ----
    wt_f16_kernel<<<wtg, 256>>>(out_proj_w, gWh);
    {
        dim3 g(DM / 128, (MQ + 127) / 128);
        gemm_mma_f16<<<g, 256, GEMM_SMEM>>>(gSh, gWh, out, MQ);
    }
}

// round 8
// speedup vs baseline: 6.4832x; 1.0616x over previous
#include <cuda_runtime.h>
#include <cuda_fp16.h>
#include <math.h>
#include <stdint.h>

// ---------------- problem constants ----------------
#define T_DIM   64
#define HW_DIM  729
#define M_TRK   512
#define DM      1152
#define NH      8
#define DH      144
#define MQ      (T_DIM * M_TRK)    // 32768
#define MK      (T_DIM * HW_DIM)   // 46656

// ---------------- device scratch ----------------
__device__ float g_Q[(size_t)MQ * DM];     // Q gemm out (fp32)
__device__ float g_K[(size_t)MK * DM];     // K gemm out (fp32)
__device__ __half g_TTh[(size_t)MQ * DM];  // track_tokens fp16
__device__ __half g_Fh[(size_t)MK * DM];   // features fp16 (GEMM A and attention V)
__device__ __half g_Wh[(size_t)DM * DM];   // weight fp16, transposed [N,K]
__device__ __half g_Qh[(size_t)MQ * DM];   // LN'd Q fp16
__device__ __half g_Kh[(size_t)MK * DM];   // LN'd+RoPE'd K hi
__device__ __half g_Kl[(size_t)MK * DM];   // K lo
__device__ __half g_Sh[(size_t)MQ * DM];   // attention out fp16

__device__ __forceinline__ uint32_t smem_u32(const void* p) {
    uint32_t a;
    asm("{ .reg .u64 t; cvta.to.shared.u64 t, %1; cvt.u32.u64 %0, t; }" : "=r"(a) : "l"(p));
    return a;
}
__device__ __forceinline__ void cp16(uint32_t dst, const void* src) {
    asm volatile("cp.async.cg.shared.global [%0], [%1], 16;" :: "r"(dst), "l"(src));
}
__device__ __forceinline__ void ldm4(uint32_t addr, uint32_t* r) {
    asm volatile("ldmatrix.sync.aligned.m8n8.x4.shared.b16 {%0,%1,%2,%3}, [%4];"
                 : "=r"(r[0]), "=r"(r[1]), "=r"(r[2]), "=r"(r[3])
                 : "r"(addr) : "memory");
}
__device__ __forceinline__ void ldm4t(uint32_t addr, uint32_t* r) {
    asm volatile("ldmatrix.sync.aligned.m8n8.x4.trans.shared.b16 {%0,%1,%2,%3}, [%4];"
                 : "=r"(r[0]), "=r"(r[1]), "=r"(r[2]), "=r"(r[3])
                 : "r"(addr) : "memory");
}
__device__ __forceinline__ void mma_f16(float* d, const uint32_t* a,
                                        uint32_t b0, uint32_t b1) {
    asm volatile(
        "mma.sync.aligned.m16n8k16.row.col.f32.f16.f16.f32 "
        "{%0,%1,%2,%3}, {%4,%5,%6,%7}, {%8,%9}, {%0,%1,%2,%3};"
        : "+f"(d[0]), "+f"(d[1]), "+f"(d[2]), "+f"(d[3])
        : "r"(a[0]), "r"(a[1]), "r"(a[2]), "r"(a[3]), "r"(b0), "r"(b1));
}
__device__ __forceinline__ uint32_t pack_h2(float a, float b) {
    __half2 h = __floats2half2_rn(a, b);
    return *(uint32_t*)&h;
}

// ================= fp32 -> fp16 convert ======================================
__global__ __launch_bounds__(256)
void f32_to_f16_kernel(const float* __restrict__ X, __half* __restrict__ O, long n4)
{
    long i = (long)blockIdx.x * blockDim.x + threadIdx.x;
    long stride = (long)gridDim.x * blockDim.x;
    for (; i < n4; i += stride) {
        float4 v = ((const float4*)X)[i];
        ((__half2*)O)[2*i]   = __floats2half2_rn(v.x, v.y);
        ((__half2*)O)[2*i+1] = __floats2half2_rn(v.z, v.w);
    }
}

// ============ weight fp16 + transpose: W[K,N] fp32 -> Ht [N,K] fp16 ==========
__global__ __launch_bounds__(256)
void wt_f16_kernel(const float* __restrict__ W, __half* __restrict__ Ht)
{
    __shared__ float tile[32][33];
    int tx = threadIdx.x & 31, ty = threadIdx.x >> 5;
    int nb = blockIdx.x * 32, kb = blockIdx.y * 32;
    #pragma unroll
    for (int r = ty; r < 32; r += 8)
        tile[r][tx] = W[(size_t)(kb + r) * DM + nb + tx];
    __syncthreads();
    #pragma unroll
    for (int r = ty; r < 32; r += 8)
        Ht[(size_t)(nb + r) * DM + kb + tx] = __float2half_rn(tile[tx][r]);
}

// =================== mma.sync fp16 GEMM, 64x64 warp tiles ====================
// C[M,1152] = A @ B; A fp16 row-major [M,K], BhT fp16 [N,K].
// BM=128, BN=128, BK=32; 4 warps (2M x 2N), warp tile 64x64.
// 4-stage cp.async pipeline, ONE __syncthreads per k-chunk.
#define TPITCH 80
#define TBYTES (128 * TPITCH)          // 10240
#define STAGEB (2 * TBYTES)            // 20480 (A, B)
#define NSTG   4
#define GEMM_SMEM (NSTG * STAGEB)      // 81920
#define KC 36

__global__ __launch_bounds__(128)
void gemm_mma_f16(const __half* __restrict__ A, const __half* __restrict__ BhT,
                  float* __restrict__ C, int M)
{
    extern __shared__ char dsm[];
    const int tid  = threadIdx.x;
    const int lane = tid & 31;
    const int wid  = tid >> 5;         // 0..3
    const int wm   = wid & 1;          // m offset 64*wm
    const int wn   = wid >> 1;         // n offset 64*wn
    const int n0   = blockIdx.x * 128;
    const int m0   = blockIdx.y * 128;

    uint32_t sb = smem_u32(dsm);
    const char* srcbase[2] = { (const char*)A, (const char*)BhT };

    float acc[4][8][4];
    #pragma unroll
    for (int i = 0; i < 4; i++)
        #pragma unroll
        for (int j = 0; j < 8; j++)
            #pragma unroll
            for (int q = 0; q < 4; q++) acc[i][j][q] = 0.f;

    auto load_stage = [&](int stage, int chunk) {
        uint32_t stb = sb + (uint32_t)stage * (uint32_t)STAGEB;
        #pragma unroll
        for (int it = 0; it < 8; it++) {
            int flat = tid + it * 128;          // 0..1023
            int t2 = flat >> 9;                 // 0..1
            int r  = (flat >> 2) & 127;
            int c4 = flat & 3;
            int grow;
            if (t2 == 0) { grow = m0 + r; if (grow > M - 1) grow = M - 1; }
            else         { grow = n0 + r; }
            const char* src = srcbase[t2] + (size_t)grow * (DM * 2)
                              + (size_t)chunk * 64 + c4 * 16;
            uint32_t dst = stb + (uint32_t)t2 * (uint32_t)TBYTES
                           + (uint32_t)r * TPITCH + (uint32_t)c4 * 16u;
            cp16(dst, src);
        }
        asm volatile("cp.async.commit_group;" ::: "memory");
    };

    // prologue: 3 stages in flight
    load_stage(0, 0);
    load_stage(1, 1);
    load_stage(2, 2);

    const uint32_t aoff = (uint32_t)(wm * 64 + (lane & 15)) * TPITCH + (uint32_t)(lane >> 4) * 16u;
    const uint32_t boff = (uint32_t)(wn * 64 + (lane & 15)) * TPITCH + (uint32_t)(lane >> 4) * 16u;

    for (int c = 0; c < KC; c++) {
        const int s = c & 3;
        // ensure chunk c's cp.async group has landed
        if (c < KC - 2)       asm volatile("cp.async.wait_group 2;" ::: "memory");
        else if (c == KC - 2) asm volatile("cp.async.wait_group 1;" ::: "memory");
        else                  asm volatile("cp.async.wait_group 0;" ::: "memory");
        __syncthreads();   // all warps done with chunk c-1; chunk c visible

        // refill the stage consumed at iteration c-1 with chunk c+3
        if (c + NSTG - 1 < KC) load_stage((c + 3) & 3, c + 3);

        uint32_t aH = sb + (uint32_t)s * (uint32_t)STAGEB + aoff;
        uint32_t bH = sb + (uint32_t)s * (uint32_t)STAGEB + TBYTES + boff;

        #pragma unroll
        for (int s16 = 0; s16 < 2; s16++) {
            uint32_t ah[4][4], bh[4][4];
            #pragma unroll
            for (int a = 0; a < 4; a++)
                ldm4(aH + a * (16 * TPITCH) + s16 * 32, ah[a]);
            #pragma unroll
            for (int b = 0; b < 4; b++)
                ldm4(bH + b * (16 * TPITCH) + s16 * 32, bh[b]);
            #pragma unroll
            for (int am = 0; am < 4; am++) {
                #pragma unroll
                for (int bt = 0; bt < 4; bt++) {
                    mma_f16(acc[am][2*bt],   ah[am], bh[bt][0], bh[bt][2]);
                    mma_f16(acc[am][2*bt+1], ah[am], bh[bt][1], bh[bt][3]);
                }
            }
        }
    }

    #pragma unroll
    for (int am = 0; am < 4; am++) {
        int m = m0 + wm * 64 + am * 16 + (lane >> 2);
        #pragma unroll
        for (int bt = 0; bt < 8; bt++) {
            int n = n0 + wn * 64 + bt * 8 + (lane & 3) * 2;
            if (m < M)
                *(float2*)(C + (size_t)m * DM + n) = make_float2(acc[am][bt][0], acc[am][bt][1]);
            if (m + 8 < M)
                *(float2*)(C + (size_t)(m + 8) * DM + n) = make_float2(acc[am][bt][2], acc[am][bt][3]);
        }
    }
}

// ---------------- LayerNorm helpers ------------------------------------------
__device__ __forceinline__ void block_ln_stats(const float* x, float& mu, float& inv)
{
    __shared__ float red[18];
    float s = 0.f, ss = 0.f;
    for (int i = threadIdx.x; i < DM; i += 256) {
        float v = x[i];
        s += v; ss += v * v;
    }
    #pragma unroll
    for (int o = 16; o; o >>= 1) {
        s  += __shfl_down_sync(0xffffffffu, s, o);
        ss += __shfl_down_sync(0xffffffffu, ss, o);
    }
    int wid = threadIdx.x >> 5, lane = threadIdx.x & 31;
    if (lane == 0) { red[wid] = s; red[8 + wid] = ss; }
    __syncthreads();
    if (threadIdx.x == 0) {
        float S = 0.f, SS = 0.f;
        #pragma unroll
        for (int i = 0; i < 8; i++) { S += red[i]; SS += red[8 + i]; }
        red[16] = S; red[17] = SS;
    }
    __syncthreads();
    mu  = red[16] * (1.f / DM);
    float var = red[17] * (1.f / DM) - mu * mu;
    inv = rsqrtf(var + 1e-6f);
}

// LN(Q) -> fp16
__global__ __launch_bounds__(256)
void ln_f16_kernel(const float* __restrict__ X, const float* __restrict__ w,
                   __half* __restrict__ O)
{
    const float* x = X + (size_t)blockIdx.x * DM;
    __half* o = O + (size_t)blockIdx.x * DM;
    float mu, inv;
    block_ln_stats(x, mu, inv);
    for (int i = threadIdx.x; i < DM; i += 256)
        o[i] = __float2half_rn((x[i] - mu) * inv * w[i]);
}

// RoPE + LN(K) -> fp16 hi/lo
__global__ __launch_bounds__(256)
void rope_ln_f16_kernel(float* __restrict__ X, const float* __restrict__ fpos,
                        const float* __restrict__ w,
                        __half* __restrict__ Oh, __half* __restrict__ Ol)
{
    const int row = blockIdx.x;
    const int n = row % HW_DIM;
    float* x = X + (size_t)row * DM;
    const float px = fpos[2 * n];
    const float py = fpos[2 * n + 1];
    const float TS = -9.210340371976184f / 288.0f;
    for (int p = threadIdx.x; p < 576; p += 256) {
        int q = (p < 288) ? p : (p - 288);
        float theta = expf((float)q * TS);
        float ang = ((p < 288) ? px : py) * theta;
        float c, s;
        sincosf(ang, &s, &c);
        int base = (p < 288) ? (2 * q) : (576 + 2 * q);
        float a = x[base], b = x[base + 1];
        x[base]     = a * c - b * s;
        x[base + 1] = a * s + b * c;
    }
    __syncthreads();
    float mu, inv;
    block_ln_stats(x, mu, inv);
    __half* oh = Oh + (size_t)row * DM;
    __half* ol = Ol + (size_t)row * DM;
    for (int i = threadIdx.x; i < DM; i += 256) {
        float y = (x[i] - mu) * inv * w[i];
        __half h = __float2half_rn(y);
        oh[i] = h;
        ol[i] = __float2half_rn(y - __half2float(h));
    }
}

// ---------------- tensor-core fused attention --------------------------------
#define APITCH 304
#define ATSZ   (64 * APITCH)
#define ASTG   (3 * ATSZ)
#define AKPOS  (2 * ASTG)
#define ATTN_SMEM (AKPOS + 2 * 512)

__global__ __launch_bounds__(256, 1)
void attn_mma_kernel(const __half* __restrict__ Qh, const __half* __restrict__ Kh,
                     const __half* __restrict__ Kl, const __half* __restrict__ Vh,
                     const float* __restrict__ tracks, const float* __restrict__ fpos,
                     __half* __restrict__ Sh)
{
    extern __shared__ char sm[];
    uint32_t sb = smem_u32(sm);
    const int tid  = threadIdx.x;
    const int lane = tid & 31;
    const int w    = tid >> 5;
    const int gid  = lane >> 2;
    const int tig  = lane & 3;
    const int m0   = blockIdx.x * 128;
    const int h    = blockIdx.y;
    const int t    = blockIdx.z;

    const char* qbase  = (const char*)(Qh + ((size_t)t * M_TRK + m0) * DM + h * DH);
    const char* khbase = (const char*)(Kh + (size_t)t * HW_DIM * DM + h * DH);
    const char* klbase = (const char*)(Kl + (size_t)t * HW_DIM * DM + h * DH);
    const char* vbase  = (const char*)(Vh + (size_t)t * HW_DIM * DM + h * DH);

    float2 qp0 = *(const float2*)(tracks + ((size_t)t * M_TRK + m0 + w * 16 + gid) * 2);
    float2 qp1 = *(const float2*)(tracks + ((size_t)t * M_TRK + m0 + w * 16 + gid + 8) * 2);

    #pragma unroll
    for (int i = 0; i < 9; i++) {
        int c = tid + i * 256;
        int row = c / 18, ch = c % 18;
        cp16(sb + row * APITCH + ch * 16, qbase + (size_t)row * (DM * 2) + ch * 16);
    }
    asm volatile("cp.async.commit_group;" ::: "memory");
    asm volatile("cp.async.wait_group 0;" ::: "memory");
    __syncthreads();

    uint32_t qf[9][4];
    {
        uint32_t qa = sb + (uint32_t)(w * 16 + (lane & 15)) * APITCH + (uint32_t)(lane >> 4) * 16u;
        #pragma unroll
        for (int kc = 0; kc < 9; kc++) ldm4(qa + kc * 32, qf[kc]);
    }
    __syncthreads();

    auto load_tile = [&](int st, int kt) {
        int k0 = kt * 64;
        uint32_t stb = sb + (uint32_t)st * (uint32_t)ASTG;
        #pragma unroll
        for (int i = 0; i < 14; i++) {
            int c = tid + i * 256;
            if (c < 3456) {
                int buf = c / 1152, rem = c % 1152;
                int row = rem / 18, ch = rem % 18;
                int krow = k0 + row; if (krow > HW_DIM - 1) krow = HW_DIM - 1;
                const char* src = (buf == 0) ? khbase : (buf == 1) ? klbase : vbase;
                cp16(stb + (uint32_t)buf * (uint32_t)ATSZ + (uint32_t)row * APITCH + (uint32_t)ch * 16u,
                     src + (size_t)krow * (DM * 2) + ch * 16);
            }
        }
        asm volatile("cp.async.commit_group;" ::: "memory");
        if (tid < 64) {
            int kr = k0 + tid; if (kr > HW_DIM - 1) kr = HW_DIM - 1;
            float2 v = *(const float2*)(fpos + (size_t)kr * 2);
            *(float2*)(sm + AKPOS + st * 512 + tid * 8) = v;
        }
    };

    load_tile(0, 0);
    load_tile(1, 1);

    float m_0 = -1e30f, m_1 = -1e30f, l_0 = 0.f, l_1 = 0.f;
    float oacc[18][4];
    #pragma unroll
    for (int a = 0; a < 18; a++)
        #pragma unroll
        for (int q = 0; q < 4; q++) oacc[a][q] = 0.f;

    const int NT = (HW_DIM + 63) / 64;   // 12
    for (int kt = 0; kt < NT; kt++) {
        const int st = kt & 1;
        const int k0 = kt * 64;
        const int cnt = min(64, HW_DIM - k0);
        if (kt < NT - 1) asm volatile("cp.async.wait_group 1;" ::: "memory");
        else             asm volatile("cp.async.wait_group 0;" ::: "memory");
        __syncthreads();

        uint32_t stb = sb + (uint32_t)st * (uint32_t)ASTG;
        uint32_t lrow = (uint32_t)(lane & 15) * APITCH + (uint32_t)(lane >> 4) * 16u;
        uint32_t khb = stb + lrow;
        uint32_t klb = khb + ATSZ;
        uint32_t vhb = stb + 2u * ATSZ + lrow;

        float sacc[8][4];
        #pragma unroll
        for (int a = 0; a < 8; a++)
            #pragma unroll
            for (int q = 0; q < 4; q++) sacc[a][q] = 0.f;

        #pragma unroll
        for (int kc = 0; kc < 9; kc++) {
            uint32_t bh[4][4], bl[4][4];
            #pragma unroll
            for (int g = 0; g < 4; g++) {
                ldm4(khb + g * (16 * APITCH) + kc * 32, bh[g]);
                ldm4(klb + g * (16 * APITCH) + kc * 32, bl[g]);
            }
            #pragma unroll
            for (int g = 0; g < 4; g++) {
                mma_f16(sacc[2*g],   qf[kc], bh[g][0], bh[g][2]);
                mma_f16(sacc[2*g],   qf[kc], bl[g][0], bl[g][2]);
                mma_f16(sacc[2*g+1], qf[kc], bh[g][1], bh[g][3]);
                mma_f16(sacc[2*g+1], qf[kc], bl[g][1], bl[g][3]);
            }
        }

        const float2* kp = (const float2*)(sm + AKPOS + st * 512);
        float mn0 = m_0, mn1 = m_1;
        #pragma unroll
        for (int a = 0; a < 8; a++) {
            int c0 = a * 8 + tig * 2;
            float2 ka = kp[c0];
            float2 kb = kp[c0 + 1];
            float dxa0 = qp0.x - ka.x, dya0 = qp0.y - ka.y;
            float dxb0 = qp0.x - kb.x, dyb0 = qp0.y - kb.y;
            float dxa1 = qp1.x - ka.x, dya1 = qp1.y - ka.y;
            float dxb1 = qp1.x - kb.x, dyb1 = qp1.y - kb.y;
            bool va = (c0 < cnt), vb = (c0 + 1 < cnt);
            sacc[a][0] = va ? sacc[a][0] * (1.f/12.f) - (dxa0*dxa0 + dya0*dya0) * 0.125f : -1e30f;
            sacc[a][1] = vb ? sacc[a][1] * (1.f/12.f) - (dxb0*dxb0 + dyb0*dyb0) * 0.125f : -1e30f;
            sacc[a][2] = va ? sacc[a][2] * (1.f/12.f) - (dxa1*dxa1 + dya1*dya1) * 0.125f : -1e30f;
            sacc[a][3] = vb ? sacc[a][3] * (1.f/12.f) - (dxb1*dxb1 + dyb1*dyb1) * 0.125f : -1e30f;
            mn0 = fmaxf(mn0, fmaxf(sacc[a][0], sacc[a][1]));
            mn1 = fmaxf(mn1, fmaxf(sacc[a][2], sacc[a][3]));
        }
        mn0 = fmaxf(mn0, __shfl_xor_sync(0xffffffffu, mn0, 1));
        mn0 = fmaxf(mn0, __shfl_xor_sync(0xffffffffu, mn0, 2));
        mn1 = fmaxf(mn1, __shfl_xor_sync(0xffffffffu, mn1, 1));
        mn1 = fmaxf(mn1, __shfl_xor_sync(0xffffffffu, mn1, 2));
        float corr0 = __expf(m_0 - mn0);
        float corr1 = __expf(m_1 - mn1);
        m_0 = mn0; m_1 = mn1;
        l_0 *= corr0; l_1 *= corr1;
        #pragma unroll
        for (int a = 0; a < 18; a++) {
            oacc[a][0] *= corr0; oacc[a][1] *= corr0;
            oacc[a][2] *= corr1; oacc[a][3] *= corr1;
        }
        #pragma unroll
        for (int a = 0; a < 8; a++) {
            float p0 = __expf(sacc[a][0] - m_0);
            float p1 = __expf(sacc[a][1] - m_0);
            float p2 = __expf(sacc[a][2] - m_1);
            float p3 = __expf(sacc[a][3] - m_1);
            l_0 += p0 + p1; l_1 += p2 + p3;
            sacc[a][0] = p0; sacc[a][1] = p1; sacc[a][2] = p2; sacc[a][3] = p3;
        }

        #pragma unroll
        for (int kc4 = 0; kc4 < 4; kc4++) {
            uint32_t pa[4];
            pa[0] = pack_h2(sacc[2*kc4][0],   sacc[2*kc4][1]);
            pa[1] = pack_h2(sacc[2*kc4][2],   sacc[2*kc4][3]);
            pa[2] = pack_h2(sacc[2*kc4+1][0], sacc[2*kc4+1][1]);
            pa[3] = pack_h2(sacc[2*kc4+1][2], sacc[2*kc4+1][3]);
            #pragma unroll
            for (int dp = 0; dp < 9; dp++) {
                uint32_t vf[4];
                ldm4t(vhb + kc4 * (16 * APITCH) + dp * 32, vf);
                mma_f16(oacc[2*dp],   pa, vf[0], vf[1]);
                mma_f16(oacc[2*dp+1], pa, vf[2], vf[3]);
            }
        }

        __syncthreads();
        if (kt + 2 < NT) load_tile(st, kt + 2);
    }

    l_0 += __shfl_xor_sync(0xffffffffu, l_0, 1);
    l_0 += __shfl_xor_sync(0xffffffffu, l_0, 2);
    l_1 += __shfl_xor_sync(0xffffffffu, l_1, 1);
    l_1 += __shfl_xor_sync(0xffffffffu, l_1, 2);
    float inv0 = 1.f / l_0, inv1 = 1.f / l_1;

    size_t row0 = (size_t)t * M_TRK + m0 + w * 16 + gid;
    #pragma unroll
    for (int a = 0; a < 18; a++) {
        int col = h * DH + a * 8 + tig * 2;
        *(__half2*)(Sh + row0 * DM + col) =
            __floats2half2_rn(oacc[a][0] * inv0, oacc[a][1] * inv0);
        *(__half2*)(Sh + (row0 + 8) * DM + col) =
            __floats2half2_rn(oacc[a][2] * inv1, oacc[a][3] * inv1);
    }
}

// ---------------- launch ----------------
extern "C" void kernel_launch(void* const* d_in, const int* in_sizes, int n_in,
                              void* d_out, int out_size)
{
    const float* features    = (const float*)d_in[0];
    const float* tracks      = (const float*)d_in[1];
    const float* track_toks  = (const float*)d_in[2];
    const float* fpos        = (const float*)d_in[3];
    const float* W_q         = (const float*)d_in[4];
    const float* W_k         = (const float*)d_in[5];
    const float* q_norm_w    = (const float*)d_in[6];
    const float* k_norm_w    = (const float*)d_in[7];
    const float* out_proj_w  = (const float*)d_in[8];
    float* out = (float*)d_out;

    float *gQ, *gK;
    __half *gTTh, *gFh, *gWh, *gQh, *gKh, *gKl, *gSh;
    cudaGetSymbolAddress((void**)&gQ, g_Q);
    cudaGetSymbolAddress((void**)&gK, g_K);
    cudaGetSymbolAddress((void**)&gTTh, g_TTh);
    cudaGetSymbolAddress((void**)&gFh, g_Fh);
    cudaGetSymbolAddress((void**)&gWh, g_Wh);
    cudaGetSymbolAddress((void**)&gQh, g_Qh);
    cudaGetSymbolAddress((void**)&gKh, g_Kh);
    cudaGetSymbolAddress((void**)&gKl, g_Kl);
    cudaGetSymbolAddress((void**)&gSh, g_Sh);

    cudaFuncSetAttribute(gemm_mma_f16, cudaFuncAttributeMaxDynamicSharedMemorySize,
                         GEMM_SMEM);
    cudaFuncSetAttribute(attn_mma_kernel, cudaFuncAttributeMaxDynamicSharedMemorySize,
                         ATTN_SMEM);

    dim3 wtg(DM / 32, DM / 32);

    // ---- fp16 conversions for GEMM A operands ----
    f32_to_f16_kernel<<<4096, 256>>>(track_toks, gTTh, (long)MQ * DM / 4);
    f32_to_f16_kernel<<<4096, 256>>>(features, gFh, (long)MK * DM / 4);

    // ---- Q = track_tokens @ W_q ----
    wt_f16_kernel<<<wtg, 256>>>(W_q, gWh);
    {
        dim3 g(DM / 128, (MQ + 127) / 128);
        gemm_mma_f16<<<g, 128, GEMM_SMEM>>>(gTTh, gWh, gQ, MQ);
    }

    // ---- K = features @ W_k ----
    wt_f16_kernel<<<wtg, 256>>>(W_k, gWh);
    {
        dim3 g(DM / 128, (MK + 127) / 128);
        gemm_mma_f16<<<g, 128, GEMM_SMEM>>>(gFh, gWh, gK, MK);
    }

    // ---- LN(Q)->fp16, RoPE+LN(K)->fp16 hi/lo ----
    ln_f16_kernel<<<MQ, 256>>>(gQ, q_norm_w, gQh);
    rope_ln_f16_kernel<<<MK, 256>>>(gK, fpos, k_norm_w, gKh, gKl);

    // ---- fused tensor-core attention (V = features fp16) ----
    {
        dim3 g(M_TRK / 128, NH, T_DIM);
        attn_mma_kernel<<<g, 256, ATTN_SMEM>>>(gQh, gKh, gKl, gFh, tracks, fpos, gSh);
    }

    // ---- out = sampled @ out_proj_w ----
    wt_f16_kernel<<<wtg, 256>>>(out_proj_w, gWh);
    {
        dim3 g(DM / 128, (MQ + 127) / 128);
        gemm_mma_f16<<<g, 128, GEMM_SMEM>>>(gSh, gWh, out, MQ);
    }
}

// round 9
// speedup vs baseline: 7.4003x; 1.1415x over previous
#include <cuda_runtime.h>
#include <cuda_fp16.h>
#include <math.h>
#include <stdint.h>

// ---------------- problem constants ----------------
#define T_DIM   64
#define HW_DIM  729
#define M_TRK   512
#define DM      1152
#define NH      8
#define DH      144
#define MQ      (T_DIM * M_TRK)    // 32768
#define MK      (T_DIM * HW_DIM)   // 46656

// ---------------- device scratch ----------------
__device__ float g_Q[(size_t)MQ * DM];     // Q gemm out (fp32)
__device__ float g_K[(size_t)MK * DM];     // K gemm out (fp32)
__device__ __half g_TTh[(size_t)MQ * DM];  // track_tokens fp16
__device__ __half g_Fh[(size_t)MK * DM];   // features fp16 (GEMM A and attention V)
__device__ __half g_Wh[(size_t)DM * DM];   // weight fp16, transposed [N,K]
__device__ __half g_Qh[(size_t)MQ * DM];   // LN'd Q fp16
__device__ __half g_Kh[(size_t)MK * DM];   // LN'd+RoPE'd K hi
__device__ __half g_Kl[(size_t)MK * DM];   // K lo
__device__ __half g_Sh[(size_t)MQ * DM];   // attention out fp16
__device__ float2 g_rtab[(size_t)HW_DIM * 576];  // per-position (cos,sin)

__device__ __forceinline__ uint32_t smem_u32(const void* p) {
    uint32_t a;
    asm("{ .reg .u64 t; cvta.to.shared.u64 t, %1; cvt.u32.u64 %0, t; }" : "=r"(a) : "l"(p));
    return a;
}
__device__ __forceinline__ void cp16(uint32_t dst, const void* src) {
    asm volatile("cp.async.cg.shared.global [%0], [%1], 16;" :: "r"(dst), "l"(src));
}
__device__ __forceinline__ void ldm4(uint32_t addr, uint32_t* r) {
    asm volatile("ldmatrix.sync.aligned.m8n8.x4.shared.b16 {%0,%1,%2,%3}, [%4];"
                 : "=r"(r[0]), "=r"(r[1]), "=r"(r[2]), "=r"(r[3])
                 : "r"(addr) : "memory");
}
__device__ __forceinline__ void ldm4t(uint32_t addr, uint32_t* r) {
    asm volatile("ldmatrix.sync.aligned.m8n8.x4.trans.shared.b16 {%0,%1,%2,%3}, [%4];"
                 : "=r"(r[0]), "=r"(r[1]), "=r"(r[2]), "=r"(r[3])
                 : "r"(addr) : "memory");
}
__device__ __forceinline__ void mma_f16(float* d, const uint32_t* a,
                                        uint32_t b0, uint32_t b1) {
    asm volatile(
        "mma.sync.aligned.m16n8k16.row.col.f32.f16.f16.f32 "
        "{%0,%1,%2,%3}, {%4,%5,%6,%7}, {%8,%9}, {%0,%1,%2,%3};"
        : "+f"(d[0]), "+f"(d[1]), "+f"(d[2]), "+f"(d[3])
        : "r"(a[0]), "r"(a[1]), "r"(a[2]), "r"(a[3]), "r"(b0), "r"(b1));
}
__device__ __forceinline__ uint32_t pack_h2(float a, float b) {
    __half2 h = __floats2half2_rn(a, b);
    return *(uint32_t*)&h;
}

// ================= fp32 -> fp16 convert ======================================
__global__ __launch_bounds__(256)
void f32_to_f16_kernel(const float* __restrict__ X, __half* __restrict__ O, long n4)
{
    long i = (long)blockIdx.x * blockDim.x + threadIdx.x;
    long stride = (long)gridDim.x * blockDim.x;
    for (; i < n4; i += stride) {
        float4 v = ((const float4*)X)[i];
        ((__half2*)O)[2*i]   = __floats2half2_rn(v.x, v.y);
        ((__half2*)O)[2*i+1] = __floats2half2_rn(v.z, v.w);
    }
}

// ============ weight fp16 + transpose: W[K,N] fp32 -> Ht [N,K] fp16 ==========
__global__ __launch_bounds__(256)
void wt_f16_kernel(const float* __restrict__ W, __half* __restrict__ Ht)
{
    __shared__ float tile[32][33];
    int tx = threadIdx.x & 31, ty = threadIdx.x >> 5;
    int nb = blockIdx.x * 32, kb = blockIdx.y * 32;
    #pragma unroll
    for (int r = ty; r < 32; r += 8)
        tile[r][tx] = W[(size_t)(kb + r) * DM + nb + tx];
    __syncthreads();
    #pragma unroll
    for (int r = ty; r < 32; r += 8)
        Ht[(size_t)(nb + r) * DM + kb + tx] = __float2half_rn(tile[tx][r]);
}

// ================= RoPE cos/sin table ========================================
__global__ __launch_bounds__(256)
void rope_tab_kernel(const float* __restrict__ fpos)
{
    const int n = blockIdx.x;
    const float px = fpos[2 * n];
    const float py = fpos[2 * n + 1];
    const float TS = -9.210340371976184f / 288.0f;
    for (int p = threadIdx.x; p < 576; p += 256) {
        int q = (p < 288) ? p : (p - 288);
        float theta = expf((float)q * TS);
        float ang = ((p < 288) ? px : py) * theta;
        float c, s;
        sincosf(ang, &s, &c);
        g_rtab[(size_t)n * 576 + p] = make_float2(c, s);
    }
}

// =================== mma.sync fp16 GEMM, BK=64, XOR swizzle ==================
// C[M,1152] = A @ B; A fp16 row-major [M,K], BhT fp16 [N,K].
// BM=128, BN=128, BK=64; 4 warps (2M x 2N), warp tile 64x64.
// Tile: 128 rows x 128B, chunk j stored at (j ^ (row&7))*16. 3 stages, 1 sync/chunk.
#define GTB 16384                     // one 128x128B tile
#define GSTG (2 * GTB)                // 32768 (A, B)
#define GNST 3
#define GEMM_SMEM (GNST * GSTG)       // 98304
#define KC2 18                        // 1152 / 64

__global__ __launch_bounds__(128)
void gemm_mma_f16(const __half* __restrict__ A, const __half* __restrict__ BhT,
                  float* __restrict__ C, int M)
{
    extern __shared__ char dsm[];
    const int tid  = threadIdx.x;
    const int lane = tid & 31;
    const int wid  = tid >> 5;         // 0..3
    const int wm   = wid & 1;
    const int wn   = wid >> 1;
    const int n0   = blockIdx.x * 128;
    const int m0   = blockIdx.y * 128;

    uint32_t sb = smem_u32(dsm);
    const char* srcbase[2] = { (const char*)A, (const char*)BhT };

    float acc[4][8][4];
    #pragma unroll
    for (int i = 0; i < 4; i++)
        #pragma unroll
        for (int j = 0; j < 8; j++)
            #pragma unroll
            for (int q = 0; q < 4; q++) acc[i][j][q] = 0.f;

    auto load_stage = [&](int stage, int chunk) {
        uint32_t stb = sb + (uint32_t)stage * (uint32_t)GSTG;
        #pragma unroll
        for (int it = 0; it < 16; it++) {
            int flat = tid + it * 128;          // 0..2047
            int t2 = flat >> 10;                // 0..1
            int r  = (flat >> 3) & 127;
            int c4 = flat & 7;
            int grow;
            if (t2 == 0) { grow = m0 + r; if (grow > M - 1) grow = M - 1; }
            else         { grow = n0 + r; }
            const char* src = srcbase[t2] + (size_t)grow * (DM * 2)
                              + (size_t)chunk * 128 + c4 * 16;
            uint32_t dst = stb + (uint32_t)t2 * (uint32_t)GTB
                           + (uint32_t)r * 128u + (uint32_t)((c4 ^ (r & 7)) << 4);
            cp16(dst, src);
        }
        asm volatile("cp.async.commit_group;" ::: "memory");
    };

    load_stage(0, 0);
    load_stage(1, 1);

    // ldmatrix addressing: row = tilebase + (lane&15), j = 2kc + (lane>>4)
    // all tile row-bases are multiples of 8, so row&7 == lane&7 everywhere.
    uint32_t xoff[4];
    #pragma unroll
    for (int kc = 0; kc < 4; kc++)
        xoff[kc] = (uint32_t)(((2 * kc + (lane >> 4)) ^ (lane & 7)) << 4);
    uint32_t aRow[4], bRow[4];
    #pragma unroll
    for (int i = 0; i < 4; i++) {
        aRow[i] = (uint32_t)(wm * 64 + i * 16 + (lane & 15)) * 128u;
        bRow[i] = (uint32_t)(wn * 64 + i * 16 + (lane & 15)) * 128u;
    }

    for (int c = 0; c < KC2; c++) {
        const int s = c % GNST;
        if (c < KC2 - 1) asm volatile("cp.async.wait_group 1;" ::: "memory");
        else             asm volatile("cp.async.wait_group 0;" ::: "memory");
        __syncthreads();   // chunk c visible; all warps done with chunk c-1

        if (c + 2 < KC2) load_stage((c + 2) % GNST, c + 2);

        uint32_t stb = sb + (uint32_t)s * (uint32_t)GSTG;
        #pragma unroll
        for (int kc = 0; kc < 4; kc++) {
            uint32_t ah[4][4], bh[4][4];
            #pragma unroll
            for (int a = 0; a < 4; a++)
                ldm4(stb + aRow[a] + xoff[kc], ah[a]);
            #pragma unroll
            for (int b = 0; b < 4; b++)
                ldm4(stb + GTB + bRow[b] + xoff[kc], bh[b]);
            #pragma unroll
            for (int am = 0; am < 4; am++) {
                #pragma unroll
                for (int bt = 0; bt < 4; bt++) {
                    mma_f16(acc[am][2*bt],   ah[am], bh[bt][0], bh[bt][2]);
                    mma_f16(acc[am][2*bt+1], ah[am], bh[bt][1], bh[bt][3]);
                }
            }
        }
    }

    #pragma unroll
    for (int am = 0; am < 4; am++) {
        int m = m0 + wm * 64 + am * 16 + (lane >> 2);
        #pragma unroll
        for (int bt = 0; bt < 8; bt++) {
            int n = n0 + wn * 64 + bt * 8 + (lane & 3) * 2;
            if (m < M)
                *(float2*)(C + (size_t)m * DM + n) = make_float2(acc[am][bt][0], acc[am][bt][1]);
            if (m + 8 < M)
                *(float2*)(C + (size_t)(m + 8) * DM + n) = make_float2(acc[am][bt][2], acc[am][bt][3]);
        }
    }
}

// ---------------- LayerNorm helpers ------------------------------------------
__device__ __forceinline__ void block_ln_stats(const float* x, float& mu, float& inv)
{
    __shared__ float red[18];
    float s = 0.f, ss = 0.f;
    for (int i = threadIdx.x; i < DM; i += 256) {
        float v = x[i];
        s += v; ss += v * v;
    }
    #pragma unroll
    for (int o = 16; o; o >>= 1) {
        s  += __shfl_down_sync(0xffffffffu, s, o);
        ss += __shfl_down_sync(0xffffffffu, ss, o);
    }
    int wid = threadIdx.x >> 5, lane = threadIdx.x & 31;
    if (lane == 0) { red[wid] = s; red[8 + wid] = ss; }
    __syncthreads();
    if (threadIdx.x == 0) {
        float S = 0.f, SS = 0.f;
        #pragma unroll
        for (int i = 0; i < 8; i++) { S += red[i]; SS += red[8 + i]; }
        red[16] = S; red[17] = SS;
    }
    __syncthreads();
    mu  = red[16] * (1.f / DM);
    float var = red[17] * (1.f / DM) - mu * mu;
    inv = rsqrtf(var + 1e-6f);
}

// LN(Q) -> fp16
__global__ __launch_bounds__(256)
void ln_f16_kernel(const float* __restrict__ X, const float* __restrict__ w,
                   __half* __restrict__ O)
{
    const float* x = X + (size_t)blockIdx.x * DM;
    __half* o = O + (size_t)blockIdx.x * DM;
    float mu, inv;
    block_ln_stats(x, mu, inv);
    for (int i = threadIdx.x; i < DM; i += 256)
        o[i] = __float2half_rn((x[i] - mu) * inv * w[i]);
}

// RoPE (table-driven) + LN(K) -> fp16 hi/lo
__global__ __launch_bounds__(256)
void rope_ln_f16_kernel(float* __restrict__ X, const float* __restrict__ w,
                        __half* __restrict__ Oh, __half* __restrict__ Ol)
{
    const int row = blockIdx.x;
    const int n = row % HW_DIM;
    float* x = X + (size_t)row * DM;
    const float2* rt = g_rtab + (size_t)n * 576;
    for (int p = threadIdx.x; p < 576; p += 256) {
        float2 cs = rt[p];
        int q = (p < 288) ? p : (p - 288);
        int base = (p < 288) ? (2 * q) : (576 + 2 * q);
        float a = x[base], b = x[base + 1];
        x[base]     = a * cs.x - b * cs.y;
        x[base + 1] = a * cs.y + b * cs.x;
    }
    __syncthreads();
    float mu, inv;
    block_ln_stats(x, mu, inv);
    __half* oh = Oh + (size_t)row * DM;
    __half* ol = Ol + (size_t)row * DM;
    for (int i = threadIdx.x; i < DM; i += 256) {
        float y = (x[i] - mu) * inv * w[i];
        __half h = __float2half_rn(y);
        oh[i] = h;
        ol[i] = __float2half_rn(y - __half2float(h));
    }
}

// ---------------- tensor-core fused attention (3-stage, 1 sync/tile) ---------
#define APITCH 304
#define ATSZ   (64 * APITCH)
#define ASTG   (3 * ATSZ)              // Kh, Kl, Vh
#define ANST   3
#define AKPOS  (ANST * ASTG)           // 175104
#define ATTN_SMEM (AKPOS + ANST * 512) // 176640

__global__ __launch_bounds__(256, 1)
void attn_mma_kernel(const __half* __restrict__ Qh, const __half* __restrict__ Kh,
                     const __half* __restrict__ Kl, const __half* __restrict__ Vh,
                     const float* __restrict__ tracks, const float* __restrict__ fpos,
                     __half* __restrict__ Sh)
{
    extern __shared__ char sm[];
    uint32_t sb = smem_u32(sm);
    const int tid  = threadIdx.x;
    const int lane = tid & 31;
    const int w    = tid >> 5;
    const int gid  = lane >> 2;
    const int tig  = lane & 3;
    const int m0   = blockIdx.x * 128;
    const int h    = blockIdx.y;
    const int t    = blockIdx.z;

    const char* qbase  = (const char*)(Qh + ((size_t)t * M_TRK + m0) * DM + h * DH);
    const char* khbase = (const char*)(Kh + (size_t)t * HW_DIM * DM + h * DH);
    const char* klbase = (const char*)(Kl + (size_t)t * HW_DIM * DM + h * DH);
    const char* vbase  = (const char*)(Vh + (size_t)t * HW_DIM * DM + h * DH);

    float2 qp0 = *(const float2*)(tracks + ((size_t)t * M_TRK + m0 + w * 16 + gid) * 2);
    float2 qp1 = *(const float2*)(tracks + ((size_t)t * M_TRK + m0 + w * 16 + gid + 8) * 2);

    #pragma unroll
    for (int i = 0; i < 9; i++) {
        int c = tid + i * 256;
        int row = c / 18, ch = c % 18;
        cp16(sb + row * APITCH + ch * 16, qbase + (size_t)row * (DM * 2) + ch * 16);
    }
    asm volatile("cp.async.commit_group;" ::: "memory");
    asm volatile("cp.async.wait_group 0;" ::: "memory");
    __syncthreads();

    uint32_t qf[9][4];
    {
        uint32_t qa = sb + (uint32_t)(w * 16 + (lane & 15)) * APITCH + (uint32_t)(lane >> 4) * 16u;
        #pragma unroll
        for (int kc = 0; kc < 9; kc++) ldm4(qa + kc * 32, qf[kc]);
    }
    __syncthreads();

    auto load_tile = [&](int st, int kt) {
        int k0 = kt * 64;
        uint32_t stb = sb + (uint32_t)st * (uint32_t)ASTG;
        #pragma unroll
        for (int i = 0; i < 14; i++) {
            int c = tid + i * 256;
            if (c < 3456) {
                int buf = c / 1152, rem = c % 1152;
                int row = rem / 18, ch = rem % 18;
                int krow = k0 + row; if (krow > HW_DIM - 1) krow = HW_DIM - 1;
                const char* src = (buf == 0) ? khbase : (buf == 1) ? klbase : vbase;
                cp16(stb + (uint32_t)buf * (uint32_t)ATSZ + (uint32_t)row * APITCH + (uint32_t)ch * 16u,
                     src + (size_t)krow * (DM * 2) + ch * 16);
            }
        }
        asm volatile("cp.async.commit_group;" ::: "memory");
        if (tid < 64) {
            int kr = k0 + tid; if (kr > HW_DIM - 1) kr = HW_DIM - 1;
            float2 v = *(const float2*)(fpos + (size_t)kr * 2);
            *(float2*)(sm + AKPOS + st * 512 + tid * 8) = v;
        }
    };

    load_tile(0, 0);
    load_tile(1, 1);

    float m_0 = -1e30f, m_1 = -1e30f, l_0 = 0.f, l_1 = 0.f;
    float oacc[18][4];
    #pragma unroll
    for (int a = 0; a < 18; a++)
        #pragma unroll
        for (int q = 0; q < 4; q++) oacc[a][q] = 0.f;

    const int NT = (HW_DIM + 63) / 64;   // 12
    for (int kt = 0; kt < NT; kt++) {
        const int st = kt % ANST;
        const int k0 = kt * 64;
        const int cnt = min(64, HW_DIM - k0);
        if (kt < NT - 1) asm volatile("cp.async.wait_group 1;" ::: "memory");
        else             asm volatile("cp.async.wait_group 0;" ::: "memory");
        __syncthreads();   // tile kt visible; all warps done with tile kt-1

        if (kt + 2 < NT) load_tile((kt + 2) % ANST, kt + 2);

        uint32_t stb = sb + (uint32_t)st * (uint32_t)ASTG;
        uint32_t lrow = (uint32_t)(lane & 15) * APITCH + (uint32_t)(lane >> 4) * 16u;
        uint32_t khb = stb + lrow;
        uint32_t klb = khb + ATSZ;
        uint32_t vhb = stb + 2u * ATSZ + lrow;

        float sacc[8][4];
        #pragma unroll
        for (int a = 0; a < 8; a++)
            #pragma unroll
            for (int q = 0; q < 4; q++) sacc[a][q] = 0.f;

        #pragma unroll
        for (int kc = 0; kc < 9; kc++) {
            uint32_t bh[4][4], bl[4][4];
            #pragma unroll
            for (int g = 0; g < 4; g++) {
                ldm4(khb + g * (16 * APITCH) + kc * 32, bh[g]);
                ldm4(klb + g * (16 * APITCH) + kc * 32, bl[g]);
            }
            #pragma unroll
            for (int g = 0; g < 4; g++) {
                mma_f16(sacc[2*g],   qf[kc], bh[g][0], bh[g][2]);
                mma_f16(sacc[2*g],   qf[kc], bl[g][0], bl[g][2]);
                mma_f16(sacc[2*g+1], qf[kc], bh[g][1], bh[g][3]);
                mma_f16(sacc[2*g+1], qf[kc], bl[g][1], bl[g][3]);
            }
        }

        const float2* kp = (const float2*)(sm + AKPOS + st * 512);
        float mn0 = m_0, mn1 = m_1;
        #pragma unroll
        for (int a = 0; a < 8; a++) {
            int c0 = a * 8 + tig * 2;
            float2 ka = kp[c0];
            float2 kb = kp[c0 + 1];
            float dxa0 = qp0.x - ka.x, dya0 = qp0.y - ka.y;
            float dxb0 = qp0.x - kb.x, dyb0 = qp0.y - kb.y;
            float dxa1 = qp1.x - ka.x, dya1 = qp1.y - ka.y;
            float dxb1 = qp1.x - kb.x, dyb1 = qp1.y - kb.y;
            bool va = (c0 < cnt), vb = (c0 + 1 < cnt);
            sacc[a][0] = va ? sacc[a][0] * (1.f/12.f) - (dxa0*dxa0 + dya0*dya0) * 0.125f : -1e30f;
            sacc[a][1] = vb ? sacc[a][1] * (1.f/12.f) - (dxb0*dxb0 + dyb0*dyb0) * 0.125f : -1e30f;
            sacc[a][2] = va ? sacc[a][2] * (1.f/12.f) - (dxa1*dxa1 + dya1*dya1) * 0.125f : -1e30f;
            sacc[a][3] = vb ? sacc[a][3] * (1.f/12.f) - (dxb1*dxb1 + dyb1*dyb1) * 0.125f : -1e30f;
            mn0 = fmaxf(mn0, fmaxf(sacc[a][0], sacc[a][1]));
            mn1 = fmaxf(mn1, fmaxf(sacc[a][2], sacc[a][3]));
        }
        mn0 = fmaxf(mn0, __shfl_xor_sync(0xffffffffu, mn0, 1));
        mn0 = fmaxf(mn0, __shfl_xor_sync(0xffffffffu, mn0, 2));
        mn1 = fmaxf(mn1, __shfl_xor_sync(0xffffffffu, mn1, 1));
        mn1 = fmaxf(mn1, __shfl_xor_sync(0xffffffffu, mn1, 2));
        float corr0 = __expf(m_0 - mn0);
        float corr1 = __expf(m_1 - mn1);
        m_0 = mn0; m_1 = mn1;
        l_0 *= corr0; l_1 *= corr1;
        #pragma unroll
        for (int a = 0; a < 18; a++) {
            oacc[a][0] *= corr0; oacc[a][1] *= corr0;
            oacc[a][2] *= corr1; oacc[a][3] *= corr1;
        }
        #pragma unroll
        for (int a = 0; a < 8; a++) {
            float p0 = __expf(sacc[a][0] - m_0);
            float p1 = __expf(sacc[a][1] - m_0);
            float p2 = __expf(sacc[a][2] - m_1);
            float p3 = __expf(sacc[a][3] - m_1);
            l_0 += p0 + p1; l_1 += p2 + p3;
            sacc[a][0] = p0; sacc[a][1] = p1; sacc[a][2] = p2; sacc[a][3] = p3;
        }

        #pragma unroll
        for (int kc4 = 0; kc4 < 4; kc4++) {
            uint32_t pa[4];
            pa[0] = pack_h2(sacc[2*kc4][0],   sacc[2*kc4][1]);
            pa[1] = pack_h2(sacc[2*kc4][2],   sacc[2*kc4][3]);
            pa[2] = pack_h2(sacc[2*kc4+1][0], sacc[2*kc4+1][1]);
            pa[3] = pack_h2(sacc[2*kc4+1][2], sacc[2*kc4+1][3]);
            #pragma unroll
            for (int dp = 0; dp < 9; dp++) {
                uint32_t vf[4];
                ldm4t(vhb + kc4 * (16 * APITCH) + dp * 32, vf);
                mma_f16(oacc[2*dp],   pa, vf[0], vf[1]);
                mma_f16(oacc[2*dp+1], pa, vf[2], vf[3]);
            }
        }
    }

    l_0 += __shfl_xor_sync(0xffffffffu, l_0, 1);
    l_0 += __shfl_xor_sync(0xffffffffu, l_0, 2);
    l_1 += __shfl_xor_sync(0xffffffffu, l_1, 1);
    l_1 += __shfl_xor_sync(0xffffffffu, l_1, 2);
    float inv0 = 1.f / l_0, inv1 = 1.f / l_1;

    size_t row0 = (size_t)t * M_TRK + m0 + w * 16 + gid;
    #pragma unroll
    for (int a = 0; a < 18; a++) {
        int col = h * DH + a * 8 + tig * 2;
        *(__half2*)(Sh + row0 * DM + col) =
            __floats2half2_rn(oacc[a][0] * inv0, oacc[a][1] * inv0);
        *(__half2*)(Sh + (row0 + 8) * DM + col) =
            __floats2half2_rn(oacc[a][2] * inv1, oacc[a][3] * inv1);
    }
}

// ---------------- launch ----------------
extern "C" void kernel_launch(void* const* d_in, const int* in_sizes, int n_in,
                              void* d_out, int out_size)
{
    const float* features    = (const float*)d_in[0];
    const float* tracks      = (const float*)d_in[1];
    const float* track_toks  = (const float*)d_in[2];
    const float* fpos        = (const float*)d_in[3];
    const float* W_q         = (const float*)d_in[4];
    const float* W_k         = (const float*)d_in[5];
    const float* q_norm_w    = (const float*)d_in[6];
    const float* k_norm_w    = (const float*)d_in[7];
    const float* out_proj_w  = (const float*)d_in[8];
    float* out = (float*)d_out;

    float *gQ, *gK;
    __half *gTTh, *gFh, *gWh, *gQh, *gKh, *gKl, *gSh;
    cudaGetSymbolAddress((void**)&gQ, g_Q);
    cudaGetSymbolAddress((void**)&gK, g_K);
    cudaGetSymbolAddress((void**)&gTTh, g_TTh);
    cudaGetSymbolAddress((void**)&gFh, g_Fh);
    cudaGetSymbolAddress((void**)&gWh, g_Wh);
    cudaGetSymbolAddress((void**)&gQh, g_Qh);
    cudaGetSymbolAddress((void**)&gKh, g_Kh);
    cudaGetSymbolAddress((void**)&gKl, g_Kl);
    cudaGetSymbolAddress((void**)&gSh, g_Sh);

    cudaFuncSetAttribute(gemm_mma_f16, cudaFuncAttributeMaxDynamicSharedMemorySize,
                         GEMM_SMEM);
    cudaFuncSetAttribute(attn_mma_kernel, cudaFuncAttributeMaxDynamicSharedMemorySize,
                         ATTN_SMEM);

    dim3 wtg(DM / 32, DM / 32);

    // ---- fp16 conversions + RoPE table ----
    f32_to_f16_kernel<<<4096, 256>>>(track_toks, gTTh, (long)MQ * DM / 4);
    f32_to_f16_kernel<<<4096, 256>>>(features, gFh, (long)MK * DM / 4);
    rope_tab_kernel<<<HW_DIM, 256>>>(fpos);

    // ---- Q = track_tokens @ W_q ----
    wt_f16_kernel<<<wtg, 256>>>(W_q, gWh);
    {
        dim3 g(DM / 128, (MQ + 127) / 128);
        gemm_mma_f16<<<g, 128, GEMM_SMEM>>>(gTTh, gWh, gQ, MQ);
    }

    // ---- K = features @ W_k ----
    wt_f16_kernel<<<wtg, 256>>>(W_k, gWh);
    {
        dim3 g(DM / 128, (MK + 127) / 128);
        gemm_mma_f16<<<g, 128, GEMM_SMEM>>>(gFh, gWh, gK, MK);
    }

    // ---- LN(Q)->fp16, RoPE+LN(K)->fp16 hi/lo ----
    ln_f16_kernel<<<MQ, 256>>>(gQ, q_norm_w, gQh);
    rope_ln_f16_kernel<<<MK, 256>>>(gK, k_norm_w, gKh, gKl);

    // ---- fused tensor-core attention (V = features fp16) ----
    {
        dim3 g(M_TRK / 128, NH, T_DIM);
        attn_mma_kernel<<<g, 256, ATTN_SMEM>>>(gQh, gKh, gKl, gFh, tracks, fpos, gSh);
    }

    // ---- out = sampled @ out_proj_w ----
    wt_f16_kernel<<<wtg, 256>>>(out_proj_w, gWh);
    {
        dim3 g(DM / 128, (MQ + 127) / 128);
        gemm_mma_f16<<<g, 128, GEMM_SMEM>>>(gSh, gWh, out, MQ);
    }
}

// round 10
// speedup vs baseline: 8.5894x; 1.1607x over previous
#include <cuda_runtime.h>
#include <cuda_fp16.h>
#include <math.h>
#include <stdint.h>

// ---------------- problem constants ----------------
#define T_DIM   64
#define HW_DIM  729
#define M_TRK   512
#define DM      1152
#define NH      8
#define DH      144
#define MQ      (T_DIM * M_TRK)    // 32768
#define MK      (T_DIM * HW_DIM)   // 46656

// ---------------- device scratch ----------------
__device__ __half g_Qg[(size_t)MQ * DM];   // Q gemm out (fp16)
__device__ __half g_Kg[(size_t)MK * DM];   // K gemm out (fp16)
__device__ __half g_TTh[(size_t)MQ * DM];  // track_tokens fp16
__device__ __half g_Fh[(size_t)MK * DM];   // features fp16 (GEMM A and attention V)
__device__ __half g_Wh[(size_t)DM * DM];   // weight fp16, transposed [N,K]
__device__ __half g_Qh[(size_t)MQ * DM];   // LN'd Q fp16
__device__ __half g_Kh[(size_t)MK * DM];   // LN'd+RoPE'd K fp16
__device__ __half g_Sh[(size_t)MQ * DM];   // attention out fp16
__device__ float2 g_rtab[(size_t)HW_DIM * 576];  // per-position (cos,sin)

__device__ __forceinline__ uint32_t smem_u32(const void* p) {
    uint32_t a;
    asm("{ .reg .u64 t; cvta.to.shared.u64 t, %1; cvt.u32.u64 %0, t; }" : "=r"(a) : "l"(p));
    return a;
}
__device__ __forceinline__ void cp16(uint32_t dst, const void* src) {
    asm volatile("cp.async.cg.shared.global [%0], [%1], 16;" :: "r"(dst), "l"(src));
}
__device__ __forceinline__ void ldm4(uint32_t addr, uint32_t* r) {
    asm volatile("ldmatrix.sync.aligned.m8n8.x4.shared.b16 {%0,%1,%2,%3}, [%4];"
                 : "=r"(r[0]), "=r"(r[1]), "=r"(r[2]), "=r"(r[3])
                 : "r"(addr) : "memory");
}
__device__ __forceinline__ void ldm4t(uint32_t addr, uint32_t* r) {
    asm volatile("ldmatrix.sync.aligned.m8n8.x4.trans.shared.b16 {%0,%1,%2,%3}, [%4];"
                 : "=r"(r[0]), "=r"(r[1]), "=r"(r[2]), "=r"(r[3])
                 : "r"(addr) : "memory");
}
__device__ __forceinline__ void mma_f16(float* d, const uint32_t* a,
                                        uint32_t b0, uint32_t b1) {
    asm volatile(
        "mma.sync.aligned.m16n8k16.row.col.f32.f16.f16.f32 "
        "{%0,%1,%2,%3}, {%4,%5,%6,%7}, {%8,%9}, {%0,%1,%2,%3};"
        : "+f"(d[0]), "+f"(d[1]), "+f"(d[2]), "+f"(d[3])
        : "r"(a[0]), "r"(a[1]), "r"(a[2]), "r"(a[3]), "r"(b0), "r"(b1));
}
__device__ __forceinline__ uint32_t pack_h2(float a, float b) {
    __half2 h = __floats2half2_rn(a, b);
    return *(uint32_t*)&h;
}

// ================= fp32 -> fp16 convert ======================================
__global__ __launch_bounds__(256)
void f32_to_f16_kernel(const float* __restrict__ X, __half* __restrict__ O, long n4)
{
    long i = (long)blockIdx.x * blockDim.x + threadIdx.x;
    long stride = (long)gridDim.x * blockDim.x;
    for (; i < n4; i += stride) {
        float4 v = ((const float4*)X)[i];
        ((__half2*)O)[2*i]   = __floats2half2_rn(v.x, v.y);
        ((__half2*)O)[2*i+1] = __floats2half2_rn(v.z, v.w);
    }
}

// ============ weight fp16 + transpose: W[K,N] fp32 -> Ht [N,K] fp16 ==========
__global__ __launch_bounds__(256)
void wt_f16_kernel(const float* __restrict__ W, __half* __restrict__ Ht)
{
    __shared__ float tile[32][33];
    int tx = threadIdx.x & 31, ty = threadIdx.x >> 5;
    int nb = blockIdx.x * 32, kb = blockIdx.y * 32;
    #pragma unroll
    for (int r = ty; r < 32; r += 8)
        tile[r][tx] = W[(size_t)(kb + r) * DM + nb + tx];
    __syncthreads();
    #pragma unroll
    for (int r = ty; r < 32; r += 8)
        Ht[(size_t)(nb + r) * DM + kb + tx] = __float2half_rn(tile[tx][r]);
}

// ================= RoPE cos/sin table ========================================
__global__ __launch_bounds__(256)
void rope_tab_kernel(const float* __restrict__ fpos)
{
    const int n = blockIdx.x;
    const float px = fpos[2 * n];
    const float py = fpos[2 * n + 1];
    const float TS = -9.210340371976184f / 288.0f;
    for (int p = threadIdx.x; p < 576; p += 256) {
        int q = (p < 288) ? p : (p - 288);
        float theta = expf((float)q * TS);
        float ang = ((p < 288) ? px : py) * theta;
        float c, s;
        sincosf(ang, &s, &c);
        g_rtab[(size_t)n * 576 + p] = make_float2(c, s);
    }
}

// =================== mma.sync fp16 GEMM, BK=64, XOR swizzle ==================
// C[M,1152] = A @ B; A fp16 row-major [M,K], BhT fp16 [N,K].
// BM=128, BN=128, BK=64; 4 warps (2M x 2N), warp tile 64x64.
#define GTB 16384
#define GSTG (2 * GTB)
#define GNST 3
#define GEMM_SMEM (GNST * GSTG)       // 98304
#define KC2 18

template <typename TO>
__global__ __launch_bounds__(128)
void gemm_mma_f16(const __half* __restrict__ A, const __half* __restrict__ BhT,
                  TO* __restrict__ C, int M)
{
    extern __shared__ char dsm[];
    const int tid  = threadIdx.x;
    const int lane = tid & 31;
    const int wid  = tid >> 5;
    const int wm   = wid & 1;
    const int wn   = wid >> 1;
    const int n0   = blockIdx.x * 128;
    const int m0   = blockIdx.y * 128;

    uint32_t sb = smem_u32(dsm);
    const char* srcbase[2] = { (const char*)A, (const char*)BhT };

    float acc[4][8][4];
    #pragma unroll
    for (int i = 0; i < 4; i++)
        #pragma unroll
        for (int j = 0; j < 8; j++)
            #pragma unroll
            for (int q = 0; q < 4; q++) acc[i][j][q] = 0.f;

    auto load_stage = [&](int stage, int chunk) {
        uint32_t stb = sb + (uint32_t)stage * (uint32_t)GSTG;
        #pragma unroll
        for (int it = 0; it < 16; it++) {
            int flat = tid + it * 128;
            int t2 = flat >> 10;
            int r  = (flat >> 3) & 127;
            int c4 = flat & 7;
            int grow;
            if (t2 == 0) { grow = m0 + r; if (grow > M - 1) grow = M - 1; }
            else         { grow = n0 + r; }
            const char* src = srcbase[t2] + (size_t)grow * (DM * 2)
                              + (size_t)chunk * 128 + c4 * 16;
            uint32_t dst = stb + (uint32_t)t2 * (uint32_t)GTB
                           + (uint32_t)r * 128u + (uint32_t)((c4 ^ (r & 7)) << 4);
            cp16(dst, src);
        }
        asm volatile("cp.async.commit_group;" ::: "memory");
    };

    load_stage(0, 0);
    load_stage(1, 1);

    uint32_t xoff[4];
    #pragma unroll
    for (int kc = 0; kc < 4; kc++)
        xoff[kc] = (uint32_t)(((2 * kc + (lane >> 4)) ^ (lane & 7)) << 4);
    uint32_t aRow[4], bRow[4];
    #pragma unroll
    for (int i = 0; i < 4; i++) {
        aRow[i] = (uint32_t)(wm * 64 + i * 16 + (lane & 15)) * 128u;
        bRow[i] = (uint32_t)(wn * 64 + i * 16 + (lane & 15)) * 128u;
    }

    for (int c = 0; c < KC2; c++) {
        const int s = c % GNST;
        if (c < KC2 - 1) asm volatile("cp.async.wait_group 1;" ::: "memory");
        else             asm volatile("cp.async.wait_group 0;" ::: "memory");
        __syncthreads();

        if (c + 2 < KC2) load_stage((c + 2) % GNST, c + 2);

        uint32_t stb = sb + (uint32_t)s * (uint32_t)GSTG;
        #pragma unroll
        for (int kc = 0; kc < 4; kc++) {
            uint32_t ah[4][4], bh[4][4];
            #pragma unroll
            for (int a = 0; a < 4; a++)
                ldm4(stb + aRow[a] + xoff[kc], ah[a]);
            #pragma unroll
            for (int b = 0; b < 4; b++)
                ldm4(stb + GTB + bRow[b] + xoff[kc], bh[b]);
            #pragma unroll
            for (int am = 0; am < 4; am++) {
                #pragma unroll
                for (int bt = 0; bt < 4; bt++) {
                    mma_f16(acc[am][2*bt],   ah[am], bh[bt][0], bh[bt][2]);
                    mma_f16(acc[am][2*bt+1], ah[am], bh[bt][1], bh[bt][3]);
                }
            }
        }
    }

    #pragma unroll
    for (int am = 0; am < 4; am++) {
        int m = m0 + wm * 64 + am * 16 + (lane >> 2);
        #pragma unroll
        for (int bt = 0; bt < 8; bt++) {
            int n = n0 + wn * 64 + bt * 8 + (lane & 3) * 2;
            if (sizeof(TO) == 4) {
                if (m < M)
                    *(float2*)((float*)C + (size_t)m * DM + n) =
                        make_float2(acc[am][bt][0], acc[am][bt][1]);
                if (m + 8 < M)
                    *(float2*)((float*)C + (size_t)(m + 8) * DM + n) =
                        make_float2(acc[am][bt][2], acc[am][bt][3]);
            } else {
                if (m < M)
                    *(__half2*)((__half*)C + (size_t)m * DM + n) =
                        __floats2half2_rn(acc[am][bt][0], acc[am][bt][1]);
                if (m + 8 < M)
                    *(__half2*)((__half*)C + (size_t)(m + 8) * DM + n) =
                        __floats2half2_rn(acc[am][bt][2], acc[am][bt][3]);
            }
        }
    }
}

// ---------------- LayerNorm helpers (fp32 smem buffer) -----------------------
__device__ __forceinline__ void block_ln_stats(const float* x, float& mu, float& inv)
{
    __shared__ float red[18];
    float s = 0.f, ss = 0.f;
    for (int i = threadIdx.x; i < DM; i += 256) {
        float v = x[i];
        s += v; ss += v * v;
    }
    #pragma unroll
    for (int o = 16; o; o >>= 1) {
        s  += __shfl_down_sync(0xffffffffu, s, o);
        ss += __shfl_down_sync(0xffffffffu, ss, o);
    }
    int wid = threadIdx.x >> 5, lane = threadIdx.x & 31;
    if (lane == 0) { red[wid] = s; red[8 + wid] = ss; }
    __syncthreads();
    if (threadIdx.x == 0) {
        float S = 0.f, SS = 0.f;
        #pragma unroll
        for (int i = 0; i < 8; i++) { S += red[i]; SS += red[8 + i]; }
        red[16] = S; red[17] = SS;
    }
    __syncthreads();
    mu  = red[16] * (1.f / DM);
    float var = red[17] * (1.f / DM) - mu * mu;
    inv = rsqrtf(var + 1e-6f);
}

// LN(Q): fp16 in -> fp16 out
__global__ __launch_bounds__(256)
void ln_f16_kernel(const __half* __restrict__ X, const float* __restrict__ w,
                   __half* __restrict__ O)
{
    __shared__ float xs[DM];
    const __half2* x2 = (const __half2*)(X + (size_t)blockIdx.x * DM);
    for (int i = threadIdx.x; i < DM / 2; i += 256) {
        __half2 v = x2[i];
        xs[2*i]   = __low2float(v);
        xs[2*i+1] = __high2float(v);
    }
    __syncthreads();
    float mu, inv;
    block_ln_stats(xs, mu, inv);
    __half2* o2 = (__half2*)(O + (size_t)blockIdx.x * DM);
    for (int i = threadIdx.x; i < DM / 2; i += 256)
        o2[i] = __floats2half2_rn((xs[2*i]   - mu) * inv * w[2*i],
                                  (xs[2*i+1] - mu) * inv * w[2*i+1]);
}

// RoPE (table) + LN(K): fp16 in -> fp16 out
__global__ __launch_bounds__(256)
void rope_ln_f16_kernel(const __half* __restrict__ X, const float* __restrict__ w,
                        __half* __restrict__ Oh)
{
    __shared__ float xs[DM];
    const int row = blockIdx.x;
    const int n = row % HW_DIM;
    const __half2* x2 = (const __half2*)(X + (size_t)row * DM);
    const float2* rt = g_rtab + (size_t)n * 576;
    for (int p = threadIdx.x; p < 576; p += 256) {
        float2 cs = rt[p];
        int q = (p < 288) ? p : (p - 288);
        int h2i = (p < 288) ? q : (288 + q);    // pair (2q,2q+1) or (576+2q, 576+2q+1)
        __half2 v = x2[h2i];
        float a = __low2float(v), b = __high2float(v);
        xs[2*h2i]   = a * cs.x - b * cs.y;
        xs[2*h2i+1] = a * cs.y + b * cs.x;
    }
    __syncthreads();
    float mu, inv;
    block_ln_stats(xs, mu, inv);
    __half2* o2 = (__half2*)(Oh + (size_t)row * DM);
    for (int i = threadIdx.x; i < DM / 2; i += 256)
        o2[i] = __floats2half2_rn((xs[2*i]   - mu) * inv * w[2*i],
                                  (xs[2*i+1] - mu) * inv * w[2*i+1]);
}

// ---------------- tensor-core fused attention (3-stage, single fp16 K) -------
#define APITCH 304
#define ATSZ   (64 * APITCH)
#define ASTG   (2 * ATSZ)              // Kh, Vh
#define ANST   3
#define AKPOS  (ANST * ASTG)           // 116736
#define ATTN_SMEM (AKPOS + ANST * 512) // 118272

__global__ __launch_bounds__(256, 1)
void attn_mma_kernel(const __half* __restrict__ Qh, const __half* __restrict__ Kh,
                     const __half* __restrict__ Vh,
                     const float* __restrict__ tracks, const float* __restrict__ fpos,
                     __half* __restrict__ Sh)
{
    extern __shared__ char sm[];
    uint32_t sb = smem_u32(sm);
    const int tid  = threadIdx.x;
    const int lane = tid & 31;
    const int w    = tid >> 5;
    const int gid  = lane >> 2;
    const int tig  = lane & 3;
    const int m0   = blockIdx.x * 128;
    const int h    = blockIdx.y;
    const int t    = blockIdx.z;

    const char* qbase  = (const char*)(Qh + ((size_t)t * M_TRK + m0) * DM + h * DH);
    const char* khbase = (const char*)(Kh + (size_t)t * HW_DIM * DM + h * DH);
    const char* vbase  = (const char*)(Vh + (size_t)t * HW_DIM * DM + h * DH);

    float2 qp0 = *(const float2*)(tracks + ((size_t)t * M_TRK + m0 + w * 16 + gid) * 2);
    float2 qp1 = *(const float2*)(tracks + ((size_t)t * M_TRK + m0 + w * 16 + gid + 8) * 2);

    #pragma unroll
    for (int i = 0; i < 9; i++) {
        int c = tid + i * 256;
        int row = c / 18, ch = c % 18;
        cp16(sb + row * APITCH + ch * 16, qbase + (size_t)row * (DM * 2) + ch * 16);
    }
    asm volatile("cp.async.commit_group;" ::: "memory");
    asm volatile("cp.async.wait_group 0;" ::: "memory");
    __syncthreads();

    uint32_t qf[9][4];
    {
        uint32_t qa = sb + (uint32_t)(w * 16 + (lane & 15)) * APITCH + (uint32_t)(lane >> 4) * 16u;
        #pragma unroll
        for (int kc = 0; kc < 9; kc++) ldm4(qa + kc * 32, qf[kc]);
    }
    __syncthreads();

    auto load_tile = [&](int st, int kt) {
        int k0 = kt * 64;
        uint32_t stb = sb + (uint32_t)st * (uint32_t)ASTG;
        #pragma unroll
        for (int i = 0; i < 9; i++) {
            int c = tid + i * 256;
            if (c < 2304) {
                int buf = c / 1152, rem = c % 1152;
                int row = rem / 18, ch = rem % 18;
                int krow = k0 + row; if (krow > HW_DIM - 1) krow = HW_DIM - 1;
                const char* src = (buf == 0) ? khbase : vbase;
                cp16(stb + (uint32_t)buf * (uint32_t)ATSZ + (uint32_t)row * APITCH + (uint32_t)ch * 16u,
                     src + (size_t)krow * (DM * 2) + ch * 16);
            }
        }
        asm volatile("cp.async.commit_group;" ::: "memory");
        if (tid < 64) {
            int kr = k0 + tid; if (kr > HW_DIM - 1) kr = HW_DIM - 1;
            float2 v = *(const float2*)(fpos + (size_t)kr * 2);
            *(float2*)(sm + AKPOS + st * 512 + tid * 8) = v;
        }
    };

    load_tile(0, 0);
    load_tile(1, 1);

    float m_0 = -1e30f, m_1 = -1e30f, l_0 = 0.f, l_1 = 0.f;
    float oacc[18][4];
    #pragma unroll
    for (int a = 0; a < 18; a++)
        #pragma unroll
        for (int q = 0; q < 4; q++) oacc[a][q] = 0.f;

    const int NT = (HW_DIM + 63) / 64;   // 12
    for (int kt = 0; kt < NT; kt++) {
        const int st = kt % ANST;
        const int k0 = kt * 64;
        const int cnt = min(64, HW_DIM - k0);
        if (kt < NT - 1) asm volatile("cp.async.wait_group 1;" ::: "memory");
        else             asm volatile("cp.async.wait_group 0;" ::: "memory");
        __syncthreads();

        if (kt + 2 < NT) load_tile((kt + 2) % ANST, kt + 2);

        uint32_t stb = sb + (uint32_t)st * (uint32_t)ASTG;
        uint32_t lrow = (uint32_t)(lane & 15) * APITCH + (uint32_t)(lane >> 4) * 16u;
        uint32_t khb = stb + lrow;
        uint32_t vhb = stb + ATSZ + lrow;

        float sacc[8][4];
        #pragma unroll
        for (int a = 0; a < 8; a++)
            #pragma unroll
            for (int q = 0; q < 4; q++) sacc[a][q] = 0.f;

        #pragma unroll
        for (int kc = 0; kc < 9; kc++) {
            uint32_t bh[4][4];
            #pragma unroll
            for (int g = 0; g < 4; g++)
                ldm4(khb + g * (16 * APITCH) + kc * 32, bh[g]);
            #pragma unroll
            for (int g = 0; g < 4; g++) {
                mma_f16(sacc[2*g],   qf[kc], bh[g][0], bh[g][2]);
                mma_f16(sacc[2*g+1], qf[kc], bh[g][1], bh[g][3]);
            }
        }

        const float2* kp = (const float2*)(sm + AKPOS + st * 512);
        float mn0 = m_0, mn1 = m_1;
        #pragma unroll
        for (int a = 0; a < 8; a++) {
            int c0 = a * 8 + tig * 2;
            float2 ka = kp[c0];
            float2 kb = kp[c0 + 1];
            float dxa0 = qp0.x - ka.x, dya0 = qp0.y - ka.y;
            float dxb0 = qp0.x - kb.x, dyb0 = qp0.y - kb.y;
            float dxa1 = qp1.x - ka.x, dya1 = qp1.y - ka.y;
            float dxb1 = qp1.x - kb.x, dyb1 = qp1.y - kb.y;
            bool va = (c0 < cnt), vb = (c0 + 1 < cnt);
            sacc[a][0] = va ? sacc[a][0] * (1.f/12.f) - (dxa0*dxa0 + dya0*dya0) * 0.125f : -1e30f;
            sacc[a][1] = vb ? sacc[a][1] * (1.f/12.f) - (dxb0*dxb0 + dyb0*dyb0) * 0.125f : -1e30f;
            sacc[a][2] = va ? sacc[a][2] * (1.f/12.f) - (dxa1*dxa1 + dya1*dya1) * 0.125f : -1e30f;
            sacc[a][3] = vb ? sacc[a][3] * (1.f/12.f) - (dxb1*dxb1 + dyb1*dyb1) * 0.125f : -1e30f;
            mn0 = fmaxf(mn0, fmaxf(sacc[a][0], sacc[a][1]));
            mn1 = fmaxf(mn1, fmaxf(sacc[a][2], sacc[a][3]));
        }
        mn0 = fmaxf(mn0, __shfl_xor_sync(0xffffffffu, mn0, 1));
        mn0 = fmaxf(mn0, __shfl_xor_sync(0xffffffffu, mn0, 2));
        mn1 = fmaxf(mn1, __shfl_xor_sync(0xffffffffu, mn1, 1));
        mn1 = fmaxf(mn1, __shfl_xor_sync(0xffffffffu, mn1, 2));
        float corr0 = __expf(m_0 - mn0);
        float corr1 = __expf(m_1 - mn1);
        m_0 = mn0; m_1 = mn1;
        l_0 *= corr0; l_1 *= corr1;
        #pragma unroll
        for (int a = 0; a < 18; a++) {
            oacc[a][0] *= corr0; oacc[a][1] *= corr0;
            oacc[a][2] *= corr1; oacc[a][3] *= corr1;
        }
        #pragma unroll
        for (int a = 0; a < 8; a++) {
            float p0 = __expf(sacc[a][0] - m_0);
            float p1 = __expf(sacc[a][1] - m_0);
            float p2 = __expf(sacc[a][2] - m_1);
            float p3 = __expf(sacc[a][3] - m_1);
            l_0 += p0 + p1; l_1 += p2 + p3;
            sacc[a][0] = p0; sacc[a][1] = p1; sacc[a][2] = p2; sacc[a][3] = p3;
        }

        #pragma unroll
        for (int kc4 = 0; kc4 < 4; kc4++) {
            uint32_t pa[4];
            pa[0] = pack_h2(sacc[2*kc4][0],   sacc[2*kc4][1]);
            pa[1] = pack_h2(sacc[2*kc4][2],   sacc[2*kc4][3]);
            pa[2] = pack_h2(sacc[2*kc4+1][0], sacc[2*kc4+1][1]);
            pa[3] = pack_h2(sacc[2*kc4+1][2], sacc[2*kc4+1][3]);
            #pragma unroll
            for (int dp = 0; dp < 9; dp++) {
                uint32_t vf[4];
                ldm4t(vhb + kc4 * (16 * APITCH) + dp * 32, vf);
                mma_f16(oacc[2*dp],   pa, vf[0], vf[1]);
                mma_f16(oacc[2*dp+1], pa, vf[2], vf[3]);
            }
        }
    }

    l_0 += __shfl_xor_sync(0xffffffffu, l_0, 1);
    l_0 += __shfl_xor_sync(0xffffffffu, l_0, 2);
    l_1 += __shfl_xor_sync(0xffffffffu, l_1, 1);
    l_1 += __shfl_xor_sync(0xffffffffu, l_1, 2);
    float inv0 = 1.f / l_0, inv1 = 1.f / l_1;

    size_t row0 = (size_t)t * M_TRK + m0 + w * 16 + gid;
    #pragma unroll
    for (int a = 0; a < 18; a++) {
        int col = h * DH + a * 8 + tig * 2;
        *(__half2*)(Sh + row0 * DM + col) =
            __floats2half2_rn(oacc[a][0] * inv0, oacc[a][1] * inv0);
        *(__half2*)(Sh + (row0 + 8) * DM + col) =
            __floats2half2_rn(oacc[a][2] * inv1, oacc[a][3] * inv1);
    }
}

// ---------------- launch ----------------
extern "C" void kernel_launch(void* const* d_in, const int* in_sizes, int n_in,
                              void* d_out, int out_size)
{
    const float* features    = (const float*)d_in[0];
    const float* tracks      = (const float*)d_in[1];
    const float* track_toks  = (const float*)d_in[2];
    const float* fpos        = (const float*)d_in[3];
    const float* W_q         = (const float*)d_in[4];
    const float* W_k         = (const float*)d_in[5];
    const float* q_norm_w    = (const float*)d_in[6];
    const float* k_norm_w    = (const float*)d_in[7];
    const float* out_proj_w  = (const float*)d_in[8];
    float* out = (float*)d_out;

    __half *gQg, *gKg, *gTTh, *gFh, *gWh, *gQh, *gKh, *gSh;
    cudaGetSymbolAddress((void**)&gQg, g_Qg);
    cudaGetSymbolAddress((void**)&gKg, g_Kg);
    cudaGetSymbolAddress((void**)&gTTh, g_TTh);
    cudaGetSymbolAddress((void**)&gFh, g_Fh);
    cudaGetSymbolAddress((void**)&gWh, g_Wh);
    cudaGetSymbolAddress((void**)&gQh, g_Qh);
    cudaGetSymbolAddress((void**)&gKh, g_Kh);
    cudaGetSymbolAddress((void**)&gSh, g_Sh);

    cudaFuncSetAttribute(gemm_mma_f16<float>,
                         cudaFuncAttributeMaxDynamicSharedMemorySize, GEMM_SMEM);
    cudaFuncSetAttribute(gemm_mma_f16<__half>,
                         cudaFuncAttributeMaxDynamicSharedMemorySize, GEMM_SMEM);
    cudaFuncSetAttribute(attn_mma_kernel,
                         cudaFuncAttributeMaxDynamicSharedMemorySize, ATTN_SMEM);

    dim3 wtg(DM / 32, DM / 32);

    // ---- fp16 conversions + RoPE table ----
    f32_to_f16_kernel<<<4096, 256>>>(track_toks, gTTh, (long)MQ * DM / 4);
    f32_to_f16_kernel<<<4096, 256>>>(features, gFh, (long)MK * DM / 4);
    rope_tab_kernel<<<HW_DIM, 256>>>(fpos);

    // ---- Q = track_tokens @ W_q (fp16 out) ----
    wt_f16_kernel<<<wtg, 256>>>(W_q, gWh);
    {
        dim3 g(DM / 128, (MQ + 127) / 128);
        gemm_mma_f16<__half><<<g, 128, GEMM_SMEM>>>(gTTh, gWh, gQg, MQ);
    }

    // ---- K = features @ W_k (fp16 out) ----
    wt_f16_kernel<<<wtg, 256>>>(W_k, gWh);
    {
        dim3 g(DM / 128, (MK + 127) / 128);
        gemm_mma_f16<__half><<<g, 128, GEMM_SMEM>>>(gFh, gWh, gKg, MK);
    }

    // ---- LN(Q)->fp16, RoPE+LN(K)->fp16 ----
    ln_f16_kernel<<<MQ, 256>>>(gQg, q_norm_w, gQh);
    rope_ln_f16_kernel<<<MK, 256>>>(gKg, k_norm_w, gKh);

    // ---- fused tensor-core attention (V = features fp16) ----
    {
        dim3 g(M_TRK / 128, NH, T_DIM);
        attn_mma_kernel<<<g, 256, ATTN_SMEM>>>(gQh, gKh, gFh, tracks, fpos, gSh);
    }

    // ---- out = sampled @ out_proj_w (fp32 out) ----
    wt_f16_kernel<<<wtg, 256>>>(out_proj_w, gWh);
    {
        dim3 g(DM / 128, (MQ + 127) / 128);
        gemm_mma_f16<float><<<g, 128, GEMM_SMEM>>>(gSh, gWh, out, MQ);
    }
}

// round 11
// speedup vs baseline: 8.7630x; 1.0202x over previous
#include <cuda_runtime.h>
#include <cuda_fp16.h>
#include <math.h>
#include <stdint.h>

// ---------------- problem constants ----------------
#define T_DIM   64
#define HW_DIM  729
#define M_TRK   512
#define DM      1152
#define NH      8
#define DH      144
#define MQ      (T_DIM * M_TRK)    // 32768
#define MK      (T_DIM * HW_DIM)   // 46656

// ---------------- device scratch ----------------
__device__ __half g_Qg[(size_t)MQ * DM];   // Q gemm out (fp16)
__device__ __half g_Kg[(size_t)MK * DM];   // K gemm out (fp16)
__device__ __half g_TTh[(size_t)MQ * DM];  // track_tokens fp16
__device__ __half g_Fh[(size_t)MK * DM];   // features fp16 (GEMM A and attention V)
__device__ __half g_Wh[(size_t)DM * DM];   // weight fp16, transposed [N,K]
__device__ __half g_Qh[(size_t)MQ * DM];   // LN'd Q fp16
__device__ __half g_Kh[(size_t)MK * DM];   // LN'd+RoPE'd K fp16
__device__ __half g_Sh[(size_t)MQ * DM];   // attention out fp16
__device__ float2 g_rtab[(size_t)HW_DIM * 576];  // per-position (cos,sin)

__device__ __forceinline__ uint32_t smem_u32(const void* p) {
    uint32_t a;
    asm("{ .reg .u64 t; cvta.to.shared.u64 t, %1; cvt.u32.u64 %0, t; }" : "=r"(a) : "l"(p));
    return a;
}
__device__ __forceinline__ void cp16(uint32_t dst, const void* src) {
    asm volatile("cp.async.cg.shared.global [%0], [%1], 16;" :: "r"(dst), "l"(src));
}
__device__ __forceinline__ void ldm4(uint32_t addr, uint32_t* r) {
    asm volatile("ldmatrix.sync.aligned.m8n8.x4.shared.b16 {%0,%1,%2,%3}, [%4];"
                 : "=r"(r[0]), "=r"(r[1]), "=r"(r[2]), "=r"(r[3])
                 : "r"(addr) : "memory");
}
__device__ __forceinline__ void ldm4t(uint32_t addr, uint32_t* r) {
    asm volatile("ldmatrix.sync.aligned.m8n8.x4.trans.shared.b16 {%0,%1,%2,%3}, [%4];"
                 : "=r"(r[0]), "=r"(r[1]), "=r"(r[2]), "=r"(r[3])
                 : "r"(addr) : "memory");
}
__device__ __forceinline__ void mma_f16(float* d, const uint32_t* a,
                                        uint32_t b0, uint32_t b1) {
    asm volatile(
        "mma.sync.aligned.m16n8k16.row.col.f32.f16.f16.f32 "
        "{%0,%1,%2,%3}, {%4,%5,%6,%7}, {%8,%9}, {%0,%1,%2,%3};"
        : "+f"(d[0]), "+f"(d[1]), "+f"(d[2]), "+f"(d[3])
        : "r"(a[0]), "r"(a[1]), "r"(a[2]), "r"(a[3]), "r"(b0), "r"(b1));
}
__device__ __forceinline__ uint32_t pack_h2(float a, float b) {
    __half2 h = __floats2half2_rn(a, b);
    return *(uint32_t*)&h;
}

// ================= fp32 -> fp16 convert ======================================
__global__ __launch_bounds__(256)
void f32_to_f16_kernel(const float* __restrict__ X, __half* __restrict__ O, long n4)
{
    long i = (long)blockIdx.x * blockDim.x + threadIdx.x;
    long stride = (long)gridDim.x * blockDim.x;
    for (; i < n4; i += stride) {
        float4 v = ((const float4*)X)[i];
        ((__half2*)O)[2*i]   = __floats2half2_rn(v.x, v.y);
        ((__half2*)O)[2*i+1] = __floats2half2_rn(v.z, v.w);
    }
}

// ============ weight fp16 + transpose: W[K,N] fp32 -> Ht [N,K] fp16 ==========
__global__ __launch_bounds__(256)
void wt_f16_kernel(const float* __restrict__ W, __half* __restrict__ Ht)
{
    __shared__ float tile[32][33];
    int tx = threadIdx.x & 31, ty = threadIdx.x >> 5;
    int nb = blockIdx.x * 32, kb = blockIdx.y * 32;
    #pragma unroll
    for (int r = ty; r < 32; r += 8)
        tile[r][tx] = W[(size_t)(kb + r) * DM + nb + tx];
    __syncthreads();
    #pragma unroll
    for (int r = ty; r < 32; r += 8)
        Ht[(size_t)(nb + r) * DM + kb + tx] = __float2half_rn(tile[tx][r]);
}

// ================= RoPE cos/sin table ========================================
__global__ __launch_bounds__(256)
void rope_tab_kernel(const float* __restrict__ fpos)
{
    const int n = blockIdx.x;
    const float px = fpos[2 * n];
    const float py = fpos[2 * n + 1];
    const float TS = -9.210340371976184f / 288.0f;
    for (int p = threadIdx.x; p < 576; p += 256) {
        int q = (p < 288) ? p : (p - 288);
        float theta = expf((float)q * TS);
        float ang = ((p < 288) ? px : py) * theta;
        float c, s;
        sincosf(ang, &s, &c);
        g_rtab[(size_t)n * 576 + p] = make_float2(c, s);
    }
}

// =================== mma.sync fp16 GEMM, BK=64, XOR swizzle, SW-pipelined ====
#define GTB 16384
#define GSTG (2 * GTB)
#define GNST 3
#define GEMM_SMEM (GNST * GSTG)       // 98304
#define KC2 18

template <typename TO>
__global__ __launch_bounds__(128)
void gemm_mma_f16(const __half* __restrict__ A, const __half* __restrict__ BhT,
                  TO* __restrict__ C, int M)
{
    extern __shared__ char dsm[];
    const int tid  = threadIdx.x;
    const int lane = tid & 31;
    const int wid  = tid >> 5;
    const int wm   = wid & 1;
    const int wn   = wid >> 1;
    const int n0   = blockIdx.x * 128;
    const int m0   = blockIdx.y * 128;

    uint32_t sb = smem_u32(dsm);
    const char* srcbase[2] = { (const char*)A, (const char*)BhT };

    float acc[4][8][4];
    #pragma unroll
    for (int i = 0; i < 4; i++)
        #pragma unroll
        for (int j = 0; j < 8; j++)
            #pragma unroll
            for (int q = 0; q < 4; q++) acc[i][j][q] = 0.f;

    auto load_stage = [&](int stage, int chunk) {
        uint32_t stb = sb + (uint32_t)stage * (uint32_t)GSTG;
        #pragma unroll
        for (int it = 0; it < 16; it++) {
            int flat = tid + it * 128;
            int t2 = flat >> 10;
            int r  = (flat >> 3) & 127;
            int c4 = flat & 7;
            int grow;
            if (t2 == 0) { grow = m0 + r; if (grow > M - 1) grow = M - 1; }
            else         { grow = n0 + r; }
            const char* src = srcbase[t2] + (size_t)grow * (DM * 2)
                              + (size_t)chunk * 128 + c4 * 16;
            uint32_t dst = stb + (uint32_t)t2 * (uint32_t)GTB
                           + (uint32_t)r * 128u + (uint32_t)((c4 ^ (r & 7)) << 4);
            cp16(dst, src);
        }
        asm volatile("cp.async.commit_group;" ::: "memory");
    };

    load_stage(0, 0);
    load_stage(1, 1);

    uint32_t xoff[4];
    #pragma unroll
    for (int kc = 0; kc < 4; kc++)
        xoff[kc] = (uint32_t)(((2 * kc + (lane >> 4)) ^ (lane & 7)) << 4);
    uint32_t aRow[4], bRow[4];
    #pragma unroll
    for (int i = 0; i < 4; i++) {
        aRow[i] = (uint32_t)(wm * 64 + i * 16 + (lane & 15)) * 128u;
        bRow[i] = (uint32_t)(wn * 64 + i * 16 + (lane & 15)) * 128u;
    }

    uint32_t ah[2][4][4], bh[2][4][4];   // double-buffered fragments

    for (int c = 0; c < KC2; c++) {
        const int s = c % GNST;
        if (c < KC2 - 1) asm volatile("cp.async.wait_group 1;" ::: "memory");
        else             asm volatile("cp.async.wait_group 0;" ::: "memory");
        __syncthreads();

        if (c + 2 < KC2) load_stage((c + 2) % GNST, c + 2);

        uint32_t stb = sb + (uint32_t)s * (uint32_t)GSTG;

        // prime kc=0 fragments
        #pragma unroll
        for (int a = 0; a < 4; a++) ldm4(stb + aRow[a] + xoff[0], ah[0][a]);
        #pragma unroll
        for (int b = 0; b < 4; b++) ldm4(stb + GTB + bRow[b] + xoff[0], bh[0][b]);

        #pragma unroll
        for (int kc = 0; kc < 4; kc++) {
            const int cur = kc & 1, nxt = cur ^ 1;
            if (kc < 3) {   // prefetch kc+1 BEFORE issuing kc's MMAs
                #pragma unroll
                for (int a = 0; a < 4; a++) ldm4(stb + aRow[a] + xoff[kc+1], ah[nxt][a]);
                #pragma unroll
                for (int b = 0; b < 4; b++) ldm4(stb + GTB + bRow[b] + xoff[kc+1], bh[nxt][b]);
            }
            #pragma unroll
            for (int am = 0; am < 4; am++) {
                #pragma unroll
                for (int bt = 0; bt < 4; bt++) {
                    mma_f16(acc[am][2*bt],   ah[cur][am], bh[cur][bt][0], bh[cur][bt][2]);
                    mma_f16(acc[am][2*bt+1], ah[cur][am], bh[cur][bt][1], bh[cur][bt][3]);
                }
            }
        }
    }

    #pragma unroll
    for (int am = 0; am < 4; am++) {
        int m = m0 + wm * 64 + am * 16 + (lane >> 2);
        #pragma unroll
        for (int bt = 0; bt < 8; bt++) {
            int n = n0 + wn * 64 + bt * 8 + (lane & 3) * 2;
            if (sizeof(TO) == 4) {
                if (m < M)
                    *(float2*)((float*)C + (size_t)m * DM + n) =
                        make_float2(acc[am][bt][0], acc[am][bt][1]);
                if (m + 8 < M)
                    *(float2*)((float*)C + (size_t)(m + 8) * DM + n) =
                        make_float2(acc[am][bt][2], acc[am][bt][3]);
            } else {
                if (m < M)
                    *(__half2*)((__half*)C + (size_t)m * DM + n) =
                        __floats2half2_rn(acc[am][bt][0], acc[am][bt][1]);
                if (m + 8 < M)
                    *(__half2*)((__half*)C + (size_t)(m + 8) * DM + n) =
                        __floats2half2_rn(acc[am][bt][2], acc[am][bt][3]);
            }
        }
    }
}

// ---------------- LayerNorm helpers (fp32 smem buffer) -----------------------
__device__ __forceinline__ void block_ln_stats(const float* x, float& mu, float& inv)
{
    __shared__ float red[18];
    float s = 0.f, ss = 0.f;
    for (int i = threadIdx.x; i < DM; i += 256) {
        float v = x[i];
        s += v; ss += v * v;
    }
    #pragma unroll
    for (int o = 16; o; o >>= 1) {
        s  += __shfl_down_sync(0xffffffffu, s, o);
        ss += __shfl_down_sync(0xffffffffu, ss, o);
    }
    int wid = threadIdx.x >> 5, lane = threadIdx.x & 31;
    if (lane == 0) { red[wid] = s; red[8 + wid] = ss; }
    __syncthreads();
    if (threadIdx.x == 0) {
        float S = 0.f, SS = 0.f;
        #pragma unroll
        for (int i = 0; i < 8; i++) { S += red[i]; SS += red[8 + i]; }
        red[16] = S; red[17] = SS;
    }
    __syncthreads();
    mu  = red[16] * (1.f / DM);
    float var = red[17] * (1.f / DM) - mu * mu;
    inv = rsqrtf(var + 1e-6f);
}

// LN(Q): fp16 in -> fp16 out
__global__ __launch_bounds__(256)
void ln_f16_kernel(const __half* __restrict__ X, const float* __restrict__ w,
                   __half* __restrict__ O)
{
    __shared__ float xs[DM];
    const __half2* x2 = (const __half2*)(X + (size_t)blockIdx.x * DM);
    for (int i = threadIdx.x; i < DM / 2; i += 256) {
        __half2 v = x2[i];
        xs[2*i]   = __low2float(v);
        xs[2*i+1] = __high2float(v);
    }
    __syncthreads();
    float mu, inv;
    block_ln_stats(xs, mu, inv);
    __half2* o2 = (__half2*)(O + (size_t)blockIdx.x * DM);
    for (int i = threadIdx.x; i < DM / 2; i += 256)
        o2[i] = __floats2half2_rn((xs[2*i]   - mu) * inv * w[2*i],
                                  (xs[2*i+1] - mu) * inv * w[2*i+1]);
}

// RoPE (table) + LN(K): fp16 in -> fp16 out
__global__ __launch_bounds__(256)
void rope_ln_f16_kernel(const __half* __restrict__ X, const float* __restrict__ w,
                        __half* __restrict__ Oh)
{
    __shared__ float xs[DM];
    const int row = blockIdx.x;
    const int n = row % HW_DIM;
    const __half2* x2 = (const __half2*)(X + (size_t)row * DM);
    const float2* rt = g_rtab + (size_t)n * 576;
    for (int p = threadIdx.x; p < 576; p += 256) {
        float2 cs = rt[p];
        int q = (p < 288) ? p : (p - 288);
        int h2i = (p < 288) ? q : (288 + q);
        __half2 v = x2[h2i];
        float a = __low2float(v), b = __high2float(v);
        xs[2*h2i]   = a * cs.x - b * cs.y;
        xs[2*h2i+1] = a * cs.y + b * cs.x;
    }
    __syncthreads();
    float mu, inv;
    block_ln_stats(xs, mu, inv);
    __half2* o2 = (__half2*)(Oh + (size_t)row * DM);
    for (int i = threadIdx.x; i < DM / 2; i += 256)
        o2[i] = __floats2half2_rn((xs[2*i]   - mu) * inv * w[2*i],
                                  (xs[2*i+1] - mu) * inv * w[2*i+1]);
}

// ---------------- tensor-core fused attention (SW-pipelined) -----------------
#define APITCH 304
#define ATSZ   (64 * APITCH)
#define ASTG   (2 * ATSZ)              // Kh, Vh
#define ANST   3
#define AKPOS  (ANST * ASTG)           // 116736
#define ATTN_SMEM (AKPOS + ANST * 512) // 118272

__global__ __launch_bounds__(256, 1)
void attn_mma_kernel(const __half* __restrict__ Qh, const __half* __restrict__ Kh,
                     const __half* __restrict__ Vh,
                     const float* __restrict__ tracks, const float* __restrict__ fpos,
                     __half* __restrict__ Sh)
{
    extern __shared__ char sm[];
    uint32_t sb = smem_u32(sm);
    const int tid  = threadIdx.x;
    const int lane = tid & 31;
    const int w    = tid >> 5;
    const int gid  = lane >> 2;
    const int tig  = lane & 3;
    const int m0   = blockIdx.x * 128;
    const int h    = blockIdx.y;
    const int t    = blockIdx.z;

    const char* qbase  = (const char*)(Qh + ((size_t)t * M_TRK + m0) * DM + h * DH);
    const char* khbase = (const char*)(Kh + (size_t)t * HW_DIM * DM + h * DH);
    const char* vbase  = (const char*)(Vh + (size_t)t * HW_DIM * DM + h * DH);

    float2 qp0 = *(const float2*)(tracks + ((size_t)t * M_TRK + m0 + w * 16 + gid) * 2);
    float2 qp1 = *(const float2*)(tracks + ((size_t)t * M_TRK + m0 + w * 16 + gid + 8) * 2);

    #pragma unroll
    for (int i = 0; i < 9; i++) {
        int c = tid + i * 256;
        int row = c / 18, ch = c % 18;
        cp16(sb + row * APITCH + ch * 16, qbase + (size_t)row * (DM * 2) + ch * 16);
    }
    asm volatile("cp.async.commit_group;" ::: "memory");
    asm volatile("cp.async.wait_group 0;" ::: "memory");
    __syncthreads();

    uint32_t qf[9][4];
    {
        uint32_t qa = sb + (uint32_t)(w * 16 + (lane & 15)) * APITCH + (uint32_t)(lane >> 4) * 16u;
        #pragma unroll
        for (int kc = 0; kc < 9; kc++) ldm4(qa + kc * 32, qf[kc]);
    }
    __syncthreads();

    auto load_tile = [&](int st, int kt) {
        int k0 = kt * 64;
        uint32_t stb = sb + (uint32_t)st * (uint32_t)ASTG;
        #pragma unroll
        for (int i = 0; i < 9; i++) {
            int c = tid + i * 256;
            if (c < 2304) {
                int buf = c / 1152, rem = c % 1152;
                int row = rem / 18, ch = rem % 18;
                int krow = k0 + row; if (krow > HW_DIM - 1) krow = HW_DIM - 1;
                const char* src = (buf == 0) ? khbase : vbase;
                cp16(stb + (uint32_t)buf * (uint32_t)ATSZ + (uint32_t)row * APITCH + (uint32_t)ch * 16u,
                     src + (size_t)krow * (DM * 2) + ch * 16);
            }
        }
        asm volatile("cp.async.commit_group;" ::: "memory");
        if (tid < 64) {
            int kr = k0 + tid; if (kr > HW_DIM - 1) kr = HW_DIM - 1;
            float2 v = *(const float2*)(fpos + (size_t)kr * 2);
            *(float2*)(sm + AKPOS + st * 512 + tid * 8) = v;
        }
    };

    load_tile(0, 0);
    load_tile(1, 1);

    float m_0 = -1e30f, m_1 = -1e30f, l_0 = 0.f, l_1 = 0.f;
    float oacc[18][4];
    #pragma unroll
    for (int a = 0; a < 18; a++)
        #pragma unroll
        for (int q = 0; q < 4; q++) oacc[a][q] = 0.f;

    const int NT = (HW_DIM + 63) / 64;   // 12
    for (int kt = 0; kt < NT; kt++) {
        const int st = kt % ANST;
        const int k0 = kt * 64;
        const int cnt = min(64, HW_DIM - k0);
        if (kt < NT - 1) asm volatile("cp.async.wait_group 1;" ::: "memory");
        else             asm volatile("cp.async.wait_group 0;" ::: "memory");
        __syncthreads();

        if (kt + 2 < NT) load_tile((kt + 2) % ANST, kt + 2);

        uint32_t stb = sb + (uint32_t)st * (uint32_t)ASTG;
        uint32_t lrow = (uint32_t)(lane & 15) * APITCH + (uint32_t)(lane >> 4) * 16u;
        uint32_t khb = stb + lrow;
        uint32_t vhb = stb + ATSZ + lrow;

        float sacc[8][4];
        #pragma unroll
        for (int a = 0; a < 8; a++)
            #pragma unroll
            for (int q = 0; q < 4; q++) sacc[a][q] = 0.f;

        // ---- QK^T with fragment double-buffering
        uint32_t bhf[2][4][4];
        #pragma unroll
        for (int g = 0; g < 4; g++) ldm4(khb + g * (16 * APITCH), bhf[0][g]);
        #pragma unroll
        for (int kc = 0; kc < 9; kc++) {
            const int cur = kc & 1, nxt = cur ^ 1;
            if (kc < 8) {
                #pragma unroll
                for (int g = 0; g < 4; g++)
                    ldm4(khb + g * (16 * APITCH) + (kc + 1) * 32, bhf[nxt][g]);
            }
            #pragma unroll
            for (int g = 0; g < 4; g++) {
                mma_f16(sacc[2*g],   qf[kc], bhf[cur][g][0], bhf[cur][g][2]);
                mma_f16(sacc[2*g+1], qf[kc], bhf[cur][g][1], bhf[cur][g][3]);
            }
        }

        const float2* kp = (const float2*)(sm + AKPOS + st * 512);
        float mn0 = m_0, mn1 = m_1;
        #pragma unroll
        for (int a = 0; a < 8; a++) {
            int c0 = a * 8 + tig * 2;
            float2 ka = kp[c0];
            float2 kb = kp[c0 + 1];
            float dxa0 = qp0.x - ka.x, dya0 = qp0.y - ka.y;
            float dxb0 = qp0.x - kb.x, dyb0 = qp0.y - kb.y;
            float dxa1 = qp1.x - ka.x, dya1 = qp1.y - ka.y;
            float dxb1 = qp1.x - kb.x, dyb1 = qp1.y - kb.y;
            bool va = (c0 < cnt), vb = (c0 + 1 < cnt);
            sacc[a][0] = va ? sacc[a][0] * (1.f/12.f) - (dxa0*dxa0 + dya0*dya0) * 0.125f : -1e30f;
            sacc[a][1] = vb ? sacc[a][1] * (1.f/12.f) - (dxb0*dxb0 + dyb0*dyb0) * 0.125f : -1e30f;
            sacc[a][2] = va ? sacc[a][2] * (1.f/12.f) - (dxa1*dxa1 + dya1*dya1) * 0.125f : -1e30f;
            sacc[a][3] = vb ? sacc[a][3] * (1.f/12.f) - (dxb1*dxb1 + dyb1*dyb1) * 0.125f : -1e30f;
            mn0 = fmaxf(mn0, fmaxf(sacc[a][0], sacc[a][1]));
            mn1 = fmaxf(mn1, fmaxf(sacc[a][2], sacc[a][3]));
        }
        mn0 = fmaxf(mn0, __shfl_xor_sync(0xffffffffu, mn0, 1));
        mn0 = fmaxf(mn0, __shfl_xor_sync(0xffffffffu, mn0, 2));
        mn1 = fmaxf(mn1, __shfl_xor_sync(0xffffffffu, mn1, 1));
        mn1 = fmaxf(mn1, __shfl_xor_sync(0xffffffffu, mn1, 2));
        float corr0 = __expf(m_0 - mn0);
        float corr1 = __expf(m_1 - mn1);
        m_0 = mn0; m_1 = mn1;
        l_0 *= corr0; l_1 *= corr1;
        #pragma unroll
        for (int a = 0; a < 18; a++) {
            oacc[a][0] *= corr0; oacc[a][1] *= corr0;
            oacc[a][2] *= corr1; oacc[a][3] *= corr1;
        }
        #pragma unroll
        for (int a = 0; a < 8; a++) {
            float p0 = __expf(sacc[a][0] - m_0);
            float p1 = __expf(sacc[a][1] - m_0);
            float p2 = __expf(sacc[a][2] - m_1);
            float p3 = __expf(sacc[a][3] - m_1);
            l_0 += p0 + p1; l_1 += p2 + p3;
            sacc[a][0] = p0; sacc[a][1] = p1; sacc[a][2] = p2; sacc[a][3] = p3;
        }

        // ---- AV with vf double-buffering
        #pragma unroll
        for (int kc4 = 0; kc4 < 4; kc4++) {
            uint32_t pa[4];
            pa[0] = pack_h2(sacc[2*kc4][0],   sacc[2*kc4][1]);
            pa[1] = pack_h2(sacc[2*kc4][2],   sacc[2*kc4][3]);
            pa[2] = pack_h2(sacc[2*kc4+1][0], sacc[2*kc4+1][1]);
            pa[3] = pack_h2(sacc[2*kc4+1][2], sacc[2*kc4+1][3]);
            uint32_t vf[2][4];
            ldm4t(vhb + kc4 * (16 * APITCH), vf[0]);
            #pragma unroll
            for (int dp = 0; dp < 9; dp++) {
                const int cur = dp & 1, nxt = cur ^ 1;
                if (dp < 8)
                    ldm4t(vhb + kc4 * (16 * APITCH) + (dp + 1) * 32, vf[nxt]);
                mma_f16(oacc[2*dp],   pa, vf[cur][0], vf[cur][1]);
                mma_f16(oacc[2*dp+1], pa, vf[cur][2], vf[cur][3]);
            }
        }
    }

    l_0 += __shfl_xor_sync(0xffffffffu, l_0, 1);
    l_0 += __shfl_xor_sync(0xffffffffu, l_0, 2);
    l_1 += __shfl_xor_sync(0xffffffffu, l_1, 1);
    l_1 += __shfl_xor_sync(0xffffffffu, l_1, 2);
    float inv0 = 1.f / l_0, inv1 = 1.f / l_1;

    size_t row0 = (size_t)t * M_TRK + m0 + w * 16 + gid;
    #pragma unroll
    for (int a = 0; a < 18; a++) {
        int col = h * DH + a * 8 + tig * 2;
        *(__half2*)(Sh + row0 * DM + col) =
            __floats2half2_rn(oacc[a][0] * inv0, oacc[a][1] * inv0);
        *(__half2*)(Sh + (row0 + 8) * DM + col) =
            __floats2half2_rn(oacc[a][2] * inv1, oacc[a][3] * inv1);
    }
}

// ---------------- launch ----------------
extern "C" void kernel_launch(void* const* d_in, const int* in_sizes, int n_in,
                              void* d_out, int out_size)
{
    const float* features    = (const float*)d_in[0];
    const float* tracks      = (const float*)d_in[1];
    const float* track_toks  = (const float*)d_in[2];
    const float* fpos        = (const float*)d_in[3];
    const float* W_q         = (const float*)d_in[4];
    const float* W_k         = (const float*)d_in[5];
    const float* q_norm_w    = (const float*)d_in[6];
    const float* k_norm_w    = (const float*)d_in[7];
    const float* out_proj_w  = (const float*)d_in[8];
    float* out = (float*)d_out;

    __half *gQg, *gKg, *gTTh, *gFh, *gWh, *gQh, *gKh, *gSh;
    cudaGetSymbolAddress((void**)&gQg, g_Qg);
    cudaGetSymbolAddress((void**)&gKg, g_Kg);
    cudaGetSymbolAddress((void**)&gTTh, g_TTh);
    cudaGetSymbolAddress((void**)&gFh, g_Fh);
    cudaGetSymbolAddress((void**)&gWh, g_Wh);
    cudaGetSymbolAddress((void**)&gQh, g_Qh);
    cudaGetSymbolAddress((void**)&gKh, g_Kh);
    cudaGetSymbolAddress((void**)&gSh, g_Sh);

    cudaFuncSetAttribute(gemm_mma_f16<float>,
                         cudaFuncAttributeMaxDynamicSharedMemorySize, GEMM_SMEM);
    cudaFuncSetAttribute(gemm_mma_f16<__half>,
                         cudaFuncAttributeMaxDynamicSharedMemorySize, GEMM_SMEM);
    cudaFuncSetAttribute(attn_mma_kernel,
                         cudaFuncAttributeMaxDynamicSharedMemorySize, ATTN_SMEM);

    dim3 wtg(DM / 32, DM / 32);

    // ---- fp16 conversions + RoPE table ----
    f32_to_f16_kernel<<<4096, 256>>>(track_toks, gTTh, (long)MQ * DM / 4);
    f32_to_f16_kernel<<<4096, 256>>>(features, gFh, (long)MK * DM / 4);
    rope_tab_kernel<<<HW_DIM, 256>>>(fpos);

    // ---- Q = track_tokens @ W_q (fp16 out) ----
    wt_f16_kernel<<<wtg, 256>>>(W_q, gWh);
    {
        dim3 g(DM / 128, (MQ + 127) / 128);
        gemm_mma_f16<__half><<<g, 128, GEMM_SMEM>>>(gTTh, gWh, gQg, MQ);
    }

    // ---- K = features @ W_k (fp16 out) ----
    wt_f16_kernel<<<wtg, 256>>>(W_k, gWh);
    {
        dim3 g(DM / 128, (MK + 127) / 128);
        gemm_mma_f16<__half><<<g, 128, GEMM_SMEM>>>(gFh, gWh, gKg, MK);
    }

    // ---- LN(Q)->fp16, RoPE+LN(K)->fp16 ----
    ln_f16_kernel<<<MQ, 256>>>(gQg, q_norm_w, gQh);
    rope_ln_f16_kernel<<<MK, 256>>>(gKg, k_norm_w, gKh);

    // ---- fused tensor-core attention (V = features fp16) ----
    {
        dim3 g(M_TRK / 128, NH, T_DIM);
        attn_mma_kernel<<<g, 256, ATTN_SMEM>>>(gQh, gKh, gFh, tracks, fpos, gSh);
    }

    // ---- out = sampled @ out_proj_w (fp32 out) ----
    wt_f16_kernel<<<wtg, 256>>>(out_proj_w, gWh);
    {
        dim3 g(DM / 128, (MQ + 127) / 128);
        gemm_mma_f16<float><<<g, 128, GEMM_SMEM>>>(gSh, gWh, out, MQ);
    }
}